// round 1
// baseline (speedup 1.0000x reference)
#include <cuda_runtime.h>
#include <math.h>
#include <stdint.h>

#define B_ 4
#define L_ 1024
#define D_ 768
#define H_ 12
#define NE_ 42
#define M_ 4
#define P_ 512
#define BLK_ 64
#define NL_ 97
#define OFFSET_ 1
#define BP_ (B_*P_)          // 2048
#define KCH_ (D_/BLK_)       // 12 channel blocks

// ---------------- scratch (device globals; no runtime allocation) ----------
__device__ float g_ent_emb[B_*NE_*D_];        // [B,NE,D]
__device__ float g_ent_att[B_*NE_*H_*L_];     // [B,NE,H,L]
__device__ float g_ht[B_*P_*L_];              // [B,P,L]
__device__ float g_rs[B_*P_*D_];              // [B,P,D]
__device__ float g_zs[B_*P_*D_];
__device__ float g_zo[B_*P_*D_];
__device__ float g_part[KCH_*BP_*NL_];        // split-K partials for classifier

// ---------------- kernel A: entity embeds = logsumexp over mentions --------
__global__ void k_ent_emb(const float* __restrict__ seq,
                          const int* __restrict__ mpos) {
    int be = blockIdx.x;               // b*NE + e
    int b  = be / NE_;
    int base = be * M_;
    int p0 = mpos[base+0] + OFFSET_;
    int p1 = mpos[base+1] + OFFSET_;
    int p2 = mpos[base+2] + OFFSET_;
    int p3 = mpos[base+3] + OFFSET_;
    const float* s0 = seq + ((size_t)b*L_ + p0)*D_;
    const float* s1 = seq + ((size_t)b*L_ + p1)*D_;
    const float* s2 = seq + ((size_t)b*L_ + p2)*D_;
    const float* s3 = seq + ((size_t)b*L_ + p3)*D_;
    float* out = g_ent_emb + (size_t)be*D_;
    for (int d = threadIdx.x; d < D_; d += blockDim.x) {
        float x0 = s0[d], x1 = s1[d], x2 = s2[d], x3 = s3[d];
        float mx = fmaxf(fmaxf(x0,x1), fmaxf(x2,x3));
        float s = expf(x0-mx) + expf(x1-mx) + expf(x2-mx) + expf(x3-mx);
        out[d] = mx + logf(s);
    }
}

// ---------------- kernel B: entity attention = mean over mention rows ------
__global__ void k_ent_att(const float* __restrict__ att,
                          const int* __restrict__ mpos) {
    int id = blockIdx.x;               // (b*NE+e)*H + h
    int h  = id % H_;
    int be = id / H_;
    int b  = be / NE_;
    int base = be * M_;
    const float* a = att + (((size_t)b*H_ + h)*L_)*L_;
    const float* r0 = a + (size_t)(mpos[base+0]+OFFSET_)*L_;
    const float* r1 = a + (size_t)(mpos[base+1]+OFFSET_)*L_;
    const float* r2 = a + (size_t)(mpos[base+2]+OFFSET_)*L_;
    const float* r3 = a + (size_t)(mpos[base+3]+OFFSET_)*L_;
    float* out = g_ent_att + ((size_t)be*H_ + h)*L_;
    for (int l = threadIdx.x; l < L_; l += blockDim.x)
        out[l] = 0.25f * (r0[l] + r1[l] + r2[l] + r3[l]);
}

// ---------------- kernel C: per-pair channel attention, normalized ---------
__global__ void k_ht(const int* __restrict__ hts) {
    int bp = blockIdx.x;               // b*P + p
    int b  = bp / P_;
    int hi = hts[bp*2 + 0];
    int ti = hts[bp*2 + 1];
    const float* ah = g_ent_att + (size_t)(b*NE_ + hi)*H_*L_;
    const float* at = g_ent_att + (size_t)(b*NE_ + ti)*H_*L_;
    const int T = 256;
    float v[4];
    float lsum = 0.f;
    #pragma unroll
    for (int it = 0; it < 4; it++) {
        int l = threadIdx.x + it*T;
        float acc = 0.f;
        #pragma unroll
        for (int h = 0; h < H_; h++)
            acc += ah[h*L_ + l] * at[h*L_ + l];
        acc *= (1.f/H_);
        v[it] = acc;
        lsum += acc;
    }
    __shared__ float red[32];
    #pragma unroll
    for (int o = 16; o; o >>= 1) lsum += __shfl_down_sync(~0u, lsum, o);
    if ((threadIdx.x & 31) == 0) red[threadIdx.x >> 5] = lsum;
    __syncthreads();
    if (threadIdx.x < 8) {
        float t = red[threadIdx.x];
        #pragma unroll
        for (int o = 4; o; o >>= 1) t += __shfl_down_sync(0xffu, t, o);
        if (threadIdx.x == 0) red[0] = 1.f / (t + 1e-5f);
    }
    __syncthreads();
    float inv = red[0];
    float* o = g_ht + (size_t)bp*L_;
    #pragma unroll
    for (int it = 0; it < 4; it++)
        o[threadIdx.x + it*T] = v[it] * inv;
}

// ---------------- kernel D: rs = ht_att @ sequence_output ------------------
// per batch: [P,L] @ [L,D]. block tile 32p x 128d, kc=32, micro 4x4.
__global__ void k_rs(const float* __restrict__ seq) {
    int b  = blockIdx.z;
    int p0 = blockIdx.y * 32;
    int d0 = blockIdx.x * 128;
    __shared__ float ht_s[32][33];
    __shared__ float seq_s[32][128];
    int tid = threadIdx.x;             // 256
    int pi = tid >> 5;                 // 0..7 (4 p-rows each)
    int di = tid & 31;                 // 0..31 (4 d-cols each)
    float acc[4][4] = {};
    const float* seqb = seq + (size_t)b*L_*D_;
    const float* htb  = g_ht + ((size_t)b*P_ + p0)*L_;
    for (int lc = 0; lc < L_; lc += 32) {
        #pragma unroll
        for (int i = 0; i < 4; i++) {
            int idx = tid + i*256;     // 1024 = 32x32
            int r = idx >> 5, c = idx & 31;
            ht_s[r][c] = htb[(size_t)r*L_ + lc + c];
        }
        #pragma unroll
        for (int i = 0; i < 4; i++) {
            int idx = tid + i*256;     // 1024 float4 = 32x128
            int r = idx >> 5, c4 = idx & 31;
            ((float4*)seq_s[r])[c4] =
                ((const float4*)(seqb + (size_t)(lc+r)*D_ + d0))[c4];
        }
        __syncthreads();
        #pragma unroll
        for (int l = 0; l < 32; l++) {
            float hv[4];
            #pragma unroll
            for (int pp = 0; pp < 4; pp++) hv[pp] = ht_s[pi*4+pp][l];
            float4 sv = ((float4*)seq_s[l])[di];
            float sc[4] = {sv.x, sv.y, sv.z, sv.w};
            #pragma unroll
            for (int pp = 0; pp < 4; pp++)
                #pragma unroll
                for (int dd = 0; dd < 4; dd++)
                    acc[pp][dd] += hv[pp] * sc[dd];
        }
        __syncthreads();
    }
    #pragma unroll
    for (int pp = 0; pp < 4; pp++) {
        int p = p0 + pi*4 + pp;
        float* o = g_rs + ((size_t)b*P_ + p)*D_ + d0 + di*4;
        o[0]=acc[pp][0]; o[1]=acc[pp][1]; o[2]=acc[pp][2]; o[3]=acc[pp][3];
    }
}

// ---------------- kernel E: extractors zs/zo = tanh([e,rs]@W + b) ----------
// [2048,1536]@[1536,768], block tile 64bp x 128d, kc=16, micro 8x8, 128 thr.
__global__ void k_extract(const int* __restrict__ hts,
                          const float* __restrict__ Wh, const float* __restrict__ bh,
                          const float* __restrict__ Wt, const float* __restrict__ bt) {
    int sel = blockIdx.z;              // 0 = head/zs, 1 = tail/zo
    const float* W    = sel ? Wt : Wh;
    const float* bias = sel ? bt : bh;
    float* out        = sel ? g_zo : g_zs;
    int r0 = blockIdx.x * 64;          // bp base (tile stays in one batch)
    int d0 = blockIdx.y * 128;
    int b  = r0 / P_;
    __shared__ float A_s[64][17];
    __shared__ float W_s[16][128];
    __shared__ int   s_idx[64];
    int tid = threadIdx.x;             // 128
    if (tid < 64) s_idx[tid] = hts[(size_t)(r0 + tid)*2 + sel];
    __syncthreads();
    int ni = tid & 15;                 // 16 n-groups of 8 d
    int pi = tid >> 4;                 // 8 p-groups of 8 rows
    float acc[8][8] = {};
    for (int kc0 = 0; kc0 < 2*D_; kc0 += 16) {
        #pragma unroll
        for (int i = 0; i < 8; i++) {
            int idx = tid + i*128;     // 1024 = 64x16
            int r = idx >> 4, kk = idx & 15;
            int kg = kc0 + kk;
            int bp = r0 + r;
            float v;
            if (kg < D_) v = g_ent_emb[((size_t)b*NE_ + s_idx[r])*D_ + kg];
            else         v = g_rs[(size_t)bp*D_ + (kg - D_)];
            A_s[r][kk] = v;
        }
        #pragma unroll
        for (int i = 0; i < 4; i++) {
            int idx = tid + i*128;     // 512 float4 = 16x128
            int r = idx >> 5, c4 = idx & 31;
            ((float4*)W_s[r])[c4] =
                ((const float4*)(W + (size_t)(kc0+r)*D_ + d0))[c4];
        }
        __syncthreads();
        #pragma unroll
        for (int kk = 0; kk < 16; kk++) {
            float a[8], w[8];
            #pragma unroll
            for (int pp = 0; pp < 8; pp++) a[pp] = A_s[pi*8+pp][kk];
            float4 w0 = ((float4*)W_s[kk])[ni*2];
            float4 w1 = ((float4*)W_s[kk])[ni*2+1];
            w[0]=w0.x; w[1]=w0.y; w[2]=w0.z; w[3]=w0.w;
            w[4]=w1.x; w[5]=w1.y; w[6]=w1.z; w[7]=w1.w;
            #pragma unroll
            for (int pp = 0; pp < 8; pp++)
                #pragma unroll
                for (int dd = 0; dd < 8; dd++)
                    acc[pp][dd] += a[pp] * w[dd];
        }
        __syncthreads();
    }
    #pragma unroll
    for (int pp = 0; pp < 8; pp++) {
        int bp = r0 + pi*8 + pp;
        float* o = out + (size_t)bp*D_ + d0 + ni*8;
        #pragma unroll
        for (int dd = 0; dd < 8; dd++)
            o[dd] = tanhf(acc[pp][dd] + bias[d0 + ni*8 + dd]);
    }
}

// ---------------- kernel F: grouped bilinear classifier (split-K) ----------
// logits_k[bp,n] = sum_{i,j} zs[bp,k,i]*zo[bp,k,j]*W[(k*64+i)*64+j, n]
// grid (32 pair-tiles, 12 k). block 64p x 97n(pad 128), 256 threads, 8p x 4n.
__global__ void k_bilinear(const float* __restrict__ Wbi) {
    extern __shared__ float sm[];
    float* zs_s = sm;                  // [64][64]
    float* zo_s = sm + 64*64;          // [64][64]
    float* W_s  = sm + 2*64*64;        // [64][128] padded n
    int k  = blockIdx.y;
    int r0 = blockIdx.x * 64;          // bp base
    int tid = threadIdx.x;             // 256
    int ni = tid & 31;                 // 4 n each
    int pi = tid >> 5;                 // 8 p each
    for (int idx = tid; idx < 64*64; idx += 256) {
        int r = idx >> 6, c = idx & 63;
        zs_s[idx] = g_zs[(size_t)(r0+r)*D_ + k*BLK_ + c];
        zo_s[idx] = g_zo[(size_t)(r0+r)*D_ + k*BLK_ + c];
    }
    float acc[8][4] = {};
    for (int i = 0; i < 64; i++) {
        __syncthreads();               // prev-iter W_s readers done (+ z loads)
        for (int idx = tid; idx < 64*128; idx += 256) {
            int j = idx >> 7, n = idx & 127;
            W_s[idx] = (n < NL_)
                ? Wbi[((size_t)((k*BLK_ + i)*BLK_) + j)*NL_ + n] : 0.f;
        }
        __syncthreads();
        float azs[8];
        #pragma unroll
        for (int pp = 0; pp < 8; pp++) azs[pp] = zs_s[(pi*8+pp)*64 + i];
        #pragma unroll 4
        for (int j = 0; j < 64; j++) {
            float4 wv = ((float4*)(W_s + j*128))[ni];
            #pragma unroll
            for (int pp = 0; pp < 8; pp++) {
                float ab = azs[pp] * zo_s[(pi*8+pp)*64 + j];
                acc[pp][0] += ab * wv.x;
                acc[pp][1] += ab * wv.y;
                acc[pp][2] += ab * wv.z;
                acc[pp][3] += ab * wv.w;
            }
        }
    }
    int n0 = ni*4;
    #pragma unroll
    for (int pp = 0; pp < 8; pp++) {
        int bp = r0 + pi*8 + pp;
        float* o = g_part + ((size_t)k*BP_ + bp)*NL_;
        #pragma unroll
        for (int nn = 0; nn < 4; nn++)
            if (n0 + nn < NL_) o[n0+nn] = acc[pp][nn];
    }
}

// ---------------- kernel G: reduce split-K partials + bias -----------------
__global__ void k_reduce(const float* __restrict__ bbi, float* __restrict__ out) {
    int idx = blockIdx.x*256 + threadIdx.x;
    if (idx >= BP_*NL_) return;
    int n = idx % NL_;
    float s = bbi[n];
    #pragma unroll
    for (int k = 0; k < KCH_; k++)
        s += g_part[(size_t)k*BP_*NL_ + idx];
    out[idx] = s;
}

// ---------------- launch ---------------------------------------------------
extern "C" void kernel_launch(void* const* d_in, const int* in_sizes, int n_in,
                              void* d_out, int out_size) {
    const float* seq  = (const float*)d_in[0];
    const float* att  = (const float*)d_in[1];
    const int*   mpos = (const int*)d_in[2];
    const int*   hts  = (const int*)d_in[3];
    const float* Wh   = (const float*)d_in[4];
    const float* bh   = (const float*)d_in[5];
    const float* Wt   = (const float*)d_in[6];
    const float* bt   = (const float*)d_in[7];
    const float* Wbi  = (const float*)d_in[8];
    const float* bbi  = (const float*)d_in[9];
    float* out = (float*)d_out;

    cudaFuncSetAttribute(k_bilinear,
                         cudaFuncAttributeMaxDynamicSharedMemorySize, 65536);

    k_ent_emb<<<B_*NE_, 256>>>(seq, mpos);
    k_ent_att<<<B_*NE_*H_, 256>>>(att, mpos);
    k_ht<<<B_*P_, 256>>>(hts);
    k_rs<<<dim3(D_/128, P_/32, B_), 256>>>(seq);
    k_extract<<<dim3(BP_/64, D_/128, 2), 128>>>(hts, Wh, bh, Wt, bt);
    k_bilinear<<<dim3(BP_/64, KCH_), 256, 65536>>>(Wbi);
    k_reduce<<<(BP_*NL_ + 255)/256, 256>>>(bbi, out);
}

// round 2
// speedup vs baseline: 1.0661x; 1.0661x over previous
#include <cuda_runtime.h>
#include <math.h>
#include <stdint.h>

#define B_ 4
#define L_ 1024
#define D_ 768
#define H_ 12
#define NE_ 42
#define M_ 4
#define P_ 512
#define BLK_ 64
#define NL_ 97
#define OFFSET_ 1
#define BP_ (B_*P_)          // 2048
#define KCH_ (D_/BLK_)       // 12 channel blocks
#define NPAD_ 128

typedef unsigned long long u64;

__device__ __forceinline__ u64 f2pack(float lo, float hi) {
    u64 r; asm("mov.b64 %0,{%1,%2};" : "=l"(r) : "f"(lo), "f"(hi)); return r;
}
__device__ __forceinline__ void f2unpack(u64 v, float& lo, float& hi) {
    asm("mov.b64 {%0,%1},%2;" : "=f"(lo), "=f"(hi) : "l"(v));
}
__device__ __forceinline__ u64 ffma2(u64 a, u64 b, u64 c) {
    u64 d; asm("fma.rn.f32x2 %0,%1,%2,%3;" : "=l"(d) : "l"(a), "l"(b), "l"(c)); return d;
}
__device__ __forceinline__ u64 fmul2(u64 a, u64 b) {
    u64 d; asm("mul.rn.f32x2 %0,%1,%2;" : "=l"(d) : "l"(a), "l"(b)); return d;
}

// ---------------- scratch (device globals; no runtime allocation) ----------
__device__ float g_ent_emb[B_*NE_*D_];        // [B,NE,D]
__device__ float g_ent_att[B_*NE_*H_*L_];     // [B,NE,H,L]
__device__ float g_ht[B_*P_*L_];              // [B,P,L]
__device__ float g_rs[B_*P_*D_];              // [B,P,D]
__device__ float g_zs[B_*P_*D_];
__device__ float g_zo[B_*P_*D_];
__device__ float g_part[KCH_*BP_*NL_];        // split-K partials
__device__ float g_Wpad[KCH_*BLK_*BLK_*NPAD_]; // W_bi padded to n=128

// ---------------- kernel A: entity embeds = logsumexp over mentions --------
__global__ void k_ent_emb(const float* __restrict__ seq,
                          const int* __restrict__ mpos) {
    int be = blockIdx.x;
    int b  = be / NE_;
    int base = be * M_;
    int p0 = mpos[base+0] + OFFSET_;
    int p1 = mpos[base+1] + OFFSET_;
    int p2 = mpos[base+2] + OFFSET_;
    int p3 = mpos[base+3] + OFFSET_;
    const float* s0 = seq + ((size_t)b*L_ + p0)*D_;
    const float* s1 = seq + ((size_t)b*L_ + p1)*D_;
    const float* s2 = seq + ((size_t)b*L_ + p2)*D_;
    const float* s3 = seq + ((size_t)b*L_ + p3)*D_;
    float* out = g_ent_emb + (size_t)be*D_;
    for (int d = threadIdx.x; d < D_; d += blockDim.x) {
        float x0 = s0[d], x1 = s1[d], x2 = s2[d], x3 = s3[d];
        float mx = fmaxf(fmaxf(x0,x1), fmaxf(x2,x3));
        float s = expf(x0-mx) + expf(x1-mx) + expf(x2-mx) + expf(x3-mx);
        out[d] = mx + logf(s);
    }
}

// ---------------- kernel B: entity attention = mean over mention rows ------
__global__ void k_ent_att(const float* __restrict__ att,
                          const int* __restrict__ mpos) {
    int id = blockIdx.x;
    int h  = id % H_;
    int be = id / H_;
    int b  = be / NE_;
    int base = be * M_;
    const float* a = att + (((size_t)b*H_ + h)*L_)*L_;
    const float* r0 = a + (size_t)(mpos[base+0]+OFFSET_)*L_;
    const float* r1 = a + (size_t)(mpos[base+1]+OFFSET_)*L_;
    const float* r2 = a + (size_t)(mpos[base+2]+OFFSET_)*L_;
    const float* r3 = a + (size_t)(mpos[base+3]+OFFSET_)*L_;
    float* out = g_ent_att + ((size_t)be*H_ + h)*L_;
    for (int l = threadIdx.x; l < L_; l += blockDim.x)
        out[l] = 0.25f * (r0[l] + r1[l] + r2[l] + r3[l]);
}

// ---------------- kernel C: per-pair channel attention, normalized ---------
__global__ void k_ht(const int* __restrict__ hts) {
    int bp = blockIdx.x;
    int b  = bp / P_;
    int hi = hts[bp*2 + 0];
    int ti = hts[bp*2 + 1];
    const float* ah = g_ent_att + (size_t)(b*NE_ + hi)*H_*L_;
    const float* at = g_ent_att + (size_t)(b*NE_ + ti)*H_*L_;
    const int T = 256;
    float v[4];
    float lsum = 0.f;
    #pragma unroll
    for (int it = 0; it < 4; it++) {
        int l = threadIdx.x + it*T;
        float acc = 0.f;
        #pragma unroll
        for (int h = 0; h < H_; h++)
            acc += ah[h*L_ + l] * at[h*L_ + l];
        acc *= (1.f/H_);
        v[it] = acc;
        lsum += acc;
    }
    __shared__ float red[32];
    #pragma unroll
    for (int o = 16; o; o >>= 1) lsum += __shfl_down_sync(~0u, lsum, o);
    if ((threadIdx.x & 31) == 0) red[threadIdx.x >> 5] = lsum;
    __syncthreads();
    if (threadIdx.x < 8) {
        float t = red[threadIdx.x];
        #pragma unroll
        for (int o = 4; o; o >>= 1) t += __shfl_down_sync(0xffu, t, o);
        if (threadIdx.x == 0) red[0] = 1.f / (t + 1e-5f);
    }
    __syncthreads();
    float inv = red[0];
    float* o = g_ht + (size_t)bp*L_;
    #pragma unroll
    for (int it = 0; it < 4; it++)
        o[threadIdx.x + it*T] = v[it] * inv;
}

// ---------------- kernel D: rs = ht_att @ sequence_output (f32x2) ----------
// per batch: [P,L]@[L,D]. tile 64p x 128d, kc=32, micro 4x8, 256 thr.
__global__ void __launch_bounds__(256) k_rs(const float* __restrict__ seq) {
    int b  = blockIdx.z;
    int p0 = blockIdx.y * 64;
    int d0 = blockIdx.x * 128;
    __shared__ float ht_s[32][66];     // transposed [l][p], pad 66 (8B-even pairs)
    __shared__ float seq_s[32][128];
    int tid = threadIdx.x;
    int ni = tid & 15;                 // 8 d each
    int pi = tid >> 4;                 // 16 groups x 4 rows
    u64 acc2[2][8];
    #pragma unroll
    for (int r = 0; r < 2; r++)
        #pragma unroll
        for (int d = 0; d < 8; d++) acc2[r][d] = 0ull;
    const float* seqb = seq + (size_t)b*L_*D_;
    const float* htb  = g_ht + ((size_t)b*P_ + p0)*L_;
    for (int lc = 0; lc < L_; lc += 32) {
        #pragma unroll
        for (int i = 0; i < 8; i++) {
            int idx = tid + i*256;     // 2048 = 64r x 32l
            int l = idx & 31, r = idx >> 5;
            ht_s[l][r] = htb[(size_t)r*L_ + lc + l];
        }
        #pragma unroll
        for (int i = 0; i < 4; i++) {
            int idx = tid + i*256;     // 1024 f4 = 32 x 128
            int r = idx >> 5, c4 = idx & 31;
            ((float4*)seq_s[r])[c4] =
                ((const float4*)(seqb + (size_t)(lc+r)*D_ + d0))[c4];
        }
        __syncthreads();
        #pragma unroll 4
        for (int l = 0; l < 32; l++) {
            u64 a2[2];
            a2[0] = *(const u64*)&ht_s[l][pi*4 + 0];
            a2[1] = *(const u64*)&ht_s[l][pi*4 + 2];
            float4 w0 = ((float4*)seq_s[l])[ni*2];
            float4 w1 = ((float4*)seq_s[l])[ni*2+1];
            float wf[8] = {w0.x,w0.y,w0.z,w0.w,w1.x,w1.y,w1.z,w1.w};
            u64 wd[8];
            #pragma unroll
            for (int d = 0; d < 8; d++) wd[d] = f2pack(wf[d], wf[d]);
            #pragma unroll
            for (int r = 0; r < 2; r++)
                #pragma unroll
                for (int d = 0; d < 8; d++)
                    acc2[r][d] = ffma2(a2[r], wd[d], acc2[r][d]);
        }
        __syncthreads();
    }
    #pragma unroll
    for (int r = 0; r < 2; r++) {
        float lo[8], hi[8];
        #pragma unroll
        for (int d = 0; d < 8; d++) f2unpack(acc2[r][d], lo[d], hi[d]);
        int row0 = p0 + pi*4 + r*2;
        float* o0 = g_rs + ((size_t)b*P_ + row0)*D_ + d0 + ni*8;
        float* o1 = o0 + D_;
        ((float4*)o0)[0] = make_float4(lo[0],lo[1],lo[2],lo[3]);
        ((float4*)o0)[1] = make_float4(lo[4],lo[5],lo[6],lo[7]);
        ((float4*)o1)[0] = make_float4(hi[0],hi[1],hi[2],hi[3]);
        ((float4*)o1)[1] = make_float4(hi[4],hi[5],hi[6],hi[7]);
    }
}

// ---------------- kernel E: extractors zs/zo = tanh([e,rs]@W+b) (f32x2) ----
// [2048,1536]@[1536,768], tile 64r x 128d, kc=16, micro 8x8, 128 thr.
__global__ void __launch_bounds__(128) k_extract(const int* __restrict__ hts,
                          const float* __restrict__ Wh, const float* __restrict__ bh,
                          const float* __restrict__ Wt, const float* __restrict__ bt) {
    int sel = blockIdx.z;
    const float* W    = sel ? Wt : Wh;
    const float* bias = sel ? bt : bh;
    float* out        = sel ? g_zo : g_zs;
    int r0 = blockIdx.x * 64;
    int d0 = blockIdx.y * 128;
    int b  = r0 / P_;
    __shared__ float A_s[16][66];      // transposed [k][row]
    __shared__ float W_s[16][128];
    __shared__ int   s_idx[64];
    int tid = threadIdx.x;
    if (tid < 64) s_idx[tid] = hts[(size_t)(r0 + tid)*2 + sel];
    __syncthreads();
    int ni = tid & 15;                 // 8 d each
    int pi = tid >> 4;                 // 8 groups x 8 rows
    u64 acc2[4][8];
    #pragma unroll
    for (int r = 0; r < 4; r++)
        #pragma unroll
        for (int d = 0; d < 8; d++) acc2[r][d] = 0ull;
    for (int kc0 = 0; kc0 < 2*D_; kc0 += 16) {
        #pragma unroll
        for (int i = 0; i < 8; i++) {
            int idx = tid + i*128;     // 1024 = 64r x 16k
            int kk = idx & 15, r = idx >> 4;
            int kg = kc0 + kk;
            int bp = r0 + r;
            float v;
            if (kg < D_) v = g_ent_emb[((size_t)b*NE_ + s_idx[r])*D_ + kg];
            else         v = g_rs[(size_t)bp*D_ + (kg - D_)];
            A_s[kk][r] = v;
        }
        #pragma unroll
        for (int i = 0; i < 4; i++) {
            int idx = tid + i*128;     // 512 f4 = 16 x 128
            int r = idx >> 5, c4 = idx & 31;
            ((float4*)W_s[r])[c4] =
                ((const float4*)(W + (size_t)(kc0+r)*D_ + d0))[c4];
        }
        __syncthreads();
        #pragma unroll
        for (int kk = 0; kk < 16; kk++) {
            u64 a2[4];
            #pragma unroll
            for (int r = 0; r < 4; r++)
                a2[r] = *(const u64*)&A_s[kk][pi*8 + r*2];
            float4 w0 = ((float4*)W_s[kk])[ni*2];
            float4 w1 = ((float4*)W_s[kk])[ni*2+1];
            float wf[8] = {w0.x,w0.y,w0.z,w0.w,w1.x,w1.y,w1.z,w1.w};
            u64 wd[8];
            #pragma unroll
            for (int d = 0; d < 8; d++) wd[d] = f2pack(wf[d], wf[d]);
            #pragma unroll
            for (int r = 0; r < 4; r++)
                #pragma unroll
                for (int d = 0; d < 8; d++)
                    acc2[r][d] = ffma2(a2[r], wd[d], acc2[r][d]);
        }
        __syncthreads();
    }
    float bv[8];
    #pragma unroll
    for (int d = 0; d < 8; d++) bv[d] = bias[d0 + ni*8 + d];
    #pragma unroll
    for (int r = 0; r < 4; r++) {
        float lo[8], hi[8];
        #pragma unroll
        for (int d = 0; d < 8; d++) {
            f2unpack(acc2[r][d], lo[d], hi[d]);
            lo[d] = tanhf(lo[d] + bv[d]);
            hi[d] = tanhf(hi[d] + bv[d]);
        }
        int row0 = r0 + pi*8 + r*2;
        float* o0 = out + (size_t)row0*D_ + d0 + ni*8;
        float* o1 = o0 + D_;
        ((float4*)o0)[0] = make_float4(lo[0],lo[1],lo[2],lo[3]);
        ((float4*)o0)[1] = make_float4(lo[4],lo[5],lo[6],lo[7]);
        ((float4*)o1)[0] = make_float4(hi[0],hi[1],hi[2],hi[3]);
        ((float4*)o1)[1] = make_float4(hi[4],hi[5],hi[6],hi[7]);
    }
}

// ---------------- kernel Wpad: pad W_bi n-dim 97 -> 128 --------------------
__global__ void k_padW(const float* __restrict__ Wbi) {
    int ki = blockIdx.x;               // k*64 + i  (768 blocks)
    for (int idx = threadIdx.x; idx < BLK_*NPAD_; idx += blockDim.x) {
        int j = idx >> 7, n = idx & 127;
        g_Wpad[(size_t)ki*BLK_*NPAD_ + idx] =
            (n < NL_) ? Wbi[((size_t)ki*BLK_ + j)*NL_ + n] : 0.f;
    }
}

// ---------------- kernel F: grouped bilinear classifier (f32x2, split-K) ---
// grid (32 pair-tiles, 12 k). 64 rows x 128n(pad), 256 thr, micro 8r x 4n.
__global__ void __launch_bounds__(256) k_bilinear() {
    extern __shared__ float sm[];
    float* zs_s = sm;                  // [64][66] transposed [i][row]
    float* zo_s = sm + 64*66;          // [64][66] transposed [j][row]
    float* W_s  = sm + 2*64*66;        // [64][128]
    int k  = blockIdx.y;
    int r0 = blockIdx.x * 64;
    int tid = threadIdx.x;
    int ni = tid & 31;                 // 4 n each
    int rg = tid >> 5;                 // 8 groups x 8 rows
    #pragma unroll
    for (int it = 0; it < 16; it++) {
        int idx = tid + it*256;        // 4096 = 64r x 64i
        int i = idx & 63, r = idx >> 6;
        zs_s[i*66 + r] = g_zs[(size_t)(r0+r)*D_ + k*BLK_ + i];
        zo_s[i*66 + r] = g_zo[(size_t)(r0+r)*D_ + k*BLK_ + i];
    }
    u64 acc2[4][4];
    #pragma unroll
    for (int r = 0; r < 4; r++)
        #pragma unroll
        for (int n = 0; n < 4; n++) acc2[r][n] = 0ull;
    const float* wsrc = g_Wpad + (size_t)(k*BLK_)*BLK_*NPAD_;
    for (int i = 0; i < 64; i++) {
        __syncthreads();               // covers zs/zo staging + prev W_s readers
        #pragma unroll
        for (int it = 0; it < 8; it++) {
            int idx = tid + it*256;    // 2048 f4 = 64j x 32
            ((float4*)W_s)[idx] =
                ((const float4*)(wsrc + (size_t)i*BLK_*NPAD_))[idx];
        }
        __syncthreads();
        u64 azs2[4];
        #pragma unroll
        for (int r = 0; r < 4; r++)
            azs2[r] = *(const u64*)&zs_s[i*66 + rg*8 + r*2];
        #pragma unroll 4
        for (int j = 0; j < 64; j++) {
            float4 wv = ((float4*)(W_s + j*128))[ni];
            u64 wd0 = f2pack(wv.x, wv.x);
            u64 wd1 = f2pack(wv.y, wv.y);
            u64 wd2 = f2pack(wv.z, wv.z);
            u64 wd3 = f2pack(wv.w, wv.w);
            #pragma unroll
            for (int r = 0; r < 4; r++) {
                u64 zo2 = *(const u64*)&zo_s[j*66 + rg*8 + r*2];
                u64 ab2 = fmul2(azs2[r], zo2);
                acc2[r][0] = ffma2(ab2, wd0, acc2[r][0]);
                acc2[r][1] = ffma2(ab2, wd1, acc2[r][1]);
                acc2[r][2] = ffma2(ab2, wd2, acc2[r][2]);
                acc2[r][3] = ffma2(ab2, wd3, acc2[r][3]);
            }
        }
    }
    int n0 = ni*4;
    #pragma unroll
    for (int r = 0; r < 4; r++) {
        float lo[4], hi[4];
        #pragma unroll
        for (int n = 0; n < 4; n++) f2unpack(acc2[r][n], lo[n], hi[n]);
        int row0 = r0 + rg*8 + r*2;
        float* o0 = g_part + ((size_t)k*BP_ + row0)*NL_;
        float* o1 = o0 + NL_;
        #pragma unroll
        for (int n = 0; n < 4; n++) {
            if (n0 + n < NL_) { o0[n0+n] = lo[n]; o1[n0+n] = hi[n]; }
        }
    }
}

// ---------------- kernel G: reduce split-K partials + bias -----------------
__global__ void k_reduce(const float* __restrict__ bbi, float* __restrict__ out) {
    int idx = blockIdx.x*256 + threadIdx.x;
    if (idx >= BP_*NL_) return;
    int n = idx % NL_;
    float s = bbi[n];
    #pragma unroll
    for (int k = 0; k < KCH_; k++)
        s += g_part[(size_t)k*BP_*NL_ + idx];
    out[idx] = s;
}

// ---------------- launch ---------------------------------------------------
extern "C" void kernel_launch(void* const* d_in, const int* in_sizes, int n_in,
                              void* d_out, int out_size) {
    const float* seq  = (const float*)d_in[0];
    const float* att  = (const float*)d_in[1];
    const int*   mpos = (const int*)d_in[2];
    const int*   hts  = (const int*)d_in[3];
    const float* Wh   = (const float*)d_in[4];
    const float* bh   = (const float*)d_in[5];
    const float* Wt   = (const float*)d_in[6];
    const float* bt   = (const float*)d_in[7];
    const float* Wbi  = (const float*)d_in[8];
    const float* bbi  = (const float*)d_in[9];
    float* out = (float*)d_out;

    static bool attr_set = false;
    if (!attr_set) {
        cudaFuncSetAttribute(k_bilinear,
            cudaFuncAttributeMaxDynamicSharedMemorySize, 2*64*66*4 + 64*128*4);
        attr_set = true;
    }

    k_padW<<<KCH_*BLK_, 256>>>(Wbi);
    k_ent_emb<<<B_*NE_, 256>>>(seq, mpos);
    k_ent_att<<<B_*NE_*H_, 256>>>(att, mpos);
    k_ht<<<B_*P_, 256>>>(hts);
    k_rs<<<dim3(D_/128, P_/64, B_), 256>>>(seq);
    k_extract<<<dim3(BP_/64, D_/128, 2), 128>>>(hts, Wh, bh, Wt, bt);
    k_bilinear<<<dim3(BP_/64, KCH_), 256, 2*64*66*4 + 64*128*4>>>();
    k_reduce<<<(BP_*NL_ + 255)/256, 256>>>(bbi, out);
}

// round 4
// speedup vs baseline: 1.8446x; 1.7302x over previous
#include <cuda_runtime.h>
#include <cuda_bf16.h>
#include <math.h>
#include <stdint.h>

#define B_ 4
#define L_ 1024
#define D_ 768
#define H_ 12
#define NE_ 42
#define M_ 4
#define P_ 512
#define BLK_ 64
#define NL_ 97
#define OFFSET_ 1
#define BP_ (B_*P_)          // 2048
#define KCH_ (D_/BLK_)       // 12 channel blocks
#define WPITCH_ 136          // padded n (bf16), 272B rows -> conflict-free ldmatrix
#define WTILE_ (BLK_*WPITCH_) // 8704 elems = 17408 bytes per (k,i) split tile

typedef unsigned long long u64;
typedef unsigned int u32;

// ---------------- f32x2 helpers (scalar kernels) ---------------------------
__device__ __forceinline__ u64 f2pack(float lo, float hi) {
    u64 r; asm("mov.b64 %0,{%1,%2};" : "=l"(r) : "f"(lo), "f"(hi)); return r;
}
__device__ __forceinline__ void f2unpack(u64 v, float& lo, float& hi) {
    asm("mov.b64 {%0,%1},%2;" : "=f"(lo), "=f"(hi) : "l"(v));
}
__device__ __forceinline__ u64 ffma2(u64 a, u64 b, u64 c) {
    u64 d; asm("fma.rn.f32x2 %0,%1,%2,%3;" : "=l"(d) : "l"(a), "l"(b), "l"(c)); return d;
}

// ---------------- mma helpers ----------------------------------------------
__device__ __forceinline__ u32 smem_u32(const void* p) {
    u32 a; asm("{ .reg .u64 t; cvta.to.shared.u64 t, %1; cvt.u32.u64 %0, t; }"
               : "=r"(a) : "l"(p));
    return a;
}
// pack two f32 -> bf16x2 (first arg -> LOWER half)
__device__ __forceinline__ u32 cvt_bf2(float lo, float hi) {
    u32 d; asm("cvt.rn.bf16x2.f32 %0, %1, %2;" : "=r"(d) : "f"(hi), "f"(lo));
    return d;
}
__device__ __forceinline__ float bf_lo_f(u32 c) { return __uint_as_float(c << 16); }
__device__ __forceinline__ float bf_hi_f(u32 c) { return __uint_as_float(c & 0xFFFF0000u); }

__device__ __forceinline__ void cpa16(u32 dst, const void* src) {
    asm volatile("cp.async.cg.shared.global [%0], [%1], 16;"
                 :: "r"(dst), "l"(src) : "memory");
}
__device__ __forceinline__ void cpa_commit() {
    asm volatile("cp.async.commit_group;" ::: "memory");
}
__device__ __forceinline__ void cpa_wait1() {
    asm volatile("cp.async.wait_group 1;" ::: "memory");
}

__device__ __forceinline__ void ldsm4t(u32 addr, u32& r0, u32& r1, u32& r2, u32& r3) {
    asm volatile("ldmatrix.sync.aligned.m8n8.x4.trans.shared.b16 {%0,%1,%2,%3}, [%4];"
                 : "=r"(r0), "=r"(r1), "=r"(r2), "=r"(r3) : "r"(addr));
}
__device__ __forceinline__ void mma16816(float* d,
                                         u32 a0, u32 a1, u32 a2, u32 a3,
                                         u32 b0, u32 b1) {
    asm volatile(
        "mma.sync.aligned.m16n8k16.row.col.f32.bf16.bf16.f32 "
        "{%0,%1,%2,%3}, {%4,%5,%6,%7}, {%8,%9}, {%0,%1,%2,%3};"
        : "+f"(d[0]), "+f"(d[1]), "+f"(d[2]), "+f"(d[3])
        : "r"(a0), "r"(a1), "r"(a2), "r"(a3), "r"(b0), "r"(b1));
}

// ---------------- scratch (device globals; no runtime allocation) ----------
__device__ float g_ent_emb[B_*NE_*D_];
__device__ float g_ent_att[B_*NE_*H_*L_];
__device__ float g_ht[B_*P_*L_];
__device__ float g_rs[B_*P_*D_];
__device__ float g_zs[B_*P_*D_];
__device__ float g_zo[B_*P_*D_];
__device__ float g_part[KCH_*BP_*NL_];          // split-K partials
__device__ __nv_bfloat16 g_Wb0[KCH_*BLK_*WTILE_]; // W split hi  [ki][64][136]
__device__ __nv_bfloat16 g_Wb1[KCH_*BLK_*WTILE_]; // W split lo

// ---------------- kernel A: entity embeds = logsumexp over mentions --------
__global__ void k_ent_emb(const float* __restrict__ seq,
                          const int* __restrict__ mpos) {
    int be = blockIdx.x;
    int b  = be / NE_;
    int base = be * M_;
    int p0 = mpos[base+0] + OFFSET_;
    int p1 = mpos[base+1] + OFFSET_;
    int p2 = mpos[base+2] + OFFSET_;
    int p3 = mpos[base+3] + OFFSET_;
    const float* s0 = seq + ((size_t)b*L_ + p0)*D_;
    const float* s1 = seq + ((size_t)b*L_ + p1)*D_;
    const float* s2 = seq + ((size_t)b*L_ + p2)*D_;
    const float* s3 = seq + ((size_t)b*L_ + p3)*D_;
    float* out = g_ent_emb + (size_t)be*D_;
    for (int d = threadIdx.x; d < D_; d += blockDim.x) {
        float x0 = s0[d], x1 = s1[d], x2 = s2[d], x3 = s3[d];
        float mx = fmaxf(fmaxf(x0,x1), fmaxf(x2,x3));
        float s = expf(x0-mx) + expf(x1-mx) + expf(x2-mx) + expf(x3-mx);
        out[d] = mx + logf(s);
    }
}

// ---------------- kernel B: entity attention = mean over mention rows ------
__global__ void k_ent_att(const float* __restrict__ att,
                          const int* __restrict__ mpos) {
    int id = blockIdx.x;
    int h  = id % H_;
    int be = id / H_;
    int b  = be / NE_;
    int base = be * M_;
    const float* a = att + (((size_t)b*H_ + h)*L_)*L_;
    const float* r0 = a + (size_t)(mpos[base+0]+OFFSET_)*L_;
    const float* r1 = a + (size_t)(mpos[base+1]+OFFSET_)*L_;
    const float* r2 = a + (size_t)(mpos[base+2]+OFFSET_)*L_;
    const float* r3 = a + (size_t)(mpos[base+3]+OFFSET_)*L_;
    float* out = g_ent_att + ((size_t)be*H_ + h)*L_;
    for (int l = threadIdx.x; l < L_; l += blockDim.x)
        out[l] = 0.25f * (r0[l] + r1[l] + r2[l] + r3[l]);
}

// ---------------- kernel C: per-pair channel attention, normalized ---------
__global__ void k_ht(const int* __restrict__ hts) {
    int bp = blockIdx.x;
    int b  = bp / P_;
    int hi = hts[bp*2 + 0];
    int ti = hts[bp*2 + 1];
    const float* ah = g_ent_att + (size_t)(b*NE_ + hi)*H_*L_;
    const float* at = g_ent_att + (size_t)(b*NE_ + ti)*H_*L_;
    const int T = 256;
    float v[4];
    float lsum = 0.f;
    #pragma unroll
    for (int it = 0; it < 4; it++) {
        int l = threadIdx.x + it*T;
        float acc = 0.f;
        #pragma unroll
        for (int h = 0; h < H_; h++)
            acc += ah[h*L_ + l] * at[h*L_ + l];
        acc *= (1.f/H_);
        v[it] = acc;
        lsum += acc;
    }
    __shared__ float red[32];
    #pragma unroll
    for (int o = 16; o; o >>= 1) lsum += __shfl_down_sync(~0u, lsum, o);
    if ((threadIdx.x & 31) == 0) red[threadIdx.x >> 5] = lsum;
    __syncthreads();
    if (threadIdx.x < 8) {
        float t = red[threadIdx.x];
        #pragma unroll
        for (int o = 4; o; o >>= 1) t += __shfl_down_sync(0xffu, t, o);
        if (threadIdx.x == 0) red[0] = 1.f / (t + 1e-5f);
    }
    __syncthreads();
    float inv = red[0];
    float* o = g_ht + (size_t)bp*L_;
    #pragma unroll
    for (int it = 0; it < 4; it++)
        o[threadIdx.x + it*T] = v[it] * inv;
}

// ---------------- kernel D: rs = ht_att @ sequence_output (f32x2) ----------
__global__ void __launch_bounds__(256) k_rs(const float* __restrict__ seq) {
    int b  = blockIdx.z;
    int p0 = blockIdx.y * 64;
    int d0 = blockIdx.x * 128;
    __shared__ float ht_s[32][66];
    __shared__ float seq_s[32][128];
    int tid = threadIdx.x;
    int ni = tid & 15;
    int pi = tid >> 4;
    u64 acc2[2][8];
    #pragma unroll
    for (int r = 0; r < 2; r++)
        #pragma unroll
        for (int d = 0; d < 8; d++) acc2[r][d] = 0ull;
    const float* seqb = seq + (size_t)b*L_*D_;
    const float* htb  = g_ht + ((size_t)b*P_ + p0)*L_;
    for (int lc = 0; lc < L_; lc += 32) {
        #pragma unroll
        for (int i = 0; i < 8; i++) {
            int idx = tid + i*256;
            int l = idx & 31, r = idx >> 5;
            ht_s[l][r] = htb[(size_t)r*L_ + lc + l];
        }
        #pragma unroll
        for (int i = 0; i < 4; i++) {
            int idx = tid + i*256;
            int r = idx >> 5, c4 = idx & 31;
            ((float4*)seq_s[r])[c4] =
                ((const float4*)(seqb + (size_t)(lc+r)*D_ + d0))[c4];
        }
        __syncthreads();
        #pragma unroll 4
        for (int l = 0; l < 32; l++) {
            u64 a2[2];
            a2[0] = *(const u64*)&ht_s[l][pi*4 + 0];
            a2[1] = *(const u64*)&ht_s[l][pi*4 + 2];
            float4 w0 = ((float4*)seq_s[l])[ni*2];
            float4 w1 = ((float4*)seq_s[l])[ni*2+1];
            float wf[8] = {w0.x,w0.y,w0.z,w0.w,w1.x,w1.y,w1.z,w1.w};
            u64 wd[8];
            #pragma unroll
            for (int d = 0; d < 8; d++) wd[d] = f2pack(wf[d], wf[d]);
            #pragma unroll
            for (int r = 0; r < 2; r++)
                #pragma unroll
                for (int d = 0; d < 8; d++)
                    acc2[r][d] = ffma2(a2[r], wd[d], acc2[r][d]);
        }
        __syncthreads();
    }
    #pragma unroll
    for (int r = 0; r < 2; r++) {
        float lo[8], hi[8];
        #pragma unroll
        for (int d = 0; d < 8; d++) f2unpack(acc2[r][d], lo[d], hi[d]);
        int row0 = p0 + pi*4 + r*2;
        float* o0 = g_rs + ((size_t)b*P_ + row0)*D_ + d0 + ni*8;
        float* o1 = o0 + D_;
        ((float4*)o0)[0] = make_float4(lo[0],lo[1],lo[2],lo[3]);
        ((float4*)o0)[1] = make_float4(lo[4],lo[5],lo[6],lo[7]);
        ((float4*)o1)[0] = make_float4(hi[0],hi[1],hi[2],hi[3]);
        ((float4*)o1)[1] = make_float4(hi[4],hi[5],hi[6],hi[7]);
    }
}

// ---------------- kernel E: extractors zs/zo = tanh([e,rs]@W+b) (f32x2) ----
__global__ void __launch_bounds__(128) k_extract(const int* __restrict__ hts,
                          const float* __restrict__ Wh, const float* __restrict__ bh,
                          const float* __restrict__ Wt, const float* __restrict__ bt) {
    int sel = blockIdx.z;
    const float* W    = sel ? Wt : Wh;
    const float* bias = sel ? bt : bh;
    float* out        = sel ? g_zo : g_zs;
    int r0 = blockIdx.x * 64;
    int d0 = blockIdx.y * 128;
    int b  = r0 / P_;
    __shared__ float A_s[16][66];
    __shared__ float W_s[16][128];
    __shared__ int   s_idx[64];
    int tid = threadIdx.x;
    if (tid < 64) s_idx[tid] = hts[(size_t)(r0 + tid)*2 + sel];
    __syncthreads();
    int ni = tid & 15;
    int pi = tid >> 4;
    u64 acc2[4][8];
    #pragma unroll
    for (int r = 0; r < 4; r++)
        #pragma unroll
        for (int d = 0; d < 8; d++) acc2[r][d] = 0ull;
    for (int kc0 = 0; kc0 < 2*D_; kc0 += 16) {
        #pragma unroll
        for (int i = 0; i < 8; i++) {
            int idx = tid + i*128;
            int kk = idx & 15, r = idx >> 4;
            int kg = kc0 + kk;
            int bp = r0 + r;
            float v;
            if (kg < D_) v = g_ent_emb[((size_t)b*NE_ + s_idx[r])*D_ + kg];
            else         v = g_rs[(size_t)bp*D_ + (kg - D_)];
            A_s[kk][r] = v;
        }
        #pragma unroll
        for (int i = 0; i < 4; i++) {
            int idx = tid + i*128;
            int r = idx >> 5, c4 = idx & 31;
            ((float4*)W_s[r])[c4] =
                ((const float4*)(W + (size_t)(kc0+r)*D_ + d0))[c4];
        }
        __syncthreads();
        #pragma unroll
        for (int kk = 0; kk < 16; kk++) {
            u64 a2[4];
            #pragma unroll
            for (int r = 0; r < 4; r++)
                a2[r] = *(const u64*)&A_s[kk][pi*8 + r*2];
            float4 w0 = ((float4*)W_s[kk])[ni*2];
            float4 w1 = ((float4*)W_s[kk])[ni*2+1];
            float wf[8] = {w0.x,w0.y,w0.z,w0.w,w1.x,w1.y,w1.z,w1.w};
            u64 wd[8];
            #pragma unroll
            for (int d = 0; d < 8; d++) wd[d] = f2pack(wf[d], wf[d]);
            #pragma unroll
            for (int r = 0; r < 4; r++)
                #pragma unroll
                for (int d = 0; d < 8; d++)
                    acc2[r][d] = ffma2(a2[r], wd[d], acc2[r][d]);
        }
        __syncthreads();
    }
    float bv[8];
    #pragma unroll
    for (int d = 0; d < 8; d++) bv[d] = bias[d0 + ni*8 + d];
    #pragma unroll
    for (int r = 0; r < 4; r++) {
        float lo[8], hi[8];
        #pragma unroll
        for (int d = 0; d < 8; d++) {
            f2unpack(acc2[r][d], lo[d], hi[d]);
            lo[d] = tanhf(lo[d] + bv[d]);
            hi[d] = tanhf(hi[d] + bv[d]);
        }
        int row0 = r0 + pi*8 + r*2;
        float* o0 = out + (size_t)row0*D_ + d0 + ni*8;
        float* o1 = o0 + D_;
        ((float4*)o0)[0] = make_float4(lo[0],lo[1],lo[2],lo[3]);
        ((float4*)o0)[1] = make_float4(lo[4],lo[5],lo[6],lo[7]);
        ((float4*)o1)[0] = make_float4(hi[0],hi[1],hi[2],hi[3]);
        ((float4*)o1)[1] = make_float4(hi[4],hi[5],hi[6],hi[7]);
    }
}

// ---------------- kernel Wpad: split W_bi into bf16 hi/lo, padded ----------
// g_Wb0/g_Wb1[ki][j][n']: n' padded to 136 (zeros beyond NL_).
__global__ void k_padW_tc(const float* __restrict__ Wbi) {
    int ki = blockIdx.x;               // 0..767 (= k*64 + i)
    __nv_bfloat16* d0 = g_Wb0 + (size_t)ki*WTILE_;
    __nv_bfloat16* d1 = g_Wb1 + (size_t)ki*WTILE_;
    for (int idx = threadIdx.x; idx < WTILE_; idx += blockDim.x) {
        int j = idx / WPITCH_, n = idx % WPITCH_;
        float w = (n < NL_) ? Wbi[((size_t)(ki*BLK_ + j))*NL_ + n] : 0.f;
        float hi = __bfloat162float(__float2bfloat16(w));
        d0[idx] = __float2bfloat16(w);
        d1[idx] = __float2bfloat16(w - hi);
    }
}

// ---------------- kernel F: bilinear classifier via mma.sync bf16 ----------
// grid (16 row-tiles, 12 k). Block: 256 thr (8 warps), 128 rows x 112 n.
// K-loop: i in 0..63 (A_i = zs[:,i] outer zo), jc in 0..3 (k16 chunks of j).
// 2-term split: acc += a0*w0 + a0*w1 + a1*w0  (a1*w1 ~ 2^-16, dropped).
#define SM_ZS 0                         // [128][65] f32 = 33280
#define SM_ZO 33280                     // [128][66] f32 = 33792
#define SM_W  67072                     // 2 stages x (hi 17408 + lo 17408)
#define WSTAGE_ 34816
#define SMEMB_ (SM_W + 2*WSTAGE_)       // 136704

__global__ void __launch_bounds__(256, 1) k_bilinear_mma() {
    extern __shared__ char smem[];
    float* zs_s = (float*)(smem + SM_ZS);   // pitch 65
    float* zo_s = (float*)(smem + SM_ZO);   // pitch 66
    u32 sw = smem_u32(smem) + SM_W;
    int tid = threadIdx.x, w = tid >> 5, l = tid & 31;
    int g = l >> 2, tg = l & 3;
    int k  = blockIdx.y;
    int r0 = blockIdx.x * 128;

    // ---- prologue: start cp.async of W stages for i=0,1 ----
    #pragma unroll
    for (int s = 0; s < 2; s++) {
        const char* src0 = (const char*)(g_Wb0 + (size_t)(k*BLK_ + s)*WTILE_);
        const char* src1 = (const char*)(g_Wb1 + (size_t)(k*BLK_ + s)*WTILE_);
        u32 dst = sw + s*WSTAGE_;
        #pragma unroll
        for (int t = 0; t < 5; t++) {
            int idx = tid + t*256;
            if (idx < 1088) {
                cpa16(dst + idx*16, src0 + idx*16);
                cpa16(dst + 17408 + idx*16, src1 + idx*16);
            }
        }
        cpa_commit();
    }

    // ---- stage zs/zo fp32 slices (128 rows x 64 ch-cols) ----
    for (int idx = tid; idx < 128*64; idx += 256) {
        int r = idx >> 6, c = idx & 63;
        zs_s[r*65 + c] = g_zs[(size_t)(r0+r)*D_ + k*BLK_ + c];
        zo_s[r*66 + c] = g_zo[(size_t)(r0+r)*D_ + k*BLK_ + c];
    }
    __syncthreads();

    // ---- preload zo fragment values (rows rg, rg+8; 4 jc x 2 pairs) ----
    int rg = w*16 + g;
    float2 zoA[4][2], zoB[4][2];
    #pragma unroll
    for (int jc = 0; jc < 4; jc++) {
        zoA[jc][0] = *(float2*)&zo_s[rg*66     + jc*16 + tg*2];
        zoA[jc][1] = *(float2*)&zo_s[rg*66     + jc*16 + tg*2 + 8];
        zoB[jc][0] = *(float2*)&zo_s[(rg+8)*66 + jc*16 + tg*2];
        zoB[jc][1] = *(float2*)&zo_s[(rg+8)*66 + jc*16 + tg*2 + 8];
    }

    float acc[14][4];
    #pragma unroll
    for (int t = 0; t < 14; t++)
        #pragma unroll
        for (int e = 0; e < 4; e++) acc[t][e] = 0.f;

    u32 laneoff = (u32)((l & 15)*272 + (l >> 4)*16);

    for (int i = 0; i < BLK_; i++) {
        int s = i & 1;
        cpa_wait1();
        __syncthreads();
        float zs0 = zs_s[rg*65 + i];
        float zs1 = zs_s[(rg+8)*65 + i];
        u32 sbase = sw + s*WSTAGE_;
        #pragma unroll
        for (int jc = 0; jc < 4; jc++) {
            // A fragments: a0h..a3h (hi), a0r..a3r (residual)
            float p0x = zs0*zoA[jc][0].x, p0y = zs0*zoA[jc][0].y;
            float p1x = zs1*zoB[jc][0].x, p1y = zs1*zoB[jc][0].y;
            float p2x = zs0*zoA[jc][1].x, p2y = zs0*zoA[jc][1].y;
            float p3x = zs1*zoB[jc][1].x, p3y = zs1*zoB[jc][1].y;
            u32 a0h = cvt_bf2(p0x, p0y);
            u32 a1h = cvt_bf2(p1x, p1y);
            u32 a2h = cvt_bf2(p2x, p2y);
            u32 a3h = cvt_bf2(p3x, p3y);
            u32 a0r = cvt_bf2(p0x - bf_lo_f(a0h), p0y - bf_hi_f(a0h));
            u32 a1r = cvt_bf2(p1x - bf_lo_f(a1h), p1y - bf_hi_f(a1h));
            u32 a2r = cvt_bf2(p2x - bf_lo_f(a2h), p2y - bf_hi_f(a2h));
            u32 a3r = cvt_bf2(p3x - bf_lo_f(a3h), p3y - bf_hi_f(a3h));
            u32 rowb = sbase + (u32)(jc*16*272) + laneoff;
            #pragma unroll
            for (int ntp = 0; ntp < 7; ntp++) {
                u32 b0, b1, b2, b3;
                ldsm4t(rowb + ntp*32, b0, b1, b2, b3);
                mma16816(acc[2*ntp],   a0h,a1h,a2h,a3h, b0, b1);
                mma16816(acc[2*ntp+1], a0h,a1h,a2h,a3h, b2, b3);
                mma16816(acc[2*ntp],   a0r,a1r,a2r,a3r, b0, b1);
                mma16816(acc[2*ntp+1], a0r,a1r,a2r,a3r, b2, b3);
                u32 c0, c1, c2, c3;
                ldsm4t(rowb + 17408 + ntp*32, c0, c1, c2, c3);
                mma16816(acc[2*ntp],   a0h,a1h,a2h,a3h, c0, c1);
                mma16816(acc[2*ntp+1], a0h,a1h,a2h,a3h, c2, c3);
            }
        }
        __syncthreads();
        if (i + 2 < BLK_) {
            const char* src0 = (const char*)(g_Wb0 + (size_t)(k*BLK_ + i + 2)*WTILE_);
            const char* src1 = (const char*)(g_Wb1 + (size_t)(k*BLK_ + i + 2)*WTILE_);
            u32 dst = sw + s*WSTAGE_;
            #pragma unroll
            for (int t = 0; t < 5; t++) {
                int idx = tid + t*256;
                if (idx < 1088) {
                    cpa16(dst + idx*16, src0 + idx*16);
                    cpa16(dst + 17408 + idx*16, src1 + idx*16);
                }
            }
        }
        cpa_commit();
    }

    // ---- epilogue: write split-K partials (n < 97) ----
    float* base0 = g_part + ((size_t)k*BP_ + r0 + rg)*NL_;
    float* base1 = g_part + ((size_t)k*BP_ + r0 + rg + 8)*NL_;
    #pragma unroll
    for (int nt = 0; nt < 13; nt++) {
        int n0 = nt*8 + tg*2;
        if (n0 < NL_) { base0[n0] = acc[nt][0]; base1[n0] = acc[nt][2]; }
        if (n0 + 1 < NL_) { base0[n0+1] = acc[nt][1]; base1[n0+1] = acc[nt][3]; }
    }
}

// ---------------- kernel G: reduce split-K partials + bias -----------------
__global__ void k_reduce(const float* __restrict__ bbi, float* __restrict__ out) {
    int idx = blockIdx.x*256 + threadIdx.x;
    if (idx >= BP_*NL_) return;
    int n = idx % NL_;
    float s = bbi[n];
    #pragma unroll
    for (int k = 0; k < KCH_; k++)
        s += g_part[(size_t)k*BP_*NL_ + idx];
    out[idx] = s;
}

// ---------------- launch ---------------------------------------------------
extern "C" void kernel_launch(void* const* d_in, const int* in_sizes, int n_in,
                              void* d_out, int out_size) {
    const float* seq  = (const float*)d_in[0];
    const float* att  = (const float*)d_in[1];
    const int*   mpos = (const int*)d_in[2];
    const int*   hts  = (const int*)d_in[3];
    const float* Wh   = (const float*)d_in[4];
    const float* bh   = (const float*)d_in[5];
    const float* Wt   = (const float*)d_in[6];
    const float* bt   = (const float*)d_in[7];
    const float* Wbi  = (const float*)d_in[8];
    const float* bbi  = (const float*)d_in[9];
    float* out = (float*)d_out;

    static bool attr_set = false;
    if (!attr_set) {
        cudaFuncSetAttribute(k_bilinear_mma,
            cudaFuncAttributeMaxDynamicSharedMemorySize, SMEMB_);
        attr_set = true;
    }

    k_padW_tc<<<KCH_*BLK_, 256>>>(Wbi);
    k_ent_emb<<<B_*NE_, 256>>>(seq, mpos);
    k_ent_att<<<B_*NE_*H_, 256>>>(att, mpos);
    k_ht<<<B_*P_, 256>>>(hts);
    k_rs<<<dim3(D_/128, P_/64, B_), 256>>>(seq);
    k_extract<<<dim3(BP_/64, D_/128, 2), 128>>>(hts, Wh, bh, Wt, bt);
    k_bilinear_mma<<<dim3(BP_/128, KCH_), 256, SMEMB_>>>();
    k_reduce<<<(BP_*NL_ + 255)/256, 256>>>(bbi, out);
}

// round 6
// speedup vs baseline: 2.8066x; 1.5215x over previous
#include <cuda_runtime.h>
#include <cuda_bf16.h>
#include <math.h>
#include <stdint.h>

#define B_ 4
#define L_ 1024
#define D_ 768
#define H_ 12
#define NE_ 42
#define M_ 4
#define P_ 512
#define BLK_ 64
#define NL_ 97
#define OFFSET_ 1
#define BP_ (B_*P_)          // 2048
#define KCH_ (D_/BLK_)       // 12 channel blocks
#define WPITCH_ 136          // padded n (bf16), 272B rows -> conflict-free ldmatrix
#define WTILE_ (BLK_*WPITCH_) // per (k,i) split tile for bilinear W

typedef unsigned long long u64;
typedef unsigned int u32;

// ---------------- helpers ---------------------------------------------------
__device__ __forceinline__ u32 smem_u32(const void* p) {
    u32 a; asm("{ .reg .u64 t; cvta.to.shared.u64 t, %1; cvt.u32.u64 %0, t; }"
               : "=r"(a) : "l"(p));
    return a;
}
// pack two f32 -> bf16x2 (first arg -> LOWER half)
__device__ __forceinline__ u32 cvt_bf2(float lo, float hi) {
    u32 d; asm("cvt.rn.bf16x2.f32 %0, %1, %2;" : "=r"(d) : "f"(hi), "f"(lo));
    return d;
}
__device__ __forceinline__ float bf_lo_f(u32 c) { return __uint_as_float(c << 16); }
__device__ __forceinline__ float bf_hi_f(u32 c) { return __uint_as_float(c & 0xFFFF0000u); }

__device__ __forceinline__ void cpa16(u32 dst, const void* src) {
    asm volatile("cp.async.cg.shared.global [%0], [%1], 16;"
                 :: "r"(dst), "l"(src) : "memory");
}
__device__ __forceinline__ void cpa_commit() {
    asm volatile("cp.async.commit_group;" ::: "memory");
}
__device__ __forceinline__ void cpa_wait1() {
    asm volatile("cp.async.wait_group 1;" ::: "memory");
}
__device__ __forceinline__ void ldsm4(u32 addr, u32& r0, u32& r1, u32& r2, u32& r3) {
    asm volatile("ldmatrix.sync.aligned.m8n8.x4.shared.b16 {%0,%1,%2,%3}, [%4];"
                 : "=r"(r0), "=r"(r1), "=r"(r2), "=r"(r3) : "r"(addr));
}
__device__ __forceinline__ void ldsm4t(u32 addr, u32& r0, u32& r1, u32& r2, u32& r3) {
    asm volatile("ldmatrix.sync.aligned.m8n8.x4.trans.shared.b16 {%0,%1,%2,%3}, [%4];"
                 : "=r"(r0), "=r"(r1), "=r"(r2), "=r"(r3) : "r"(addr));
}
__device__ __forceinline__ void mma16816(float* d,
                                         u32 a0, u32 a1, u32 a2, u32 a3,
                                         u32 b0, u32 b1) {
    asm volatile(
        "mma.sync.aligned.m16n8k16.row.col.f32.bf16.bf16.f32 "
        "{%0,%1,%2,%3}, {%4,%5,%6,%7}, {%8,%9}, {%0,%1,%2,%3};"
        : "+f"(d[0]), "+f"(d[1]), "+f"(d[2]), "+f"(d[3])
        : "r"(a0), "r"(a1), "r"(a2), "r"(a3), "r"(b0), "r"(b1));
}

// ---------------- scratch (device globals; no runtime allocation) ----------
__device__ float g_ent_att[B_*NE_*H_*L_];
__device__ __nv_bfloat16 g_ent_hi[B_*NE_*D_], g_ent_lo[B_*NE_*D_];
__device__ __nv_bfloat16 g_seq_hi[B_*L_*D_],  g_seq_lo[B_*L_*D_];
__device__ __nv_bfloat16 g_ht_hi[B_*P_*L_],   g_ht_lo[B_*P_*L_];
__device__ __nv_bfloat16 g_Ah_hi[BP_*2*D_], g_Ah_lo[BP_*2*D_];
__device__ __nv_bfloat16 g_At_hi[BP_*2*D_], g_At_lo[BP_*2*D_];
__device__ __nv_bfloat16 g_Wx_hi[2*2*D_*D_], g_Wx_lo[2*2*D_*D_];  // [Wh|Wt]
__device__ float g_zs[BP_*D_], g_zo[BP_*D_];
__device__ float g_part[KCH_*BP_*NL_];
__device__ __nv_bfloat16 g_Wb0[KCH_*BLK_*WTILE_], g_Wb1[KCH_*BLK_*WTILE_];

// ---------------- kernel S: fp32 -> bf16 hi/lo split (seq, Wh, Wt) --------
__global__ void k_split(const float* __restrict__ in, int which, int npair) {
    __nv_bfloat16 *hi, *lo;
    if (which == 0)      { hi = g_seq_hi; lo = g_seq_lo; }
    else if (which == 1) { hi = g_Wx_hi;  lo = g_Wx_lo; }
    else                 { hi = g_Wx_hi + 2*D_*D_; lo = g_Wx_lo + 2*D_*D_; }
    for (int i = blockIdx.x*blockDim.x + threadIdx.x; i < npair;
         i += gridDim.x*blockDim.x) {
        float v0 = in[2*i], v1 = in[2*i+1];
        u32 h = cvt_bf2(v0, v1);
        u32 r = cvt_bf2(v0 - bf_lo_f(h), v1 - bf_hi_f(h));
        ((u32*)hi)[i] = h;
        ((u32*)lo)[i] = r;
    }
}

// ---------------- kernel A: entity embeds = logsumexp (bf16 split out) -----
__global__ void k_ent_emb(const float* __restrict__ seq,
                          const int* __restrict__ mpos) {
    int be = blockIdx.x;
    int b  = be / NE_;
    int base = be * M_;
    int p0 = mpos[base+0] + OFFSET_;
    int p1 = mpos[base+1] + OFFSET_;
    int p2 = mpos[base+2] + OFFSET_;
    int p3 = mpos[base+3] + OFFSET_;
    const float* s0 = seq + ((size_t)b*L_ + p0)*D_;
    const float* s1 = seq + ((size_t)b*L_ + p1)*D_;
    const float* s2 = seq + ((size_t)b*L_ + p2)*D_;
    const float* s3 = seq + ((size_t)b*L_ + p3)*D_;
    for (int d = threadIdx.x; d < D_; d += blockDim.x) {
        float x0 = s0[d], x1 = s1[d], x2 = s2[d], x3 = s3[d];
        float mx = fmaxf(fmaxf(x0,x1), fmaxf(x2,x3));
        float v = mx + logf(expf(x0-mx) + expf(x1-mx) + expf(x2-mx) + expf(x3-mx));
        __nv_bfloat16 hb = __float2bfloat16(v);
        g_ent_hi[(size_t)be*D_ + d] = hb;
        g_ent_lo[(size_t)be*D_ + d] = __float2bfloat16(v - __bfloat162float(hb));
    }
}

// ---------------- kernel B: entity attention = mean over mention rows ------
__global__ void k_ent_att(const float* __restrict__ att,
                          const int* __restrict__ mpos) {
    int id = blockIdx.x;
    int h  = id % H_;
    int be = id / H_;
    int b  = be / NE_;
    int base = be * M_;
    const float* a = att + (((size_t)b*H_ + h)*L_)*L_;
    const float* r0 = a + (size_t)(mpos[base+0]+OFFSET_)*L_;
    const float* r1 = a + (size_t)(mpos[base+1]+OFFSET_)*L_;
    const float* r2 = a + (size_t)(mpos[base+2]+OFFSET_)*L_;
    const float* r3 = a + (size_t)(mpos[base+3]+OFFSET_)*L_;
    float* out = g_ent_att + ((size_t)be*H_ + h)*L_;
    for (int l = threadIdx.x; l < L_; l += blockDim.x)
        out[l] = 0.25f * (r0[l] + r1[l] + r2[l] + r3[l]);
}

// ---------------- kernel C: per-pair channel attention -> bf16 split -------
__global__ void k_ht(const int* __restrict__ hts) {
    int bp = blockIdx.x;
    int b  = bp / P_;
    int hi = hts[bp*2 + 0];
    int ti = hts[bp*2 + 1];
    const float* ah = g_ent_att + (size_t)(b*NE_ + hi)*H_*L_;
    const float* at = g_ent_att + (size_t)(b*NE_ + ti)*H_*L_;
    const int T = 256;
    float v[4];
    float lsum = 0.f;
    #pragma unroll
    for (int it = 0; it < 4; it++) {
        int l = threadIdx.x + it*T;
        float acc = 0.f;
        #pragma unroll
        for (int h = 0; h < H_; h++)
            acc += ah[h*L_ + l] * at[h*L_ + l];
        acc *= (1.f/H_);
        v[it] = acc;
        lsum += acc;
    }
    __shared__ float red[32];
    #pragma unroll
    for (int o = 16; o; o >>= 1) lsum += __shfl_down_sync(~0u, lsum, o);
    if ((threadIdx.x & 31) == 0) red[threadIdx.x >> 5] = lsum;
    __syncthreads();
    if (threadIdx.x < 8) {
        float t = red[threadIdx.x];
        #pragma unroll
        for (int o = 4; o; o >>= 1) t += __shfl_down_sync(0xffu, t, o);
        if (threadIdx.x == 0) red[0] = 1.f / (t + 1e-5f);
    }
    __syncthreads();
    float inv = red[0];
    #pragma unroll
    for (int it = 0; it < 4; it++) {
        int l = threadIdx.x + it*T;
        float vv = v[it] * inv;
        __nv_bfloat16 hb = __float2bfloat16(vv);
        g_ht_hi[(size_t)bp*L_ + l] = hb;
        g_ht_lo[(size_t)bp*L_ + l] = __float2bfloat16(vv - __bfloat162float(hb));
    }
}

// ---------------- kernel P: gather entity halves into A_h / A_t ------------
__global__ void k_prepA(const int* __restrict__ hts) {
    int bp = blockIdx.x;
    int b  = bp / P_;
    int t  = threadIdx.x;            // 384
    int arr = t / 96, c = t % 96;
    int hidx = hts[bp*2], tidx = hts[bp*2+1];
    size_t ro = (size_t)bp*2*D_;
    const uint4* src; uint4* dst;
    if (arr == 0) { src = (const uint4*)(g_ent_hi + ((size_t)b*NE_+hidx)*D_); dst = (uint4*)(g_Ah_hi + ro); }
    else if (arr == 1) { src = (const uint4*)(g_ent_lo + ((size_t)b*NE_+hidx)*D_); dst = (uint4*)(g_Ah_lo + ro); }
    else if (arr == 2) { src = (const uint4*)(g_ent_hi + ((size_t)b*NE_+tidx)*D_); dst = (uint4*)(g_At_hi + ro); }
    else { src = (const uint4*)(g_ent_lo + ((size_t)b*NE_+tidx)*D_); dst = (uint4*)(g_At_lo + ro); }
    dst[c] = src[c];
}

// ---------------- generic mma GEMM core (128x128 tile, K-chunk 32) ---------
#define GA_PITCH 80                  // bytes per A smem row (40 bf16)
#define GB_PITCH 272                 // bytes per B smem row (136 bf16)
#define GSA_ 10240                   // 128*80
#define GSB_ 8704                    // 32*272
#define GSTAGE_ 37888                // 2*GSA_ + 2*GSB_
#define GSM_ 75776

__device__ __forceinline__ void g_load_stage(u32 sbase,
    const __nv_bfloat16* __restrict__ Ah, const __nv_bfloat16* __restrict__ Al,
    int lda,
    const __nv_bfloat16* __restrict__ Bh, const __nv_bfloat16* __restrict__ Bl,
    int r0, int n0, int kc, int tid)
{
    #pragma unroll
    for (int t = 0; t < 2; t++) {
        int idx = tid + t*256;             // 512 = 128 rows x 4 chunks
        int row = idx >> 2, c = idx & 3;
        size_t so = (size_t)(r0+row)*lda + kc + c*8;
        cpa16(sbase + row*GA_PITCH + c*16, Ah + so);
        cpa16(sbase + GSA_ + row*GA_PITCH + c*16, Al + so);
    }
    #pragma unroll
    for (int t = 0; t < 2; t++) {
        int idx = tid + t*256;             // 512 = 32 rows x 16 chunks
        int row = idx >> 4, c = idx & 15;
        size_t so = (size_t)(kc+row)*D_ + n0 + c*8;
        cpa16(sbase + 2*GSA_ + row*GB_PITCH + c*16, Bh + so);
        cpa16(sbase + 2*GSA_ + GSB_ + row*GB_PITCH + c*16, Bl + so);
    }
}

__device__ __forceinline__ void g_compute(u32 sbase, int w, int l,
                                          float (*acc)[4]) {
    int wm = w >> 1, wn = w & 1;
    u32 abase = sbase + (u32)((wm*32 + (l&15))*GA_PITCH + (l>>4)*16);
    u32 bbase = sbase + 2*GSA_ +
                (u32)((l&15)*GB_PITCH + (wn*64 + (l>>4)*8)*2);
    #pragma unroll
    for (int kk = 0; kk < 2; kk++) {
        u32 ah[2][4], al[2][4];
        #pragma unroll
        for (int mi = 0; mi < 2; mi++) {
            ldsm4(abase + mi*16*GA_PITCH + kk*32,
                  ah[mi][0], ah[mi][1], ah[mi][2], ah[mi][3]);
            ldsm4(abase + GSA_ + mi*16*GA_PITCH + kk*32,
                  al[mi][0], al[mi][1], al[mi][2], al[mi][3]);
        }
        u32 bb = bbase + kk*16*GB_PITCH;
        #pragma unroll
        for (int ntp = 0; ntp < 4; ntp++) {
            u32 b0,b1,b2,b3, c0,c1,c2,c3;
            ldsm4t(bb + ntp*32, b0,b1,b2,b3);
            ldsm4t(bb + GSB_ + ntp*32, c0,c1,c2,c3);
            #pragma unroll
            for (int mi = 0; mi < 2; mi++) {
                float* A0 = acc[mi*8 + 2*ntp];
                float* A1 = acc[mi*8 + 2*ntp + 1];
                mma16816(A0, ah[mi][0],ah[mi][1],ah[mi][2],ah[mi][3], b0,b1);
                mma16816(A1, ah[mi][0],ah[mi][1],ah[mi][2],ah[mi][3], b2,b3);
                mma16816(A0, ah[mi][0],ah[mi][1],ah[mi][2],ah[mi][3], c0,c1);
                mma16816(A1, ah[mi][0],ah[mi][1],ah[mi][2],ah[mi][3], c2,c3);
                mma16816(A0, al[mi][0],al[mi][1],al[mi][2],al[mi][3], b0,b1);
                mma16816(A1, al[mi][0],al[mi][1],al[mi][2],al[mi][3], b2,b3);
            }
        }
    }
}

// ---------------- kernel D: rs GEMM -> split bf16 into A halves ------------
__global__ void __launch_bounds__(256, 1) k_rs_mma() {
    extern __shared__ char smem[];
    u32 sb = smem_u32(smem);
    int tid = threadIdx.x, w = tid >> 5, l = tid & 31;
    int r0 = blockIdx.x * 128, n0 = blockIdx.y * 128;
    int b = r0 / P_;
    const __nv_bfloat16* Ah = g_ht_hi;
    const __nv_bfloat16* Al = g_ht_lo;
    const __nv_bfloat16* Bh = g_seq_hi + (size_t)b*L_*D_;
    const __nv_bfloat16* Bl = g_seq_lo + (size_t)b*L_*D_;
    float acc[16][4];
    #pragma unroll
    for (int f = 0; f < 16; f++)
        #pragma unroll
        for (int e = 0; e < 4; e++) acc[f][e] = 0.f;
    const int NK = L_/32;           // 32
    g_load_stage(sb, Ah, Al, L_, Bh, Bl, r0, n0, 0, tid);  cpa_commit();
    g_load_stage(sb+GSTAGE_, Ah, Al, L_, Bh, Bl, r0, n0, 32, tid); cpa_commit();
    for (int i = 0; i < NK; i++) {
        cpa_wait1(); __syncthreads();
        g_compute(sb + (i&1)*GSTAGE_, w, l, acc);
        __syncthreads();
        if (i + 2 < NK)
            g_load_stage(sb + (i&1)*GSTAGE_, Ah, Al, L_, Bh, Bl, r0, n0, (i+2)*32, tid);
        cpa_commit();
    }
    int wm = w >> 1, wn = w & 1, g = l >> 2, tg = l & 3;
    #pragma unroll
    for (int mi = 0; mi < 2; mi++) {
        int row = r0 + wm*32 + mi*16 + g;
        #pragma unroll
        for (int f = 0; f < 8; f++) {
            int col = n0 + wn*64 + f*8 + tg*2;
            float* a4 = acc[mi*8 + f];
            #pragma unroll
            for (int rh = 0; rh < 2; rh++) {
                float v0 = a4[rh*2], v1 = a4[rh*2+1];
                u32 hp = cvt_bf2(v0, v1);
                u32 lp = cvt_bf2(v0 - bf_lo_f(hp), v1 - bf_hi_f(hp));
                size_t o = (size_t)(row + rh*8)*(2*D_) + D_ + col;
                *(u32*)(g_Ah_hi + o) = hp;
                *(u32*)(g_At_hi + o) = hp;
                *(u32*)(g_Ah_lo + o) = lp;
                *(u32*)(g_At_lo + o) = lp;
            }
        }
    }
}

// ---------------- kernel E: extractors via mma -> zs/zo fp32 ---------------
__global__ void __launch_bounds__(256, 1) k_extract_mma(
        const float* __restrict__ bh, const float* __restrict__ bt) {
    extern __shared__ char smem[];
    u32 sb = smem_u32(smem);
    int tid = threadIdx.x, w = tid >> 5, l = tid & 31;
    int sel = blockIdx.z;
    int r0 = blockIdx.x * 128, n0 = blockIdx.y * 128;
    const __nv_bfloat16* Ah = sel ? g_At_hi : g_Ah_hi;
    const __nv_bfloat16* Al = sel ? g_At_lo : g_Ah_lo;
    const __nv_bfloat16* Bh = g_Wx_hi + (size_t)sel*2*D_*D_;
    const __nv_bfloat16* Bl = g_Wx_lo + (size_t)sel*2*D_*D_;
    const float* bias = sel ? bt : bh;
    float* out = sel ? g_zo : g_zs;
    float acc[16][4];
    #pragma unroll
    for (int f = 0; f < 16; f++)
        #pragma unroll
        for (int e = 0; e < 4; e++) acc[f][e] = 0.f;
    const int NK = (2*D_)/32;       // 48
    g_load_stage(sb, Ah, Al, 2*D_, Bh, Bl, r0, n0, 0, tid);  cpa_commit();
    g_load_stage(sb+GSTAGE_, Ah, Al, 2*D_, Bh, Bl, r0, n0, 32, tid); cpa_commit();
    for (int i = 0; i < NK; i++) {
        cpa_wait1(); __syncthreads();
        g_compute(sb + (i&1)*GSTAGE_, w, l, acc);
        __syncthreads();
        if (i + 2 < NK)
            g_load_stage(sb + (i&1)*GSTAGE_, Ah, Al, 2*D_, Bh, Bl, r0, n0, (i+2)*32, tid);
        cpa_commit();
    }
    int wm = w >> 1, wn = w & 1, g = l >> 2, tg = l & 3;
    #pragma unroll
    for (int mi = 0; mi < 2; mi++) {
        int row = r0 + wm*32 + mi*16 + g;
        #pragma unroll
        for (int f = 0; f < 8; f++) {
            int col = n0 + wn*64 + f*8 + tg*2;
            float b0v = bias[col], b1v = bias[col+1];
            float* a4 = acc[mi*8 + f];
            out[(size_t)row*D_ + col]       = tanhf(a4[0] + b0v);
            out[(size_t)row*D_ + col+1]     = tanhf(a4[1] + b1v);
            out[(size_t)(row+8)*D_ + col]   = tanhf(a4[2] + b0v);
            out[(size_t)(row+8)*D_ + col+1] = tanhf(a4[3] + b1v);
        }
    }
}

// ---------------- kernel Wpad: split W_bi into bf16 hi/lo, padded ----------
__global__ void k_padW_tc(const float* __restrict__ Wbi) {
    int ki = blockIdx.x;               // 0..767 (= k*64 + i)
    __nv_bfloat16* d0 = g_Wb0 + (size_t)ki*WTILE_;
    __nv_bfloat16* d1 = g_Wb1 + (size_t)ki*WTILE_;
    for (int idx = threadIdx.x; idx < WTILE_; idx += blockDim.x) {
        int j = idx / WPITCH_, n = idx % WPITCH_;
        float wv = (n < NL_) ? Wbi[((size_t)(ki*BLK_ + j))*NL_ + n] : 0.f;
        float hi = __bfloat162float(__float2bfloat16(wv));
        d0[idx] = __float2bfloat16(wv);
        d1[idx] = __float2bfloat16(wv - hi);
    }
}

// ---------------- kernel F: bilinear classifier via mma.sync bf16 ----------
#define SM_ZS 0                         // [128][65] f32
#define SM_ZO 33280                     // [128][66] f32
#define SM_W  67072
#define WSTAGE_ 34816
#define SMEMB_ (SM_W + 2*WSTAGE_)       // 136704

__global__ void __launch_bounds__(256, 1) k_bilinear_mma() {
    extern __shared__ char smem[];
    float* zs_s = (float*)(smem + SM_ZS);   // pitch 65
    float* zo_s = (float*)(smem + SM_ZO);   // pitch 66
    u32 sw = smem_u32(smem) + SM_W;
    int tid = threadIdx.x, w = tid >> 5, l = tid & 31;
    int g = l >> 2, tg = l & 3;
    int k  = blockIdx.y;
    int r0 = blockIdx.x * 128;

    #pragma unroll
    for (int s = 0; s < 2; s++) {
        const char* src0 = (const char*)(g_Wb0 + (size_t)(k*BLK_ + s)*WTILE_);
        const char* src1 = (const char*)(g_Wb1 + (size_t)(k*BLK_ + s)*WTILE_);
        u32 dst = sw + s*WSTAGE_;
        #pragma unroll
        for (int t = 0; t < 5; t++) {
            int idx = tid + t*256;
            if (idx < 1088) {
                cpa16(dst + idx*16, src0 + idx*16);
                cpa16(dst + 17408 + idx*16, src1 + idx*16);
            }
        }
        cpa_commit();
    }

    for (int idx = tid; idx < 128*64; idx += 256) {
        int r = idx >> 6, c = idx & 63;
        zs_s[r*65 + c] = g_zs[(size_t)(r0+r)*D_ + k*BLK_ + c];
        zo_s[r*66 + c] = g_zo[(size_t)(r0+r)*D_ + k*BLK_ + c];
    }
    __syncthreads();

    int rg = w*16 + g;
    float2 zoA[4][2], zoB[4][2];
    #pragma unroll
    for (int jc = 0; jc < 4; jc++) {
        zoA[jc][0] = *(float2*)&zo_s[rg*66     + jc*16 + tg*2];
        zoA[jc][1] = *(float2*)&zo_s[rg*66     + jc*16 + tg*2 + 8];
        zoB[jc][0] = *(float2*)&zo_s[(rg+8)*66 + jc*16 + tg*2];
        zoB[jc][1] = *(float2*)&zo_s[(rg+8)*66 + jc*16 + tg*2 + 8];
    }

    float acc[14][4];
    #pragma unroll
    for (int t = 0; t < 14; t++)
        #pragma unroll
        for (int e = 0; e < 4; e++) acc[t][e] = 0.f;

    u32 laneoff = (u32)((l & 15)*272 + (l >> 4)*16);

    for (int i = 0; i < BLK_; i++) {
        int s = i & 1;
        cpa_wait1();
        __syncthreads();
        float zs0 = zs_s[rg*65 + i];
        float zs1 = zs_s[(rg+8)*65 + i];
        u32 sbase = sw + s*WSTAGE_;
        #pragma unroll
        for (int jc = 0; jc < 4; jc++) {
            float p0x = zs0*zoA[jc][0].x, p0y = zs0*zoA[jc][0].y;
            float p1x = zs1*zoB[jc][0].x, p1y = zs1*zoB[jc][0].y;
            float p2x = zs0*zoA[jc][1].x, p2y = zs0*zoA[jc][1].y;
            float p3x = zs1*zoB[jc][1].x, p3y = zs1*zoB[jc][1].y;
            u32 a0h = cvt_bf2(p0x, p0y);
            u32 a1h = cvt_bf2(p1x, p1y);
            u32 a2h = cvt_bf2(p2x, p2y);
            u32 a3h = cvt_bf2(p3x, p3y);
            u32 a0r = cvt_bf2(p0x - bf_lo_f(a0h), p0y - bf_hi_f(a0h));
            u32 a1r = cvt_bf2(p1x - bf_lo_f(a1h), p1y - bf_hi_f(a1h));
            u32 a2r = cvt_bf2(p2x - bf_lo_f(a2h), p2y - bf_hi_f(a2h));
            u32 a3r = cvt_bf2(p3x - bf_lo_f(a3h), p3y - bf_hi_f(a3h));
            u32 rowb = sbase + (u32)(jc*16*272) + laneoff;
            #pragma unroll
            for (int ntp = 0; ntp < 7; ntp++) {
                u32 b0, b1, b2, b3;
                ldsm4t(rowb + ntp*32, b0, b1, b2, b3);
                mma16816(acc[2*ntp],   a0h,a1h,a2h,a3h, b0, b1);
                mma16816(acc[2*ntp+1], a0h,a1h,a2h,a3h, b2, b3);
                mma16816(acc[2*ntp],   a0r,a1r,a2r,a3r, b0, b1);
                mma16816(acc[2*ntp+1], a0r,a1r,a2r,a3r, b2, b3);
                u32 c0, c1, c2, c3;
                ldsm4t(rowb + 17408 + ntp*32, c0, c1, c2, c3);
                mma16816(acc[2*ntp],   a0h,a1h,a2h,a3h, c0, c1);
                mma16816(acc[2*ntp+1], a0h,a1h,a2h,a3h, c2, c3);
            }
        }
        __syncthreads();
        if (i + 2 < BLK_) {
            const char* src0 = (const char*)(g_Wb0 + (size_t)(k*BLK_ + i + 2)*WTILE_);
            const char* src1 = (const char*)(g_Wb1 + (size_t)(k*BLK_ + i + 2)*WTILE_);
            u32 dst = sw + s*WSTAGE_;
            #pragma unroll
            for (int t = 0; t < 5; t++) {
                int idx = tid + t*256;
                if (idx < 1088) {
                    cpa16(dst + idx*16, src0 + idx*16);
                    cpa16(dst + 17408 + idx*16, src1 + idx*16);
                }
            }
        }
        cpa_commit();
    }

    float* base0 = g_part + ((size_t)k*BP_ + r0 + rg)*NL_;
    float* base1 = g_part + ((size_t)k*BP_ + r0 + rg + 8)*NL_;
    #pragma unroll
    for (int nt = 0; nt < 13; nt++) {
        int n0 = nt*8 + tg*2;
        if (n0 < NL_) { base0[n0] = acc[nt][0]; base1[n0] = acc[nt][2]; }
        if (n0 + 1 < NL_) { base0[n0+1] = acc[nt][1]; base1[n0+1] = acc[nt][3]; }
    }
}

// ---------------- kernel G: reduce split-K partials + bias -----------------
__global__ void k_reduce(const float* __restrict__ bbi, float* __restrict__ out) {
    int idx = blockIdx.x*256 + threadIdx.x;
    if (idx >= BP_*NL_) return;
    int n = idx % NL_;
    float s = bbi[n];
    #pragma unroll
    for (int k = 0; k < KCH_; k++)
        s += g_part[(size_t)k*BP_*NL_ + idx];
    out[idx] = s;
}

// ---------------- launch ---------------------------------------------------
extern "C" void kernel_launch(void* const* d_in, const int* in_sizes, int n_in,
                              void* d_out, int out_size) {
    const float* seq  = (const float*)d_in[0];
    const float* att  = (const float*)d_in[1];
    const int*   mpos = (const int*)d_in[2];
    const int*   hts  = (const int*)d_in[3];
    const float* Wh   = (const float*)d_in[4];
    const float* bh   = (const float*)d_in[5];
    const float* Wt   = (const float*)d_in[6];
    const float* bt   = (const float*)d_in[7];
    const float* Wbi  = (const float*)d_in[8];
    const float* bbi  = (const float*)d_in[9];
    float* out = (float*)d_out;

    static bool attr_set = false;
    if (!attr_set) {
        cudaFuncSetAttribute(k_bilinear_mma,
            cudaFuncAttributeMaxDynamicSharedMemorySize, SMEMB_);
        cudaFuncSetAttribute(k_rs_mma,
            cudaFuncAttributeMaxDynamicSharedMemorySize, GSM_);
        cudaFuncSetAttribute(k_extract_mma,
            cudaFuncAttributeMaxDynamicSharedMemorySize, GSM_);
        attr_set = true;
    }

    k_split<<<2048, 256>>>(seq, 0, B_*L_*D_/2);
    k_split<<<1152, 256>>>(Wh, 1, 2*D_*D_/2);
    k_split<<<1152, 256>>>(Wt, 2, 2*D_*D_/2);
    k_padW_tc<<<KCH_*BLK_, 256>>>(Wbi);
    k_ent_emb<<<B_*NE_, 256>>>(seq, mpos);
    k_ent_att<<<B_*NE_*H_, 256>>>(att, mpos);
    k_ht<<<B_*P_, 256>>>(hts);
    k_prepA<<<BP_, 384>>>(hts);
    k_rs_mma<<<dim3(BP_/128, D_/128), 256, GSM_>>>();
    k_extract_mma<<<dim3(BP_/128, D_/128, 2), 256, GSM_>>>(bh, bt);
    k_bilinear_mma<<<dim3(BP_/128, KCH_), 256, SMEMB_>>>();
    k_reduce<<<(BP_*NL_ + 255)/256, 256>>>(bbi, out);
}

// round 7
// speedup vs baseline: 3.3953x; 1.2097x over previous
#include <cuda_runtime.h>
#include <cuda_bf16.h>
#include <math.h>
#include <stdint.h>

#define B_ 4
#define L_ 1024
#define D_ 768
#define H_ 12
#define NE_ 42
#define M_ 4
#define P_ 512
#define BLK_ 64
#define NL_ 97
#define OFFSET_ 1
#define BP_ (B_*P_)          // 2048
#define KCH_ (D_/BLK_)       // 12 channel blocks
#define ISEG_ 3              // bilinear i-range split
#define KSLAB_ (ISEG_*KCH_)  // 36 partial slabs
#define WPITCH_ 136          // padded n (bf16), 272B rows -> conflict-free ldmatrix
#define WTILE_ (BLK_*WPITCH_) // per (k,i) split tile for bilinear W

typedef unsigned long long u64;
typedef unsigned int u32;

// ---------------- helpers ---------------------------------------------------
__device__ __forceinline__ u32 smem_u32(const void* p) {
    u32 a; asm("{ .reg .u64 t; cvta.to.shared.u64 t, %1; cvt.u32.u64 %0, t; }"
               : "=r"(a) : "l"(p));
    return a;
}
// pack two f32 -> bf16x2 (first arg -> LOWER half)
__device__ __forceinline__ u32 cvt_bf2(float lo, float hi) {
    u32 d; asm("cvt.rn.bf16x2.f32 %0, %1, %2;" : "=r"(d) : "f"(hi), "f"(lo));
    return d;
}
__device__ __forceinline__ float bf_lo_f(u32 c) { return __uint_as_float(c << 16); }
__device__ __forceinline__ float bf_hi_f(u32 c) { return __uint_as_float(c & 0xFFFF0000u); }

__device__ __forceinline__ void cpa16(u32 dst, const void* src) {
    asm volatile("cp.async.cg.shared.global [%0], [%1], 16;"
                 :: "r"(dst), "l"(src) : "memory");
}
__device__ __forceinline__ void cpa_commit() {
    asm volatile("cp.async.commit_group;" ::: "memory");
}
__device__ __forceinline__ void cpa_wait1() {
    asm volatile("cp.async.wait_group 1;" ::: "memory");
}
__device__ __forceinline__ void ldsm4(u32 addr, u32& r0, u32& r1, u32& r2, u32& r3) {
    asm volatile("ldmatrix.sync.aligned.m8n8.x4.shared.b16 {%0,%1,%2,%3}, [%4];"
                 : "=r"(r0), "=r"(r1), "=r"(r2), "=r"(r3) : "r"(addr));
}
__device__ __forceinline__ void ldsm4t(u32 addr, u32& r0, u32& r1, u32& r2, u32& r3) {
    asm volatile("ldmatrix.sync.aligned.m8n8.x4.trans.shared.b16 {%0,%1,%2,%3}, [%4];"
                 : "=r"(r0), "=r"(r1), "=r"(r2), "=r"(r3) : "r"(addr));
}
__device__ __forceinline__ void mma16816(float* d,
                                         u32 a0, u32 a1, u32 a2, u32 a3,
                                         u32 b0, u32 b1) {
    asm volatile(
        "mma.sync.aligned.m16n8k16.row.col.f32.bf16.bf16.f32 "
        "{%0,%1,%2,%3}, {%4,%5,%6,%7}, {%8,%9}, {%0,%1,%2,%3};"
        : "+f"(d[0]), "+f"(d[1]), "+f"(d[2]), "+f"(d[3])
        : "r"(a0), "r"(a1), "r"(a2), "r"(a3), "r"(b0), "r"(b1));
}

// ---------------- scratch (device globals; no runtime allocation) ----------
__device__ float g_ent_att[B_*NE_*H_*L_];
__device__ __nv_bfloat16 g_ent_hi[B_*NE_*D_], g_ent_lo[B_*NE_*D_];
__device__ __nv_bfloat16 g_seq_hi[B_*L_*D_],  g_seq_lo[B_*L_*D_];
__device__ __nv_bfloat16 g_ht_hi[B_*P_*L_],   g_ht_lo[B_*P_*L_];
__device__ __nv_bfloat16 g_Ah_hi[BP_*2*D_], g_Ah_lo[BP_*2*D_];
__device__ __nv_bfloat16 g_At_hi[BP_*2*D_], g_At_lo[BP_*2*D_];
__device__ __nv_bfloat16 g_Wx_hi[2*2*D_*D_], g_Wx_lo[2*2*D_*D_];  // [Wh|Wt]
__device__ float g_zs[BP_*D_], g_zo[BP_*D_];
__device__ float g_ep[4*BP_*D_];                 // extract K-split partials
__device__ float g_part[KSLAB_*BP_*NL_];         // bilinear partials
__device__ __nv_bfloat16 g_Wb0[KCH_*BLK_*WTILE_], g_Wb1[KCH_*BLK_*WTILE_];

// ---------------- kernel S: fp32 -> bf16 hi/lo split (seq + Wh + Wt) -------
#define SPLIT_SEQ (B_*L_*D_/2)
#define SPLIT_W   (2*D_*D_/2)
__global__ void k_split_all(const float* __restrict__ seq,
                            const float* __restrict__ Wh,
                            const float* __restrict__ Wt) {
    int i = blockIdx.x*blockDim.x + threadIdx.x;
    const float* in; u32 *hi, *lo; int off;
    if (i < SPLIT_SEQ) {
        in = seq; off = i; hi = (u32*)g_seq_hi; lo = (u32*)g_seq_lo;
    } else if (i < SPLIT_SEQ + SPLIT_W) {
        in = Wh; off = i - SPLIT_SEQ; hi = (u32*)g_Wx_hi; lo = (u32*)g_Wx_lo;
    } else if (i < SPLIT_SEQ + 2*SPLIT_W) {
        in = Wt; off = i - SPLIT_SEQ - SPLIT_W;
        hi = (u32*)(g_Wx_hi + 2*D_*D_); lo = (u32*)(g_Wx_lo + 2*D_*D_);
    } else return;
    float v0 = in[2*off], v1 = in[2*off+1];
    u32 h = cvt_bf2(v0, v1);
    u32 r = cvt_bf2(v0 - bf_lo_f(h), v1 - bf_hi_f(h));
    hi[off] = h;
    lo[off] = r;
}

// ---------------- kernel A: entity embeds = logsumexp (bf16 split out) -----
__global__ void k_ent_emb(const float* __restrict__ seq,
                          const int* __restrict__ mpos) {
    int be = blockIdx.x;
    int b  = be / NE_;
    int base = be * M_;
    int p0 = mpos[base+0] + OFFSET_;
    int p1 = mpos[base+1] + OFFSET_;
    int p2 = mpos[base+2] + OFFSET_;
    int p3 = mpos[base+3] + OFFSET_;
    const float* s0 = seq + ((size_t)b*L_ + p0)*D_;
    const float* s1 = seq + ((size_t)b*L_ + p1)*D_;
    const float* s2 = seq + ((size_t)b*L_ + p2)*D_;
    const float* s3 = seq + ((size_t)b*L_ + p3)*D_;
    for (int d = threadIdx.x; d < D_; d += blockDim.x) {
        float x0 = s0[d], x1 = s1[d], x2 = s2[d], x3 = s3[d];
        float mx = fmaxf(fmaxf(x0,x1), fmaxf(x2,x3));
        float v = mx + logf(expf(x0-mx) + expf(x1-mx) + expf(x2-mx) + expf(x3-mx));
        __nv_bfloat16 hb = __float2bfloat16(v);
        g_ent_hi[(size_t)be*D_ + d] = hb;
        g_ent_lo[(size_t)be*D_ + d] = __float2bfloat16(v - __bfloat162float(hb));
    }
}

// ---------------- kernel B: entity attention = mean over mention rows ------
__global__ void k_ent_att(const float* __restrict__ att,
                          const int* __restrict__ mpos) {
    int id = blockIdx.x;
    int h  = id % H_;
    int be = id / H_;
    int b  = be / NE_;
    int base = be * M_;
    const float* a = att + (((size_t)b*H_ + h)*L_)*L_;
    const float* r0 = a + (size_t)(mpos[base+0]+OFFSET_)*L_;
    const float* r1 = a + (size_t)(mpos[base+1]+OFFSET_)*L_;
    const float* r2 = a + (size_t)(mpos[base+2]+OFFSET_)*L_;
    const float* r3 = a + (size_t)(mpos[base+3]+OFFSET_)*L_;
    float* out = g_ent_att + ((size_t)be*H_ + h)*L_;
    for (int l = threadIdx.x; l < L_; l += blockDim.x)
        out[l] = 0.25f * (r0[l] + r1[l] + r2[l] + r3[l]);
}

// ---------------- kernel C: per-pair channel attention -> bf16 split -------
__global__ void k_ht(const int* __restrict__ hts) {
    int bp = blockIdx.x;
    int b  = bp / P_;
    int hi = hts[bp*2 + 0];
    int ti = hts[bp*2 + 1];
    const float* ah = g_ent_att + (size_t)(b*NE_ + hi)*H_*L_;
    const float* at = g_ent_att + (size_t)(b*NE_ + ti)*H_*L_;
    const int T = 256;
    float v[4];
    float lsum = 0.f;
    #pragma unroll
    for (int it = 0; it < 4; it++) {
        int l = threadIdx.x + it*T;
        float acc = 0.f;
        #pragma unroll
        for (int h = 0; h < H_; h++)
            acc += ah[h*L_ + l] * at[h*L_ + l];
        acc *= (1.f/H_);
        v[it] = acc;
        lsum += acc;
    }
    __shared__ float red[32];
    #pragma unroll
    for (int o = 16; o; o >>= 1) lsum += __shfl_down_sync(~0u, lsum, o);
    if ((threadIdx.x & 31) == 0) red[threadIdx.x >> 5] = lsum;
    __syncthreads();
    if (threadIdx.x < 8) {
        float t = red[threadIdx.x];
        #pragma unroll
        for (int o = 4; o; o >>= 1) t += __shfl_down_sync(0xffu, t, o);
        if (threadIdx.x == 0) red[0] = 1.f / (t + 1e-5f);
    }
    __syncthreads();
    float inv = red[0];
    #pragma unroll
    for (int it = 0; it < 4; it++) {
        int l = threadIdx.x + it*T;
        float vv = v[it] * inv;
        __nv_bfloat16 hb = __float2bfloat16(vv);
        g_ht_hi[(size_t)bp*L_ + l] = hb;
        g_ht_lo[(size_t)bp*L_ + l] = __float2bfloat16(vv - __bfloat162float(hb));
    }
}

// ---------------- kernel P: gather entity halves into A_h / A_t ------------
__global__ void k_prepA(const int* __restrict__ hts) {
    int bp = blockIdx.x;
    int b  = bp / P_;
    int t  = threadIdx.x;            // 384
    int arr = t / 96, c = t % 96;
    int hidx = hts[bp*2], tidx = hts[bp*2+1];
    size_t ro = (size_t)bp*2*D_;
    const uint4* src; uint4* dst;
    if (arr == 0) { src = (const uint4*)(g_ent_hi + ((size_t)b*NE_+hidx)*D_); dst = (uint4*)(g_Ah_hi + ro); }
    else if (arr == 1) { src = (const uint4*)(g_ent_lo + ((size_t)b*NE_+hidx)*D_); dst = (uint4*)(g_Ah_lo + ro); }
    else if (arr == 2) { src = (const uint4*)(g_ent_hi + ((size_t)b*NE_+tidx)*D_); dst = (uint4*)(g_At_hi + ro); }
    else { src = (const uint4*)(g_ent_lo + ((size_t)b*NE_+tidx)*D_); dst = (uint4*)(g_At_lo + ro); }
    dst[c] = src[c];
}

// ---------------- generic mma GEMM core (128x128 tile, K-chunk 32) ---------
#define GA_PITCH 80                  // bytes per A smem row (40 bf16)
#define GB_PITCH 272                 // bytes per B smem row (136 bf16)
#define GSA_ 10240                   // 128*80
#define GSB_ 8704                    // 32*272
#define GSTAGE_ 37888                // 2*GSA_ + 2*GSB_
#define GSM_ 75776

__device__ __forceinline__ void g_load_stage(u32 sbase,
    const __nv_bfloat16* __restrict__ Ah, const __nv_bfloat16* __restrict__ Al,
    int lda,
    const __nv_bfloat16* __restrict__ Bh, const __nv_bfloat16* __restrict__ Bl,
    int r0, int n0, int kc, int tid)
{
    #pragma unroll
    for (int t = 0; t < 2; t++) {
        int idx = tid + t*256;             // 512 = 128 rows x 4 chunks
        int row = idx >> 2, c = idx & 3;
        size_t so = (size_t)(r0+row)*lda + kc + c*8;
        cpa16(sbase + row*GA_PITCH + c*16, Ah + so);
        cpa16(sbase + GSA_ + row*GA_PITCH + c*16, Al + so);
    }
    #pragma unroll
    for (int t = 0; t < 2; t++) {
        int idx = tid + t*256;             // 512 = 32 rows x 16 chunks
        int row = idx >> 4, c = idx & 15;
        size_t so = (size_t)(kc+row)*D_ + n0 + c*8;
        cpa16(sbase + 2*GSA_ + row*GB_PITCH + c*16, Bh + so);
        cpa16(sbase + 2*GSA_ + GSB_ + row*GB_PITCH + c*16, Bl + so);
    }
}

__device__ __forceinline__ void g_compute(u32 sbase, int w, int l,
                                          float (*acc)[4]) {
    int wm = w >> 1, wn = w & 1;
    u32 abase = sbase + (u32)((wm*32 + (l&15))*GA_PITCH + (l>>4)*16);
    u32 bbase = sbase + 2*GSA_ +
                (u32)((l&15)*GB_PITCH + (wn*64 + (l>>4)*8)*2);
    #pragma unroll
    for (int kk = 0; kk < 2; kk++) {
        u32 ah[2][4], al[2][4];
        #pragma unroll
        for (int mi = 0; mi < 2; mi++) {
            ldsm4(abase + mi*16*GA_PITCH + kk*32,
                  ah[mi][0], ah[mi][1], ah[mi][2], ah[mi][3]);
            ldsm4(abase + GSA_ + mi*16*GA_PITCH + kk*32,
                  al[mi][0], al[mi][1], al[mi][2], al[mi][3]);
        }
        u32 bb = bbase + kk*16*GB_PITCH;
        #pragma unroll
        for (int ntp = 0; ntp < 4; ntp++) {
            u32 b0,b1,b2,b3, c0,c1,c2,c3;
            ldsm4t(bb + ntp*32, b0,b1,b2,b3);
            ldsm4t(bb + GSB_ + ntp*32, c0,c1,c2,c3);
            #pragma unroll
            for (int mi = 0; mi < 2; mi++) {
                float* A0 = acc[mi*8 + 2*ntp];
                float* A1 = acc[mi*8 + 2*ntp + 1];
                mma16816(A0, ah[mi][0],ah[mi][1],ah[mi][2],ah[mi][3], b0,b1);
                mma16816(A1, ah[mi][0],ah[mi][1],ah[mi][2],ah[mi][3], b2,b3);
                mma16816(A0, ah[mi][0],ah[mi][1],ah[mi][2],ah[mi][3], c0,c1);
                mma16816(A1, ah[mi][0],ah[mi][1],ah[mi][2],ah[mi][3], c2,c3);
                mma16816(A0, al[mi][0],al[mi][1],al[mi][2],al[mi][3], b0,b1);
                mma16816(A1, al[mi][0],al[mi][1],al[mi][2],al[mi][3], b2,b3);
            }
        }
    }
}

// ---------------- kernel D: rs GEMM -> split bf16 into A halves ------------
__global__ void __launch_bounds__(256, 1) k_rs_mma() {
    extern __shared__ char smem[];
    u32 sb = smem_u32(smem);
    int tid = threadIdx.x, w = tid >> 5, l = tid & 31;
    int r0 = blockIdx.x * 128, n0 = blockIdx.y * 128;
    int b = r0 / P_;
    const __nv_bfloat16* Ah = g_ht_hi;
    const __nv_bfloat16* Al = g_ht_lo;
    const __nv_bfloat16* Bh = g_seq_hi + (size_t)b*L_*D_;
    const __nv_bfloat16* Bl = g_seq_lo + (size_t)b*L_*D_;
    float acc[16][4];
    #pragma unroll
    for (int f = 0; f < 16; f++)
        #pragma unroll
        for (int e = 0; e < 4; e++) acc[f][e] = 0.f;
    const int NK = L_/32;           // 32
    g_load_stage(sb, Ah, Al, L_, Bh, Bl, r0, n0, 0, tid);  cpa_commit();
    g_load_stage(sb+GSTAGE_, Ah, Al, L_, Bh, Bl, r0, n0, 32, tid); cpa_commit();
    for (int i = 0; i < NK; i++) {
        cpa_wait1(); __syncthreads();
        g_compute(sb + (i&1)*GSTAGE_, w, l, acc);
        __syncthreads();
        if (i + 2 < NK)
            g_load_stage(sb + (i&1)*GSTAGE_, Ah, Al, L_, Bh, Bl, r0, n0, (i+2)*32, tid);
        cpa_commit();
    }
    int wm = w >> 1, wn = w & 1, g = l >> 2, tg = l & 3;
    #pragma unroll
    for (int mi = 0; mi < 2; mi++) {
        int row = r0 + wm*32 + mi*16 + g;
        #pragma unroll
        for (int f = 0; f < 8; f++) {
            int col = n0 + wn*64 + f*8 + tg*2;
            float* a4 = acc[mi*8 + f];
            #pragma unroll
            for (int rh = 0; rh < 2; rh++) {
                float v0 = a4[rh*2], v1 = a4[rh*2+1];
                u32 hp = cvt_bf2(v0, v1);
                u32 lp = cvt_bf2(v0 - bf_lo_f(hp), v1 - bf_hi_f(hp));
                size_t o = (size_t)(row + rh*8)*(2*D_) + D_ + col;
                *(u32*)(g_Ah_hi + o) = hp;
                *(u32*)(g_At_hi + o) = hp;
                *(u32*)(g_Ah_lo + o) = lp;
                *(u32*)(g_At_lo + o) = lp;
            }
        }
    }
}

// ---------------- kernel E: extractors via mma, K-split, fp32 partials -----
__global__ void __launch_bounds__(256, 1) k_extract_mma() {
    extern __shared__ char smem[];
    u32 sb = smem_u32(smem);
    int tid = threadIdx.x, w = tid >> 5, l = tid & 31;
    int sel = blockIdx.z >> 1, khalf = blockIdx.z & 1;
    int r0 = blockIdx.x * 128, n0 = blockIdx.y * 128;
    const __nv_bfloat16* Ah = sel ? g_At_hi : g_Ah_hi;
    const __nv_bfloat16* Al = sel ? g_At_lo : g_Ah_lo;
    const __nv_bfloat16* Bh = g_Wx_hi + (size_t)sel*2*D_*D_;
    const __nv_bfloat16* Bl = g_Wx_lo + (size_t)sel*2*D_*D_;
    float* out = g_ep + (size_t)(sel*2 + khalf)*BP_*D_;
    float acc[16][4];
    #pragma unroll
    for (int f = 0; f < 16; f++)
        #pragma unroll
        for (int e = 0; e < 4; e++) acc[f][e] = 0.f;
    const int NK = D_/32;           // 24 per K-half
    int kb = khalf * D_;
    g_load_stage(sb, Ah, Al, 2*D_, Bh, Bl, r0, n0, kb, tid);  cpa_commit();
    g_load_stage(sb+GSTAGE_, Ah, Al, 2*D_, Bh, Bl, r0, n0, kb+32, tid); cpa_commit();
    for (int i = 0; i < NK; i++) {
        cpa_wait1(); __syncthreads();
        g_compute(sb + (i&1)*GSTAGE_, w, l, acc);
        __syncthreads();
        if (i + 2 < NK)
            g_load_stage(sb + (i&1)*GSTAGE_, Ah, Al, 2*D_, Bh, Bl, r0, n0, kb+(i+2)*32, tid);
        cpa_commit();
    }
    int wm = w >> 1, wn = w & 1, g = l >> 2, tg = l & 3;
    #pragma unroll
    for (int mi = 0; mi < 2; mi++) {
        int row = r0 + wm*32 + mi*16 + g;
        #pragma unroll
        for (int f = 0; f < 8; f++) {
            int col = n0 + wn*64 + f*8 + tg*2;
            float* a4 = acc[mi*8 + f];
            out[(size_t)row*D_ + col]       = a4[0];
            out[(size_t)row*D_ + col+1]     = a4[1];
            out[(size_t)(row+8)*D_ + col]   = a4[2];
            out[(size_t)(row+8)*D_ + col+1] = a4[3];
        }
    }
}

// ---------------- kernel T: combine K-split partials, bias + tanh ----------
__global__ void k_tanh(const float* __restrict__ bh, const float* __restrict__ bt) {
    int i4 = blockIdx.x*blockDim.x + threadIdx.x;
    const int tot = BP_*D_/4;
    if (i4 >= 2*tot) return;
    int sel = (i4 >= tot) ? 1 : 0;
    int j4 = i4 - sel*tot;
    const float* bias = sel ? bt : bh;
    float* out = sel ? g_zo : g_zs;
    const float4 a = ((const float4*)(g_ep + (size_t)(sel*2)*BP_*D_))[j4];
    const float4 b = ((const float4*)(g_ep + (size_t)(sel*2+1)*BP_*D_))[j4];
    int col = (j4*4) % D_;
    float4 bb = *(const float4*)(bias + col);
    float4 o;
    o.x = tanhf(a.x + b.x + bb.x);
    o.y = tanhf(a.y + b.y + bb.y);
    o.z = tanhf(a.z + b.z + bb.z);
    o.w = tanhf(a.w + b.w + bb.w);
    ((float4*)out)[j4] = o;
}

// ---------------- kernel Wpad: split W_bi into bf16 hi/lo (vectorized) -----
__global__ void k_padW_tc(const float* __restrict__ Wbi) {
    int ki = blockIdx.x;               // 0..767 (= k*64 + i)
    u32* d0 = (u32*)(g_Wb0 + (size_t)ki*WTILE_);
    u32* d1 = (u32*)(g_Wb1 + (size_t)ki*WTILE_);
    const float* src = Wbi + (size_t)ki*BLK_*NL_;
    for (int c = threadIdx.x; c < WTILE_/8; c += blockDim.x) {  // 1088
        int j = c / 17, c8 = (c % 17)*8;
        u32 h[4], lo[4];
        #pragma unroll
        for (int e = 0; e < 4; e++) {
            int n0 = c8 + 2*e, n1 = n0 + 1;
            float v0 = (n0 < NL_) ? src[j*NL_ + n0] : 0.f;
            float v1 = (n1 < NL_) ? src[j*NL_ + n1] : 0.f;
            h[e]  = cvt_bf2(v0, v1);
            lo[e] = cvt_bf2(v0 - bf_lo_f(h[e]), v1 - bf_hi_f(h[e]));
        }
        int base = (j*WPITCH_ + c8) >> 1;  // u32 index, 16B aligned
        *(uint4*)(d0 + base) = make_uint4(h[0], h[1], h[2], h[3]);
        *(uint4*)(d1 + base) = make_uint4(lo[0], lo[1], lo[2], lo[3]);
    }
}

// ---------------- kernel F: bilinear classifier via mma.sync bf16 ----------
#define SM_ZS 0                         // [128][65] f32
#define SM_ZO 33280                     // [128][66] f32
#define SM_W  67072
#define WSTAGE_ 34816
#define SMEMB_ (SM_W + 2*WSTAGE_)       // 136704

__global__ void __launch_bounds__(256, 1) k_bilinear_mma() {
    extern __shared__ char smem[];
    float* zs_s = (float*)(smem + SM_ZS);   // pitch 65
    float* zo_s = (float*)(smem + SM_ZO);   // pitch 66
    u32 sw = smem_u32(smem) + SM_W;
    int tid = threadIdx.x, w = tid >> 5, l = tid & 31;
    int g = l >> 2, tg = l & 3;
    int k  = blockIdx.y;
    int r0 = blockIdx.x * 128;
    int iseg = blockIdx.z;
    int i0 = iseg*21, i1 = (iseg == ISEG_-1) ? BLK_ : (i0 + 21);

    #pragma unroll
    for (int p = 0; p < 2; p++) {
        int ii = i0 + p;
        const char* src0 = (const char*)(g_Wb0 + (size_t)(k*BLK_ + ii)*WTILE_);
        const char* src1 = (const char*)(g_Wb1 + (size_t)(k*BLK_ + ii)*WTILE_);
        u32 dst = sw + (ii & 1)*WSTAGE_;
        #pragma unroll
        for (int t = 0; t < 5; t++) {
            int idx = tid + t*256;
            if (idx < 1088) {
                cpa16(dst + idx*16, src0 + idx*16);
                cpa16(dst + 17408 + idx*16, src1 + idx*16);
            }
        }
        cpa_commit();
    }

    for (int idx = tid; idx < 128*64; idx += 256) {
        int r = idx >> 6, c = idx & 63;
        zs_s[r*65 + c] = g_zs[(size_t)(r0+r)*D_ + k*BLK_ + c];
        zo_s[r*66 + c] = g_zo[(size_t)(r0+r)*D_ + k*BLK_ + c];
    }
    __syncthreads();

    int rg = w*16 + g;
    float2 zoA[4][2], zoB[4][2];
    #pragma unroll
    for (int jc = 0; jc < 4; jc++) {
        zoA[jc][0] = *(float2*)&zo_s[rg*66     + jc*16 + tg*2];
        zoA[jc][1] = *(float2*)&zo_s[rg*66     + jc*16 + tg*2 + 8];
        zoB[jc][0] = *(float2*)&zo_s[(rg+8)*66 + jc*16 + tg*2];
        zoB[jc][1] = *(float2*)&zo_s[(rg+8)*66 + jc*16 + tg*2 + 8];
    }

    float acc[14][4];
    #pragma unroll
    for (int t = 0; t < 14; t++)
        #pragma unroll
        for (int e = 0; e < 4; e++) acc[t][e] = 0.f;

    u32 laneoff = (u32)((l & 15)*272 + (l >> 4)*16);

    for (int i = i0; i < i1; i++) {
        int s = i & 1;
        cpa_wait1();
        __syncthreads();
        float zs0 = zs_s[rg*65 + i];
        float zs1 = zs_s[(rg+8)*65 + i];
        u32 sbase = sw + s*WSTAGE_;
        #pragma unroll
        for (int jc = 0; jc < 4; jc++) {
            float p0x = zs0*zoA[jc][0].x, p0y = zs0*zoA[jc][0].y;
            float p1x = zs1*zoB[jc][0].x, p1y = zs1*zoB[jc][0].y;
            float p2x = zs0*zoA[jc][1].x, p2y = zs0*zoA[jc][1].y;
            float p3x = zs1*zoB[jc][1].x, p3y = zs1*zoB[jc][1].y;
            u32 a0h = cvt_bf2(p0x, p0y);
            u32 a1h = cvt_bf2(p1x, p1y);
            u32 a2h = cvt_bf2(p2x, p2y);
            u32 a3h = cvt_bf2(p3x, p3y);
            u32 a0r = cvt_bf2(p0x - bf_lo_f(a0h), p0y - bf_hi_f(a0h));
            u32 a1r = cvt_bf2(p1x - bf_lo_f(a1h), p1y - bf_hi_f(a1h));
            u32 a2r = cvt_bf2(p2x - bf_lo_f(a2h), p2y - bf_hi_f(a2h));
            u32 a3r = cvt_bf2(p3x - bf_lo_f(a3h), p3y - bf_hi_f(a3h));
            u32 rowb = sbase + (u32)(jc*16*272) + laneoff;
            #pragma unroll
            for (int ntp = 0; ntp < 7; ntp++) {
                u32 b0, b1, b2, b3;
                ldsm4t(rowb + ntp*32, b0, b1, b2, b3);
                mma16816(acc[2*ntp],   a0h,a1h,a2h,a3h, b0, b1);
                mma16816(acc[2*ntp+1], a0h,a1h,a2h,a3h, b2, b3);
                mma16816(acc[2*ntp],   a0r,a1r,a2r,a3r, b0, b1);
                mma16816(acc[2*ntp+1], a0r,a1r,a2r,a3r, b2, b3);
                u32 c0, c1, c2, c3;
                ldsm4t(rowb + 17408 + ntp*32, c0, c1, c2, c3);
                mma16816(acc[2*ntp],   a0h,a1h,a2h,a3h, c0, c1);
                mma16816(acc[2*ntp+1], a0h,a1h,a2h,a3h, c2, c3);
            }
        }
        __syncthreads();
        if (i + 2 < i1) {
            const char* src0 = (const char*)(g_Wb0 + (size_t)(k*BLK_ + i + 2)*WTILE_);
            const char* src1 = (const char*)(g_Wb1 + (size_t)(k*BLK_ + i + 2)*WTILE_);
            u32 dst = sw + s*WSTAGE_;
            #pragma unroll
            for (int t = 0; t < 5; t++) {
                int idx = tid + t*256;
                if (idx < 1088) {
                    cpa16(dst + idx*16, src0 + idx*16);
                    cpa16(dst + 17408 + idx*16, src1 + idx*16);
                }
            }
        }
        cpa_commit();
    }

    int slab = iseg*KCH_ + k;
    float* base0 = g_part + ((size_t)slab*BP_ + r0 + rg)*NL_;
    float* base1 = g_part + ((size_t)slab*BP_ + r0 + rg + 8)*NL_;
    #pragma unroll
    for (int nt = 0; nt < 13; nt++) {
        int n0 = nt*8 + tg*2;
        if (n0 < NL_) { base0[n0] = acc[nt][0]; base1[n0] = acc[nt][2]; }
        if (n0 + 1 < NL_) { base0[n0+1] = acc[nt][1]; base1[n0+1] = acc[nt][3]; }
    }
}

// ---------------- kernel G: reduce split-K partials + bias -----------------
__global__ void k_reduce(const float* __restrict__ bbi, float* __restrict__ out) {
    int idx = blockIdx.x*256 + threadIdx.x;
    if (idx >= BP_*NL_) return;
    int n = idx % NL_;
    float s = bbi[n];
    #pragma unroll
    for (int k = 0; k < KSLAB_; k++)
        s += g_part[(size_t)k*BP_*NL_ + idx];
    out[idx] = s;
}

// ---------------- launch ---------------------------------------------------
extern "C" void kernel_launch(void* const* d_in, const int* in_sizes, int n_in,
                              void* d_out, int out_size) {
    const float* seq  = (const float*)d_in[0];
    const float* att  = (const float*)d_in[1];
    const int*   mpos = (const int*)d_in[2];
    const int*   hts  = (const int*)d_in[3];
    const float* Wh   = (const float*)d_in[4];
    const float* bh   = (const float*)d_in[5];
    const float* Wt   = (const float*)d_in[6];
    const float* bt   = (const float*)d_in[7];
    const float* Wbi  = (const float*)d_in[8];
    const float* bbi  = (const float*)d_in[9];
    float* out = (float*)d_out;

    static bool attr_set = false;
    if (!attr_set) {
        cudaFuncSetAttribute(k_bilinear_mma,
            cudaFuncAttributeMaxDynamicSharedMemorySize, SMEMB_);
        cudaFuncSetAttribute(k_rs_mma,
            cudaFuncAttributeMaxDynamicSharedMemorySize, GSM_);
        cudaFuncSetAttribute(k_extract_mma,
            cudaFuncAttributeMaxDynamicSharedMemorySize, GSM_);
        attr_set = true;
    }

    k_split_all<<<(SPLIT_SEQ + 2*SPLIT_W + 255)/256, 256>>>(seq, Wh, Wt);
    k_padW_tc<<<KCH_*BLK_, 256>>>(Wbi);
    k_ent_emb<<<B_*NE_, 256>>>(seq, mpos);
    k_ent_att<<<B_*NE_*H_, 256>>>(att, mpos);
    k_ht<<<B_*P_, 256>>>(hts);
    k_prepA<<<BP_, 384>>>(hts);
    k_rs_mma<<<dim3(BP_/128, D_/128), 256, GSM_>>>();
    k_extract_mma<<<dim3(BP_/128, D_/128, 4), 256, GSM_>>>();
    k_tanh<<<(2*BP_*D_/4 + 255)/256, 256>>>(bh, bt);
    k_bilinear_mma<<<dim3(BP_/128, KCH_, ISEG_), 256, SMEMB_>>>();
    k_reduce<<<(BP_*NL_ + 255)/256, 256>>>(bbi, out);
}

// round 8
// speedup vs baseline: 3.5478x; 1.0449x over previous
#include <cuda_runtime.h>
#include <cuda_bf16.h>
#include <math.h>
#include <stdint.h>

#define B_ 4
#define L_ 1024
#define D_ 768
#define H_ 12
#define NE_ 42
#define M_ 4
#define P_ 512
#define BLK_ 64
#define NL_ 97
#define OFFSET_ 1
#define BP_ (B_*P_)          // 2048
#define KCH_ (D_/BLK_)       // 12 channel blocks
#define ISEG_ 3              // bilinear i-range split
#define KSLAB_ (ISEG_*KCH_)  // 36 partial slabs
#define NW_ 1536             // concat output width for extractors
#define WPITCH_ 136          // padded n (bf16), 272B rows -> conflict-free ldmatrix
#define WTILE_ (BLK_*WPITCH_) // per (k,i) split tile for bilinear W

typedef unsigned long long u64;
typedef unsigned int u32;

// ---------------- helpers ---------------------------------------------------
__device__ __forceinline__ u32 smem_u32(const void* p) {
    u32 a; asm("{ .reg .u64 t; cvta.to.shared.u64 t, %1; cvt.u32.u64 %0, t; }"
               : "=r"(a) : "l"(p));
    return a;
}
// pack two f32 -> bf16x2 (first arg -> LOWER half)
__device__ __forceinline__ u32 cvt_bf2(float lo, float hi) {
    u32 d; asm("cvt.rn.bf16x2.f32 %0, %1, %2;" : "=r"(d) : "f"(hi), "f"(lo));
    return d;
}
__device__ __forceinline__ float bf_lo_f(u32 c) { return __uint_as_float(c << 16); }
__device__ __forceinline__ float bf_hi_f(u32 c) { return __uint_as_float(c & 0xFFFF0000u); }

__device__ __forceinline__ void cpa16(u32 dst, const void* src) {
    asm volatile("cp.async.cg.shared.global [%0], [%1], 16;"
                 :: "r"(dst), "l"(src) : "memory");
}
__device__ __forceinline__ void cpa_commit() {
    asm volatile("cp.async.commit_group;" ::: "memory");
}
__device__ __forceinline__ void cpa_wait1() {
    asm volatile("cp.async.wait_group 1;" ::: "memory");
}
__device__ __forceinline__ void ldsm4(u32 addr, u32& r0, u32& r1, u32& r2, u32& r3) {
    asm volatile("ldmatrix.sync.aligned.m8n8.x4.shared.b16 {%0,%1,%2,%3}, [%4];"
                 : "=r"(r0), "=r"(r1), "=r"(r2), "=r"(r3) : "r"(addr));
}
__device__ __forceinline__ void ldsm4t(u32 addr, u32& r0, u32& r1, u32& r2, u32& r3) {
    asm volatile("ldmatrix.sync.aligned.m8n8.x4.trans.shared.b16 {%0,%1,%2,%3}, [%4];"
                 : "=r"(r0), "=r"(r1), "=r"(r2), "=r"(r3) : "r"(addr));
}
__device__ __forceinline__ void mma16816(float* d,
                                         u32 a0, u32 a1, u32 a2, u32 a3,
                                         u32 b0, u32 b1) {
    asm volatile(
        "mma.sync.aligned.m16n8k16.row.col.f32.bf16.bf16.f32 "
        "{%0,%1,%2,%3}, {%4,%5,%6,%7}, {%8,%9}, {%0,%1,%2,%3};"
        : "+f"(d[0]), "+f"(d[1]), "+f"(d[2]), "+f"(d[3])
        : "r"(a0), "r"(a1), "r"(a2), "r"(a3), "r"(b0), "r"(b1));
}

// ---------------- scratch (device globals; no runtime allocation) ----------
__device__ float g_ent_att[B_*NE_*H_*L_];
__device__ __nv_bfloat16 g_entA_hi[256*D_], g_entA_lo[256*D_];  // 168 used
__device__ __nv_bfloat16 g_seq_hi[B_*L_*D_],  g_seq_lo[B_*L_*D_];
__device__ __nv_bfloat16 g_ht_hi[B_*P_*L_],   g_ht_lo[B_*P_*L_];
__device__ __nv_bfloat16 g_rs_hi[BP_*D_], g_rs_lo[BP_*D_];
__device__ __nv_bfloat16 g_W1c_hi[D_*NW_], g_W1c_lo[D_*NW_];  // [k][Wh|Wt] rows 0..767
__device__ __nv_bfloat16 g_W2c_hi[D_*NW_], g_W2c_lo[D_*NW_];  // rows 768..1535
__device__ float g_E0[256*NW_];                  // entity-side extract
__device__ float g_ep[2*BP_*NW_];                // E1 K-split partials
__device__ float g_zs[BP_*D_], g_zo[BP_*D_];
__device__ float g_part[KSLAB_*BP_*NL_];         // bilinear partials
__device__ __nv_bfloat16 g_Wb0[KCH_*BLK_*WTILE_], g_Wb1[KCH_*BLK_*WTILE_];

// ---------------- kernel S: fp32 -> bf16 hi/lo split + W concat ------------
#define SPLIT_SEQ (B_*L_*D_/2)
#define SPLIT_W   (D_*D_)            // pairs per extractor weight (2D*D/2)
__global__ void k_split_all(const float* __restrict__ seq,
                            const float* __restrict__ Wh,
                            const float* __restrict__ Wt) {
    int i = blockIdx.x*blockDim.x + threadIdx.x;
    if (i < SPLIT_SEQ) {
        float v0 = seq[2*i], v1 = seq[2*i+1];
        u32 h = cvt_bf2(v0, v1);
        ((u32*)g_seq_hi)[i] = h;
        ((u32*)g_seq_lo)[i] = cvt_bf2(v0 - bf_lo_f(h), v1 - bf_hi_f(h));
        return;
    }
    int j = i - SPLIT_SEQ;
    if (j >= 2*SPLIT_W) return;
    int sel = (j >= SPLIT_W) ? 1 : 0;
    int off = j - sel*SPLIT_W;
    const float* W = sel ? Wt : Wh;
    int kg = (2*off) / D_;           // 0..1535
    int d  = (2*off) % D_;           // even
    float v0 = W[2*off], v1 = W[2*off+1];
    u32 h = cvt_bf2(v0, v1);
    u32 r = cvt_bf2(v0 - bf_lo_f(h), v1 - bf_hi_f(h));
    u32 *hi, *lo;
    int rowk;
    if (kg < D_) { hi = (u32*)g_W1c_hi; lo = (u32*)g_W1c_lo; rowk = kg; }
    else         { hi = (u32*)g_W2c_hi; lo = (u32*)g_W2c_lo; rowk = kg - D_; }
    int idx = rowk*(NW_/2) + sel*(D_/2) + d/2;
    hi[idx] = h;
    lo[idx] = r;
}

// ---------------- kernel A: entity embeds = logsumexp (bf16 split out) -----
__global__ void k_ent_emb(const float* __restrict__ seq,
                          const int* __restrict__ mpos) {
    int be = blockIdx.x;
    int b  = be / NE_;
    int base = be * M_;
    int p0 = mpos[base+0] + OFFSET_;
    int p1 = mpos[base+1] + OFFSET_;
    int p2 = mpos[base+2] + OFFSET_;
    int p3 = mpos[base+3] + OFFSET_;
    const float* s0 = seq + ((size_t)b*L_ + p0)*D_;
    const float* s1 = seq + ((size_t)b*L_ + p1)*D_;
    const float* s2 = seq + ((size_t)b*L_ + p2)*D_;
    const float* s3 = seq + ((size_t)b*L_ + p3)*D_;
    for (int d = threadIdx.x; d < D_; d += blockDim.x) {
        float x0 = s0[d], x1 = s1[d], x2 = s2[d], x3 = s3[d];
        float mx = fmaxf(fmaxf(x0,x1), fmaxf(x2,x3));
        float v = mx + logf(expf(x0-mx) + expf(x1-mx) + expf(x2-mx) + expf(x3-mx));
        __nv_bfloat16 hb = __float2bfloat16(v);
        g_entA_hi[(size_t)be*D_ + d] = hb;
        g_entA_lo[(size_t)be*D_ + d] = __float2bfloat16(v - __bfloat162float(hb));
    }
}

// ---------------- kernel B: entity attention = mean over mention rows ------
__global__ void k_ent_att(const float* __restrict__ att,
                          const int* __restrict__ mpos) {
    int id = blockIdx.x;
    int h  = id % H_;
    int be = id / H_;
    int b  = be / NE_;
    int base = be * M_;
    const float* a = att + (((size_t)b*H_ + h)*L_)*L_;
    const float* r0 = a + (size_t)(mpos[base+0]+OFFSET_)*L_;
    const float* r1 = a + (size_t)(mpos[base+1]+OFFSET_)*L_;
    const float* r2 = a + (size_t)(mpos[base+2]+OFFSET_)*L_;
    const float* r3 = a + (size_t)(mpos[base+3]+OFFSET_)*L_;
    float* out = g_ent_att + ((size_t)be*H_ + h)*L_;
    for (int l = threadIdx.x; l < L_; l += blockDim.x)
        out[l] = 0.25f * (r0[l] + r1[l] + r2[l] + r3[l]);
}

// ---------------- kernel C: per-pair channel attention -> bf16 split -------
__global__ void k_ht(const int* __restrict__ hts) {
    int bp = blockIdx.x;
    int b  = bp / P_;
    int hi = hts[bp*2 + 0];
    int ti = hts[bp*2 + 1];
    const float* ah = g_ent_att + (size_t)(b*NE_ + hi)*H_*L_;
    const float* at = g_ent_att + (size_t)(b*NE_ + ti)*H_*L_;
    const int T = 256;
    float v[4];
    float lsum = 0.f;
    #pragma unroll
    for (int it = 0; it < 4; it++) {
        int l = threadIdx.x + it*T;
        float acc = 0.f;
        #pragma unroll
        for (int h = 0; h < H_; h++)
            acc += ah[h*L_ + l] * at[h*L_ + l];
        acc *= (1.f/H_);
        v[it] = acc;
        lsum += acc;
    }
    __shared__ float red[32];
    #pragma unroll
    for (int o = 16; o; o >>= 1) lsum += __shfl_down_sync(~0u, lsum, o);
    if ((threadIdx.x & 31) == 0) red[threadIdx.x >> 5] = lsum;
    __syncthreads();
    if (threadIdx.x < 8) {
        float t = red[threadIdx.x];
        #pragma unroll
        for (int o = 4; o; o >>= 1) t += __shfl_down_sync(0xffu, t, o);
        if (threadIdx.x == 0) red[0] = 1.f / (t + 1e-5f);
    }
    __syncthreads();
    float inv = red[0];
    #pragma unroll
    for (int it = 0; it < 4; it++) {
        int l = threadIdx.x + it*T;
        float vv = v[it] * inv;
        __nv_bfloat16 hb = __float2bfloat16(vv);
        g_ht_hi[(size_t)bp*L_ + l] = hb;
        g_ht_lo[(size_t)bp*L_ + l] = __float2bfloat16(vv - __bfloat162float(hb));
    }
}

// ---------------- generic mma GEMM core (128x128 tile, K-chunk 32) ---------
#define GA_PITCH 80                  // bytes per A smem row (40 bf16)
#define GB_PITCH 272                 // bytes per B smem row (136 bf16)
#define GSA_ 10240                   // 128*80
#define GSB_ 8704                    // 32*272
#define GSTAGE_ 37888                // 2*GSA_ + 2*GSB_
#define GSM_ 75776

__device__ __forceinline__ void g_load_stage(u32 sbase,
    const __nv_bfloat16* __restrict__ Ah, const __nv_bfloat16* __restrict__ Al,
    int lda,
    const __nv_bfloat16* __restrict__ Bh, const __nv_bfloat16* __restrict__ Bl,
    int ldb,
    int r0, int n0, int kc, int tid)
{
    #pragma unroll
    for (int t = 0; t < 2; t++) {
        int idx = tid + t*256;             // 512 = 128 rows x 4 chunks
        int row = idx >> 2, c = idx & 3;
        size_t so = (size_t)(r0+row)*lda + kc + c*8;
        cpa16(sbase + row*GA_PITCH + c*16, Ah + so);
        cpa16(sbase + GSA_ + row*GA_PITCH + c*16, Al + so);
    }
    #pragma unroll
    for (int t = 0; t < 2; t++) {
        int idx = tid + t*256;             // 512 = 32 rows x 16 chunks
        int row = idx >> 4, c = idx & 15;
        size_t so = (size_t)(kc+row)*ldb + n0 + c*8;
        cpa16(sbase + 2*GSA_ + row*GB_PITCH + c*16, Bh + so);
        cpa16(sbase + 2*GSA_ + GSB_ + row*GB_PITCH + c*16, Bl + so);
    }
}

__device__ __forceinline__ void g_compute(u32 sbase, int w, int l,
                                          float (*acc)[4]) {
    int wm = w >> 1, wn = w & 1;
    u32 abase = sbase + (u32)((wm*32 + (l&15))*GA_PITCH + (l>>4)*16);
    u32 bbase = sbase + 2*GSA_ +
                (u32)((l&15)*GB_PITCH + (wn*64 + (l>>4)*8)*2);
    #pragma unroll
    for (int kk = 0; kk < 2; kk++) {
        u32 ah[2][4], al[2][4];
        #pragma unroll
        for (int mi = 0; mi < 2; mi++) {
            ldsm4(abase + mi*16*GA_PITCH + kk*32,
                  ah[mi][0], ah[mi][1], ah[mi][2], ah[mi][3]);
            ldsm4(abase + GSA_ + mi*16*GA_PITCH + kk*32,
                  al[mi][0], al[mi][1], al[mi][2], al[mi][3]);
        }
        u32 bb = bbase + kk*16*GB_PITCH;
        #pragma unroll
        for (int ntp = 0; ntp < 4; ntp++) {
            u32 b0,b1,b2,b3, c0,c1,c2,c3;
            ldsm4t(bb + ntp*32, b0,b1,b2,b3);
            ldsm4t(bb + GSB_ + ntp*32, c0,c1,c2,c3);
            #pragma unroll
            for (int mi = 0; mi < 2; mi++) {
                float* A0 = acc[mi*8 + 2*ntp];
                float* A1 = acc[mi*8 + 2*ntp + 1];
                mma16816(A0, ah[mi][0],ah[mi][1],ah[mi][2],ah[mi][3], b0,b1);
                mma16816(A1, ah[mi][0],ah[mi][1],ah[mi][2],ah[mi][3], b2,b3);
                mma16816(A0, ah[mi][0],ah[mi][1],ah[mi][2],ah[mi][3], c0,c1);
                mma16816(A1, ah[mi][0],ah[mi][1],ah[mi][2],ah[mi][3], c2,c3);
                mma16816(A0, al[mi][0],al[mi][1],al[mi][2],al[mi][3], b0,b1);
                mma16816(A1, al[mi][0],al[mi][1],al[mi][2],al[mi][3], b2,b3);
            }
        }
    }
}

// ---------------- kernel D: rs GEMM -> split bf16 rs arrays ----------------
__global__ void __launch_bounds__(256, 1) k_rs_mma() {
    extern __shared__ char smem[];
    u32 sb = smem_u32(smem);
    int tid = threadIdx.x, w = tid >> 5, l = tid & 31;
    int r0 = blockIdx.x * 128, n0 = blockIdx.y * 128;
    int b = r0 / P_;
    const __nv_bfloat16* Ah = g_ht_hi;
    const __nv_bfloat16* Al = g_ht_lo;
    const __nv_bfloat16* Bh = g_seq_hi + (size_t)b*L_*D_;
    const __nv_bfloat16* Bl = g_seq_lo + (size_t)b*L_*D_;
    float acc[16][4];
    #pragma unroll
    for (int f = 0; f < 16; f++)
        #pragma unroll
        for (int e = 0; e < 4; e++) acc[f][e] = 0.f;
    const int NK = L_/32;           // 32
    g_load_stage(sb, Ah, Al, L_, Bh, Bl, D_, r0, n0, 0, tid);  cpa_commit();
    g_load_stage(sb+GSTAGE_, Ah, Al, L_, Bh, Bl, D_, r0, n0, 32, tid); cpa_commit();
    for (int i = 0; i < NK; i++) {
        cpa_wait1(); __syncthreads();
        g_compute(sb + (i&1)*GSTAGE_, w, l, acc);
        __syncthreads();
        if (i + 2 < NK)
            g_load_stage(sb + (i&1)*GSTAGE_, Ah, Al, L_, Bh, Bl, D_, r0, n0, (i+2)*32, tid);
        cpa_commit();
    }
    int wm = w >> 1, wn = w & 1, g = l >> 2, tg = l & 3;
    #pragma unroll
    for (int mi = 0; mi < 2; mi++) {
        int row = r0 + wm*32 + mi*16 + g;
        #pragma unroll
        for (int f = 0; f < 8; f++) {
            int col = n0 + wn*64 + f*8 + tg*2;
            float* a4 = acc[mi*8 + f];
            #pragma unroll
            for (int rh = 0; rh < 2; rh++) {
                float v0 = a4[rh*2], v1 = a4[rh*2+1];
                u32 hp = cvt_bf2(v0, v1);
                u32 lp = cvt_bf2(v0 - bf_lo_f(hp), v1 - bf_hi_f(hp));
                size_t o = (size_t)(row + rh*8)*D_ + col;
                *(u32*)(g_rs_hi + o) = hp;
                *(u32*)(g_rs_lo + o) = lp;
            }
        }
    }
}

// ---------------- kernel E0: entity-side extract  [256,768]@[768,1536] -----
__global__ void __launch_bounds__(256, 1) k_E0() {
    extern __shared__ char smem[];
    u32 sb = smem_u32(smem);
    int tid = threadIdx.x, w = tid >> 5, l = tid & 31;
    int r0 = blockIdx.x * 128, n0 = blockIdx.y * 128;
    float acc[16][4];
    #pragma unroll
    for (int f = 0; f < 16; f++)
        #pragma unroll
        for (int e = 0; e < 4; e++) acc[f][e] = 0.f;
    const int NK = D_/32;           // 24
    g_load_stage(sb, g_entA_hi, g_entA_lo, D_, g_W1c_hi, g_W1c_lo, NW_, r0, n0, 0, tid);  cpa_commit();
    g_load_stage(sb+GSTAGE_, g_entA_hi, g_entA_lo, D_, g_W1c_hi, g_W1c_lo, NW_, r0, n0, 32, tid); cpa_commit();
    for (int i = 0; i < NK; i++) {
        cpa_wait1(); __syncthreads();
        g_compute(sb + (i&1)*GSTAGE_, w, l, acc);
        __syncthreads();
        if (i + 2 < NK)
            g_load_stage(sb + (i&1)*GSTAGE_, g_entA_hi, g_entA_lo, D_, g_W1c_hi, g_W1c_lo, NW_, r0, n0, (i+2)*32, tid);
        cpa_commit();
    }
    int wm = w >> 1, wn = w & 1, g = l >> 2, tg = l & 3;
    #pragma unroll
    for (int mi = 0; mi < 2; mi++) {
        int row = r0 + wm*32 + mi*16 + g;
        #pragma unroll
        for (int f = 0; f < 8; f++) {
            int col = n0 + wn*64 + f*8 + tg*2;
            float* a4 = acc[mi*8 + f];
            g_E0[(size_t)row*NW_ + col]       = a4[0];
            g_E0[(size_t)row*NW_ + col+1]     = a4[1];
            g_E0[(size_t)(row+8)*NW_ + col]   = a4[2];
            g_E0[(size_t)(row+8)*NW_ + col+1] = a4[3];
        }
    }
}

// ---------------- kernel E1: rs@[W2h|W2t], K-split x2 ----------------------
__global__ void __launch_bounds__(256, 1) k_E1() {
    extern __shared__ char smem[];
    u32 sb = smem_u32(smem);
    int tid = threadIdx.x, w = tid >> 5, l = tid & 31;
    int khalf = blockIdx.z;
    int r0 = blockIdx.x * 128, n0 = blockIdx.y * 128;
    float* out = g_ep + (size_t)khalf*BP_*NW_;
    float acc[16][4];
    #pragma unroll
    for (int f = 0; f < 16; f++)
        #pragma unroll
        for (int e = 0; e < 4; e++) acc[f][e] = 0.f;
    const int NK = (D_/2)/32;       // 12
    int kb = khalf * (D_/2);
    g_load_stage(sb, g_rs_hi, g_rs_lo, D_, g_W2c_hi, g_W2c_lo, NW_, r0, n0, kb, tid);  cpa_commit();
    g_load_stage(sb+GSTAGE_, g_rs_hi, g_rs_lo, D_, g_W2c_hi, g_W2c_lo, NW_, r0, n0, kb+32, tid); cpa_commit();
    for (int i = 0; i < NK; i++) {
        cpa_wait1(); __syncthreads();
        g_compute(sb + (i&1)*GSTAGE_, w, l, acc);
        __syncthreads();
        if (i + 2 < NK)
            g_load_stage(sb + (i&1)*GSTAGE_, g_rs_hi, g_rs_lo, D_, g_W2c_hi, g_W2c_lo, NW_, r0, n0, kb+(i+2)*32, tid);
        cpa_commit();
    }
    int wm = w >> 1, wn = w & 1, g = l >> 2, tg = l & 3;
    #pragma unroll
    for (int mi = 0; mi < 2; mi++) {
        int row = r0 + wm*32 + mi*16 + g;
        #pragma unroll
        for (int f = 0; f < 8; f++) {
            int col = n0 + wn*64 + f*8 + tg*2;
            float* a4 = acc[mi*8 + f];
            out[(size_t)row*NW_ + col]       = a4[0];
            out[(size_t)row*NW_ + col+1]     = a4[1];
            out[(size_t)(row+8)*NW_ + col]   = a4[2];
            out[(size_t)(row+8)*NW_ + col+1] = a4[3];
        }
    }
}

// ---------------- kernel T: combine E0(gather) + E1 partials + tanh --------
__global__ void k_tanh(const int* __restrict__ hts,
                       const float* __restrict__ bh, const float* __restrict__ bt) {
    int i4 = blockIdx.x*blockDim.x + threadIdx.x;
    if (i4 >= BP_*NW_/4) return;
    int row = (i4*4) / NW_;
    int n   = (i4*4) % NW_;
    int sel = (n >= D_) ? 1 : 0;
    int col = n - sel*D_;
    int b = row / P_;
    int eidx = hts[row*2 + sel];
    int entrow = b*NE_ + eidx;
    const float4 a = ((const float4*)(g_ep))[i4];
    const float4 c = ((const float4*)(g_ep + (size_t)BP_*NW_))[i4];
    const float4 e0 = *(const float4*)(g_E0 + (size_t)entrow*NW_ + n);
    const float* bias = sel ? bt : bh;
    float4 bb = *(const float4*)(bias + col);
    float* out = sel ? g_zo : g_zs;
    float4 o;
    o.x = tanhf(a.x + c.x + e0.x + bb.x);
    o.y = tanhf(a.y + c.y + e0.y + bb.y);
    o.z = tanhf(a.z + c.z + e0.z + bb.z);
    o.w = tanhf(a.w + c.w + e0.w + bb.w);
    *(float4*)(out + (size_t)row*D_ + col) = o;
}

// ---------------- kernel Wpad: split W_bi into bf16 hi/lo (vectorized) -----
__global__ void k_padW_tc(const float* __restrict__ Wbi) {
    int ki = blockIdx.x;               // 0..767 (= k*64 + i)
    u32* d0 = (u32*)(g_Wb0 + (size_t)ki*WTILE_);
    u32* d1 = (u32*)(g_Wb1 + (size_t)ki*WTILE_);
    const float* src = Wbi + (size_t)ki*BLK_*NL_;
    for (int c = threadIdx.x; c < WTILE_/8; c += blockDim.x) {  // 1088
        int j = c / 17, c8 = (c % 17)*8;
        u32 h[4], lo[4];
        #pragma unroll
        for (int e = 0; e < 4; e++) {
            int n0 = c8 + 2*e, n1 = n0 + 1;
            float v0 = (n0 < NL_) ? src[j*NL_ + n0] : 0.f;
            float v1 = (n1 < NL_) ? src[j*NL_ + n1] : 0.f;
            h[e]  = cvt_bf2(v0, v1);
            lo[e] = cvt_bf2(v0 - bf_lo_f(h[e]), v1 - bf_hi_f(h[e]));
        }
        int base = (j*WPITCH_ + c8) >> 1;  // u32 index, 16B aligned
        *(uint4*)(d0 + base) = make_uint4(h[0], h[1], h[2], h[3]);
        *(uint4*)(d1 + base) = make_uint4(lo[0], lo[1], lo[2], lo[3]);
    }
}

// ---------------- kernel F: bilinear classifier via mma.sync bf16 ----------
#define SM_ZS 0                         // [128][65] f32
#define SM_ZO 33280                     // [128][66] f32
#define SM_W  67072
#define WSTAGE_ 34816
#define SMEMB_ (SM_W + 2*WSTAGE_)       // 136704

__global__ void __launch_bounds__(256, 1) k_bilinear_mma() {
    extern __shared__ char smem[];
    float* zs_s = (float*)(smem + SM_ZS);   // pitch 65
    float* zo_s = (float*)(smem + SM_ZO);   // pitch 66
    u32 sw = smem_u32(smem) + SM_W;
    int tid = threadIdx.x, w = tid >> 5, l = tid & 31;
    int g = l >> 2, tg = l & 3;
    int k  = blockIdx.y;
    int r0 = blockIdx.x * 128;
    int iseg = blockIdx.z;
    int i0 = iseg*21, i1 = (iseg == ISEG_-1) ? BLK_ : (i0 + 21);

    #pragma unroll
    for (int p = 0; p < 2; p++) {
        int ii = i0 + p;
        const char* src0 = (const char*)(g_Wb0 + (size_t)(k*BLK_ + ii)*WTILE_);
        const char* src1 = (const char*)(g_Wb1 + (size_t)(k*BLK_ + ii)*WTILE_);
        u32 dst = sw + (ii & 1)*WSTAGE_;
        #pragma unroll
        for (int t = 0; t < 5; t++) {
            int idx = tid + t*256;
            if (idx < 1088) {
                cpa16(dst + idx*16, src0 + idx*16);
                cpa16(dst + 17408 + idx*16, src1 + idx*16);
            }
        }
        cpa_commit();
    }

    for (int idx = tid; idx < 128*64; idx += 256) {
        int r = idx >> 6, c = idx & 63;
        zs_s[r*65 + c] = g_zs[(size_t)(r0+r)*D_ + k*BLK_ + c];
        zo_s[r*66 + c] = g_zo[(size_t)(r0+r)*D_ + k*BLK_ + c];
    }
    __syncthreads();

    int rg = w*16 + g;
    float2 zoA[4][2], zoB[4][2];
    #pragma unroll
    for (int jc = 0; jc < 4; jc++) {
        zoA[jc][0] = *(float2*)&zo_s[rg*66     + jc*16 + tg*2];
        zoA[jc][1] = *(float2*)&zo_s[rg*66     + jc*16 + tg*2 + 8];
        zoB[jc][0] = *(float2*)&zo_s[(rg+8)*66 + jc*16 + tg*2];
        zoB[jc][1] = *(float2*)&zo_s[(rg+8)*66 + jc*16 + tg*2 + 8];
    }

    float acc[14][4];
    #pragma unroll
    for (int t = 0; t < 14; t++)
        #pragma unroll
        for (int e = 0; e < 4; e++) acc[t][e] = 0.f;

    u32 laneoff = (u32)((l & 15)*272 + (l >> 4)*16);

    for (int i = i0; i < i1; i++) {
        int s = i & 1;
        cpa_wait1();
        __syncthreads();
        float zs0 = zs_s[rg*65 + i];
        float zs1 = zs_s[(rg+8)*65 + i];
        u32 sbase = sw + s*WSTAGE_;
        #pragma unroll
        for (int jc = 0; jc < 4; jc++) {
            float p0x = zs0*zoA[jc][0].x, p0y = zs0*zoA[jc][0].y;
            float p1x = zs1*zoB[jc][0].x, p1y = zs1*zoB[jc][0].y;
            float p2x = zs0*zoA[jc][1].x, p2y = zs0*zoA[jc][1].y;
            float p3x = zs1*zoB[jc][1].x, p3y = zs1*zoB[jc][1].y;
            u32 a0h = cvt_bf2(p0x, p0y);
            u32 a1h = cvt_bf2(p1x, p1y);
            u32 a2h = cvt_bf2(p2x, p2y);
            u32 a3h = cvt_bf2(p3x, p3y);
            u32 a0r = cvt_bf2(p0x - bf_lo_f(a0h), p0y - bf_hi_f(a0h));
            u32 a1r = cvt_bf2(p1x - bf_lo_f(a1h), p1y - bf_hi_f(a1h));
            u32 a2r = cvt_bf2(p2x - bf_lo_f(a2h), p2y - bf_hi_f(a2h));
            u32 a3r = cvt_bf2(p3x - bf_lo_f(a3h), p3y - bf_hi_f(a3h));
            u32 rowb = sbase + (u32)(jc*16*272) + laneoff;
            #pragma unroll
            for (int ntp = 0; ntp < 7; ntp++) {
                u32 b0, b1, b2, b3;
                ldsm4t(rowb + ntp*32, b0, b1, b2, b3);
                mma16816(acc[2*ntp],   a0h,a1h,a2h,a3h, b0, b1);
                mma16816(acc[2*ntp+1], a0h,a1h,a2h,a3h, b2, b3);
                mma16816(acc[2*ntp],   a0r,a1r,a2r,a3r, b0, b1);
                mma16816(acc[2*ntp+1], a0r,a1r,a2r,a3r, b2, b3);
                u32 c0, c1, c2, c3;
                ldsm4t(rowb + 17408 + ntp*32, c0, c1, c2, c3);
                mma16816(acc[2*ntp],   a0h,a1h,a2h,a3h, c0, c1);
                mma16816(acc[2*ntp+1], a0h,a1h,a2h,a3h, c2, c3);
            }
        }
        __syncthreads();
        if (i + 2 < i1) {
            const char* src0 = (const char*)(g_Wb0 + (size_t)(k*BLK_ + i + 2)*WTILE_);
            const char* src1 = (const char*)(g_Wb1 + (size_t)(k*BLK_ + i + 2)*WTILE_);
            u32 dst = sw + s*WSTAGE_;
            #pragma unroll
            for (int t = 0; t < 5; t++) {
                int idx = tid + t*256;
                if (idx < 1088) {
                    cpa16(dst + idx*16, src0 + idx*16);
                    cpa16(dst + 17408 + idx*16, src1 + idx*16);
                }
            }
        }
        cpa_commit();
    }

    int slab = iseg*KCH_ + k;
    float* base0 = g_part + ((size_t)slab*BP_ + r0 + rg)*NL_;
    float* base1 = g_part + ((size_t)slab*BP_ + r0 + rg + 8)*NL_;
    #pragma unroll
    for (int nt = 0; nt < 13; nt++) {
        int n0 = nt*8 + tg*2;
        if (n0 < NL_) { base0[n0] = acc[nt][0]; base1[n0] = acc[nt][2]; }
        if (n0 + 1 < NL_) { base0[n0+1] = acc[nt][1]; base1[n0+1] = acc[nt][3]; }
    }
}

// ---------------- kernel G: reduce split-K partials + bias -----------------
__global__ void k_reduce(const float* __restrict__ bbi, float* __restrict__ out) {
    int idx = blockIdx.x*256 + threadIdx.x;
    if (idx >= BP_*NL_) return;
    int n = idx % NL_;
    float s = bbi[n];
    #pragma unroll
    for (int k = 0; k < KSLAB_; k++)
        s += g_part[(size_t)k*BP_*NL_ + idx];
    out[idx] = s;
}

// ---------------- launch ---------------------------------------------------
extern "C" void kernel_launch(void* const* d_in, const int* in_sizes, int n_in,
                              void* d_out, int out_size) {
    const float* seq  = (const float*)d_in[0];
    const float* att  = (const float*)d_in[1];
    const int*   mpos = (const int*)d_in[2];
    const int*   hts  = (const int*)d_in[3];
    const float* Wh   = (const float*)d_in[4];
    const float* bh   = (const float*)d_in[5];
    const float* Wt   = (const float*)d_in[6];
    const float* bt   = (const float*)d_in[7];
    const float* Wbi  = (const float*)d_in[8];
    const float* bbi  = (const float*)d_in[9];
    float* out = (float*)d_out;

    static bool attr_set = false;
    if (!attr_set) {
        cudaFuncSetAttribute(k_bilinear_mma,
            cudaFuncAttributeMaxDynamicSharedMemorySize, SMEMB_);
        cudaFuncSetAttribute(k_rs_mma,
            cudaFuncAttributeMaxDynamicSharedMemorySize, GSM_);
        cudaFuncSetAttribute(k_E0,
            cudaFuncAttributeMaxDynamicSharedMemorySize, GSM_);
        cudaFuncSetAttribute(k_E1,
            cudaFuncAttributeMaxDynamicSharedMemorySize, GSM_);
        attr_set = true;
    }

    k_split_all<<<(SPLIT_SEQ + 2*SPLIT_W + 255)/256, 256>>>(seq, Wh, Wt);
    k_padW_tc<<<KCH_*BLK_, 256>>>(Wbi);
    k_ent_emb<<<B_*NE_, 256>>>(seq, mpos);
    k_ent_att<<<B_*NE_*H_, 256>>>(att, mpos);
    k_ht<<<B_*P_, 256>>>(hts);
    k_rs_mma<<<dim3(BP_/128, D_/128), 256, GSM_>>>();
    k_E0<<<dim3(2, NW_/128), 256, GSM_>>>();
    k_E1<<<dim3(BP_/128, NW_/128, 2), 256, GSM_>>>();
    k_tanh<<<(BP_*NW_/4 + 255)/256, 256>>>(hts, bh, bt);
    k_bilinear_mma<<<dim3(BP_/128, KCH_, ISEG_), 256, SMEMB_>>>();
    k_reduce<<<(BP_*NL_ + 255)/256, 256>>>(bbi, out);
}

// round 9
// speedup vs baseline: 3.8873x; 1.0957x over previous
#include <cuda_runtime.h>
#include <cuda_bf16.h>
#include <math.h>
#include <stdint.h>

#define B_ 4
#define L_ 1024
#define D_ 768
#define H_ 12
#define NE_ 42
#define M_ 4
#define P_ 512
#define BLK_ 64
#define NL_ 97
#define OFFSET_ 1
#define BP_ (B_*P_)          // 2048
#define KCH_ (D_/BLK_)       // 12 channel blocks
#define ISEG_ 3              // bilinear i-range split
#define KSLAB_ (ISEG_*KCH_)  // 36 partial slabs
#define NW_ 1536             // concat output width for extractors
#define WPITCH_ 136          // padded n (bf16), 272B rows -> conflict-free ldmatrix
#define WTILE_ (BLK_*WPITCH_) // per (k,i) split tile for bilinear W

typedef unsigned long long u64;
typedef unsigned int u32;

// ---------------- helpers ---------------------------------------------------
__device__ __forceinline__ u32 smem_u32(const void* p) {
    u32 a; asm("{ .reg .u64 t; cvta.to.shared.u64 t, %1; cvt.u32.u64 %0, t; }"
               : "=r"(a) : "l"(p));
    return a;
}
// pack two f32 -> bf16x2 (first arg -> LOWER half)
__device__ __forceinline__ u32 cvt_bf2(float lo, float hi) {
    u32 d; asm("cvt.rn.bf16x2.f32 %0, %1, %2;" : "=r"(d) : "f"(hi), "f"(lo));
    return d;
}
__device__ __forceinline__ float bf_lo_f(u32 c) { return __uint_as_float(c << 16); }
__device__ __forceinline__ float bf_hi_f(u32 c) { return __uint_as_float(c & 0xFFFF0000u); }

__device__ __forceinline__ void cpa16(u32 dst, const void* src) {
    asm volatile("cp.async.cg.shared.global [%0], [%1], 16;"
                 :: "r"(dst), "l"(src) : "memory");
}
__device__ __forceinline__ void cpa_commit() {
    asm volatile("cp.async.commit_group;" ::: "memory");
}
__device__ __forceinline__ void cpa_wait1() {
    asm volatile("cp.async.wait_group 1;" ::: "memory");
}
__device__ __forceinline__ void ldsm4(u32 addr, u32& r0, u32& r1, u32& r2, u32& r3) {
    asm volatile("ldmatrix.sync.aligned.m8n8.x4.shared.b16 {%0,%1,%2,%3}, [%4];"
                 : "=r"(r0), "=r"(r1), "=r"(r2), "=r"(r3) : "r"(addr));
}
__device__ __forceinline__ void ldsm4t(u32 addr, u32& r0, u32& r1, u32& r2, u32& r3) {
    asm volatile("ldmatrix.sync.aligned.m8n8.x4.trans.shared.b16 {%0,%1,%2,%3}, [%4];"
                 : "=r"(r0), "=r"(r1), "=r"(r2), "=r"(r3) : "r"(addr));
}
__device__ __forceinline__ void mma16816(float* d,
                                         u32 a0, u32 a1, u32 a2, u32 a3,
                                         u32 b0, u32 b1) {
    asm volatile(
        "mma.sync.aligned.m16n8k16.row.col.f32.bf16.bf16.f32 "
        "{%0,%1,%2,%3}, {%4,%5,%6,%7}, {%8,%9}, {%0,%1,%2,%3};"
        : "+f"(d[0]), "+f"(d[1]), "+f"(d[2]), "+f"(d[3])
        : "r"(a0), "r"(a1), "r"(a2), "r"(a3), "r"(b0), "r"(b1));
}

// ---------------- scratch (device globals; no runtime allocation) ----------
__device__ float g_ent_att[B_*NE_*H_*L_];
__device__ __nv_bfloat16 g_entA_hi[256*D_], g_entA_lo[256*D_];  // 168 used
__device__ __nv_bfloat16 g_seq_hi[B_*L_*D_],  g_seq_lo[B_*L_*D_];
__device__ __nv_bfloat16 g_ht_hi[B_*P_*L_],   g_ht_lo[B_*P_*L_];
__device__ __nv_bfloat16 g_rs_hi[BP_*D_], g_rs_lo[BP_*D_];
__device__ __nv_bfloat16 g_W1c_hi[D_*NW_], g_W1c_lo[D_*NW_];  // [k][Wh|Wt] rows 0..767
__device__ __nv_bfloat16 g_W2c_hi[D_*NW_], g_W2c_lo[D_*NW_];  // rows 768..1535
__device__ float g_E0[256*NW_];                  // entity-side extract
__device__ float g_ep[2*BP_*NW_];                // E1 K-split partials
__device__ float g_zs[BP_*D_], g_zo[BP_*D_];
__device__ float g_part[KSLAB_*BP_*NL_];         // bilinear partials
__device__ __nv_bfloat16 g_Wb0[KCH_*BLK_*WTILE_], g_Wb1[KCH_*BLK_*WTILE_];

// ---------------- fused prep kernel: split + padW + ent_emb + ent_att ------
#define SPLIT_SEQ (B_*L_*D_/2)
#define SPLIT_W   (D_*D_)
#define NB_SPLIT ((SPLIT_SEQ + 2*SPLIT_W + 255)/256)   // 10752
#define NB_PADW  (KCH_*BLK_)                            // 768
#define NB_EMB   (B_*NE_)                               // 168
#define NB_ATT   (B_*NE_*H_)                            // 2016
#define NB_PREP  (NB_SPLIT + NB_PADW + NB_EMB + NB_ATT)

__global__ void k_prep(const float* __restrict__ seq,
                       const float* __restrict__ Wh,
                       const float* __restrict__ Wt,
                       const float* __restrict__ Wbi,
                       const int* __restrict__ mpos) {
    int bb = blockIdx.x;
    int tid = threadIdx.x;
    if (bb < NB_SPLIT) {
        // ---- fp32 -> bf16 hi/lo split: seq, then Wh|Wt concat-packed ----
        int i = bb*256 + tid;
        if (i < SPLIT_SEQ) {
            float v0 = seq[2*i], v1 = seq[2*i+1];
            u32 h = cvt_bf2(v0, v1);
            ((u32*)g_seq_hi)[i] = h;
            ((u32*)g_seq_lo)[i] = cvt_bf2(v0 - bf_lo_f(h), v1 - bf_hi_f(h));
            return;
        }
        int j = i - SPLIT_SEQ;
        if (j >= 2*SPLIT_W) return;
        int sel = (j >= SPLIT_W) ? 1 : 0;
        int off = j - sel*SPLIT_W;
        const float* W = sel ? Wt : Wh;
        int kg = (2*off) / D_;
        int d  = (2*off) % D_;
        float v0 = W[2*off], v1 = W[2*off+1];
        u32 h = cvt_bf2(v0, v1);
        u32 r = cvt_bf2(v0 - bf_lo_f(h), v1 - bf_hi_f(h));
        u32 *hi, *lo;
        int rowk;
        if (kg < D_) { hi = (u32*)g_W1c_hi; lo = (u32*)g_W1c_lo; rowk = kg; }
        else         { hi = (u32*)g_W2c_hi; lo = (u32*)g_W2c_lo; rowk = kg - D_; }
        int idx = rowk*(NW_/2) + sel*(D_/2) + d/2;
        hi[idx] = h;
        lo[idx] = r;
        return;
    }
    bb -= NB_SPLIT;
    if (bb < NB_PADW) {
        // ---- split W_bi into bf16 hi/lo, padded/pitched ----
        int ki = bb;
        u32* d0 = (u32*)(g_Wb0 + (size_t)ki*WTILE_);
        u32* d1 = (u32*)(g_Wb1 + (size_t)ki*WTILE_);
        const float* src = Wbi + (size_t)ki*BLK_*NL_;
        for (int c = tid; c < WTILE_/8; c += 256) {   // 1088
            int j = c / 17, c8 = (c % 17)*8;
            u32 h[4], lo[4];
            #pragma unroll
            for (int e = 0; e < 4; e++) {
                int n0 = c8 + 2*e, n1 = n0 + 1;
                float v0 = (n0 < NL_) ? src[j*NL_ + n0] : 0.f;
                float v1 = (n1 < NL_) ? src[j*NL_ + n1] : 0.f;
                h[e]  = cvt_bf2(v0, v1);
                lo[e] = cvt_bf2(v0 - bf_lo_f(h[e]), v1 - bf_hi_f(h[e]));
            }
            int base = (j*WPITCH_ + c8) >> 1;
            *(uint4*)(d0 + base) = make_uint4(h[0], h[1], h[2], h[3]);
            *(uint4*)(d1 + base) = make_uint4(lo[0], lo[1], lo[2], lo[3]);
        }
        return;
    }
    bb -= NB_PADW;
    if (bb < NB_EMB) {
        // ---- entity embeds = logsumexp over mentions -> bf16 split ----
        int be = bb;
        int b  = be / NE_;
        int base = be * M_;
        int p0 = mpos[base+0] + OFFSET_;
        int p1 = mpos[base+1] + OFFSET_;
        int p2 = mpos[base+2] + OFFSET_;
        int p3 = mpos[base+3] + OFFSET_;
        const float* s0 = seq + ((size_t)b*L_ + p0)*D_;
        const float* s1 = seq + ((size_t)b*L_ + p1)*D_;
        const float* s2 = seq + ((size_t)b*L_ + p2)*D_;
        const float* s3 = seq + ((size_t)b*L_ + p3)*D_;
        for (int d = tid; d < D_; d += 256) {
            float x0 = s0[d], x1 = s1[d], x2 = s2[d], x3 = s3[d];
            float mx = fmaxf(fmaxf(x0,x1), fmaxf(x2,x3));
            float v = mx + logf(expf(x0-mx) + expf(x1-mx) + expf(x2-mx) + expf(x3-mx));
            __nv_bfloat16 hb = __float2bfloat16(v);
            g_entA_hi[(size_t)be*D_ + d] = hb;
            g_entA_lo[(size_t)be*D_ + d] = __float2bfloat16(v - __bfloat162float(hb));
        }
        return;
    }
    bb -= NB_EMB;
    {
        // ---- entity attention = mean over mention rows (att passed via Wbi? no: need att) ----
        // handled in k_ent_att below (needs attention pointer) -- see dispatch note
    }
}

// ent_att kept separate (needs the big attention tensor pointer; also keeps
// k_prep's register/pointer count low). Still merged conceptually: launched
// concurrently-adjacent.
__global__ void k_ent_att(const float* __restrict__ att,
                          const int* __restrict__ mpos) {
    int id = blockIdx.x;
    int h  = id % H_;
    int be = id / H_;
    int b  = be / NE_;
    int base = be * M_;
    const float* a = att + (((size_t)b*H_ + h)*L_)*L_;
    const float* r0 = a + (size_t)(mpos[base+0]+OFFSET_)*L_;
    const float* r1 = a + (size_t)(mpos[base+1]+OFFSET_)*L_;
    const float* r2 = a + (size_t)(mpos[base+2]+OFFSET_)*L_;
    const float* r3 = a + (size_t)(mpos[base+3]+OFFSET_)*L_;
    float* out = g_ent_att + ((size_t)be*H_ + h)*L_;
    for (int l = threadIdx.x; l < L_; l += blockDim.x)
        out[l] = 0.25f * (r0[l] + r1[l] + r2[l] + r3[l]);
}

// ---------------- kernel C: per-pair channel attention -> bf16 split -------
__global__ void k_ht(const int* __restrict__ hts) {
    int bp = blockIdx.x;
    int b  = bp / P_;
    int hi = hts[bp*2 + 0];
    int ti = hts[bp*2 + 1];
    const float* ah = g_ent_att + (size_t)(b*NE_ + hi)*H_*L_;
    const float* at = g_ent_att + (size_t)(b*NE_ + ti)*H_*L_;
    const int T = 256;
    float v[4];
    float lsum = 0.f;
    #pragma unroll
    for (int it = 0; it < 4; it++) {
        int l = threadIdx.x + it*T;
        float acc = 0.f;
        #pragma unroll
        for (int h = 0; h < H_; h++)
            acc += ah[h*L_ + l] * at[h*L_ + l];
        acc *= (1.f/H_);
        v[it] = acc;
        lsum += acc;
    }
    __shared__ float red[32];
    #pragma unroll
    for (int o = 16; o; o >>= 1) lsum += __shfl_down_sync(~0u, lsum, o);
    if ((threadIdx.x & 31) == 0) red[threadIdx.x >> 5] = lsum;
    __syncthreads();
    if (threadIdx.x < 8) {
        float t = red[threadIdx.x];
        #pragma unroll
        for (int o = 4; o; o >>= 1) t += __shfl_down_sync(0xffu, t, o);
        if (threadIdx.x == 0) red[0] = 1.f / (t + 1e-5f);
    }
    __syncthreads();
    float inv = red[0];
    #pragma unroll
    for (int it = 0; it < 4; it++) {
        int l = threadIdx.x + it*T;
        float vv = v[it] * inv;
        __nv_bfloat16 hb = __float2bfloat16(vv);
        g_ht_hi[(size_t)bp*L_ + l] = hb;
        g_ht_lo[(size_t)bp*L_ + l] = __float2bfloat16(vv - __bfloat162float(hb));
    }
}

// ---------------- generic mma GEMM core (128x128 tile, K-chunk 32) ---------
#define GA_PITCH 80                  // bytes per A smem row (40 bf16)
#define GB_PITCH 272                 // bytes per B smem row (136 bf16)
#define GSA_ 10240                   // 128*80
#define GSB_ 8704                    // 32*272
#define GSTAGE_ 37888                // 2*GSA_ + 2*GSB_
#define GSM_ 75776

__device__ __forceinline__ void g_load_stage(u32 sbase,
    const __nv_bfloat16* __restrict__ Ah, const __nv_bfloat16* __restrict__ Al,
    int lda,
    const __nv_bfloat16* __restrict__ Bh, const __nv_bfloat16* __restrict__ Bl,
    int ldb,
    int r0, int n0, int kc, int tid)
{
    #pragma unroll
    for (int t = 0; t < 2; t++) {
        int idx = tid + t*256;             // 512 = 128 rows x 4 chunks
        int row = idx >> 2, c = idx & 3;
        size_t so = (size_t)(r0+row)*lda + kc + c*8;
        cpa16(sbase + row*GA_PITCH + c*16, Ah + so);
        cpa16(sbase + GSA_ + row*GA_PITCH + c*16, Al + so);
    }
    #pragma unroll
    for (int t = 0; t < 2; t++) {
        int idx = tid + t*256;             // 512 = 32 rows x 16 chunks
        int row = idx >> 4, c = idx & 15;
        size_t so = (size_t)(kc+row)*ldb + n0 + c*8;
        cpa16(sbase + 2*GSA_ + row*GB_PITCH + c*16, Bh + so);
        cpa16(sbase + 2*GSA_ + GSB_ + row*GB_PITCH + c*16, Bl + so);
    }
}

__device__ __forceinline__ void g_compute(u32 sbase, int w, int l,
                                          float (*acc)[4]) {
    int wm = w >> 1, wn = w & 1;
    u32 abase = sbase + (u32)((wm*32 + (l&15))*GA_PITCH + (l>>4)*16);
    u32 bbase = sbase + 2*GSA_ +
                (u32)((l&15)*GB_PITCH + (wn*64 + (l>>4)*8)*2);
    #pragma unroll
    for (int kk = 0; kk < 2; kk++) {
        u32 ah[2][4], al[2][4];
        #pragma unroll
        for (int mi = 0; mi < 2; mi++) {
            ldsm4(abase + mi*16*GA_PITCH + kk*32,
                  ah[mi][0], ah[mi][1], ah[mi][2], ah[mi][3]);
            ldsm4(abase + GSA_ + mi*16*GA_PITCH + kk*32,
                  al[mi][0], al[mi][1], al[mi][2], al[mi][3]);
        }
        u32 bb = bbase + kk*16*GB_PITCH;
        #pragma unroll
        for (int ntp = 0; ntp < 4; ntp++) {
            u32 b0,b1,b2,b3, c0,c1,c2,c3;
            ldsm4t(bb + ntp*32, b0,b1,b2,b3);
            ldsm4t(bb + GSB_ + ntp*32, c0,c1,c2,c3);
            #pragma unroll
            for (int mi = 0; mi < 2; mi++) {
                float* A0 = acc[mi*8 + 2*ntp];
                float* A1 = acc[mi*8 + 2*ntp + 1];
                mma16816(A0, ah[mi][0],ah[mi][1],ah[mi][2],ah[mi][3], b0,b1);
                mma16816(A1, ah[mi][0],ah[mi][1],ah[mi][2],ah[mi][3], b2,b3);
                mma16816(A0, ah[mi][0],ah[mi][1],ah[mi][2],ah[mi][3], c0,c1);
                mma16816(A1, ah[mi][0],ah[mi][1],ah[mi][2],ah[mi][3], c2,c3);
                mma16816(A0, al[mi][0],al[mi][1],al[mi][2],al[mi][3], b0,b1);
                mma16816(A1, al[mi][0],al[mi][1],al[mi][2],al[mi][3], b2,b3);
            }
        }
    }
}

// ---------------- kernel D: rs GEMM -> split bf16 rs arrays ----------------
__global__ void __launch_bounds__(256, 1) k_rs_mma() {
    extern __shared__ char smem[];
    u32 sb = smem_u32(smem);
    int tid = threadIdx.x, w = tid >> 5, l = tid & 31;
    int r0 = blockIdx.x * 128, n0 = blockIdx.y * 128;
    int b = r0 / P_;
    const __nv_bfloat16* Ah = g_ht_hi;
    const __nv_bfloat16* Al = g_ht_lo;
    const __nv_bfloat16* Bh = g_seq_hi + (size_t)b*L_*D_;
    const __nv_bfloat16* Bl = g_seq_lo + (size_t)b*L_*D_;
    float acc[16][4];
    #pragma unroll
    for (int f = 0; f < 16; f++)
        #pragma unroll
        for (int e = 0; e < 4; e++) acc[f][e] = 0.f;
    const int NK = L_/32;           // 32
    g_load_stage(sb, Ah, Al, L_, Bh, Bl, D_, r0, n0, 0, tid);  cpa_commit();
    g_load_stage(sb+GSTAGE_, Ah, Al, L_, Bh, Bl, D_, r0, n0, 32, tid); cpa_commit();
    for (int i = 0; i < NK; i++) {
        cpa_wait1(); __syncthreads();
        g_compute(sb + (i&1)*GSTAGE_, w, l, acc);
        __syncthreads();
        if (i + 2 < NK)
            g_load_stage(sb + (i&1)*GSTAGE_, Ah, Al, L_, Bh, Bl, D_, r0, n0, (i+2)*32, tid);
        cpa_commit();
    }
    int wm = w >> 1, wn = w & 1, g = l >> 2, tg = l & 3;
    #pragma unroll
    for (int mi = 0; mi < 2; mi++) {
        int row = r0 + wm*32 + mi*16 + g;
        #pragma unroll
        for (int f = 0; f < 8; f++) {
            int col = n0 + wn*64 + f*8 + tg*2;
            float* a4 = acc[mi*8 + f];
            #pragma unroll
            for (int rh = 0; rh < 2; rh++) {
                float v0 = a4[rh*2], v1 = a4[rh*2+1];
                u32 hp = cvt_bf2(v0, v1);
                u32 lp = cvt_bf2(v0 - bf_lo_f(hp), v1 - bf_hi_f(hp));
                size_t o = (size_t)(row + rh*8)*D_ + col;
                *(u32*)(g_rs_hi + o) = hp;
                *(u32*)(g_rs_lo + o) = lp;
            }
        }
    }
}

// ---------------- kernel E0: entity-side extract  [256,768]@[768,1536] -----
__global__ void __launch_bounds__(256, 1) k_E0() {
    extern __shared__ char smem[];
    u32 sb = smem_u32(smem);
    int tid = threadIdx.x, w = tid >> 5, l = tid & 31;
    int r0 = blockIdx.x * 128, n0 = blockIdx.y * 128;
    float acc[16][4];
    #pragma unroll
    for (int f = 0; f < 16; f++)
        #pragma unroll
        for (int e = 0; e < 4; e++) acc[f][e] = 0.f;
    const int NK = D_/32;           // 24
    g_load_stage(sb, g_entA_hi, g_entA_lo, D_, g_W1c_hi, g_W1c_lo, NW_, r0, n0, 0, tid);  cpa_commit();
    g_load_stage(sb+GSTAGE_, g_entA_hi, g_entA_lo, D_, g_W1c_hi, g_W1c_lo, NW_, r0, n0, 32, tid); cpa_commit();
    for (int i = 0; i < NK; i++) {
        cpa_wait1(); __syncthreads();
        g_compute(sb + (i&1)*GSTAGE_, w, l, acc);
        __syncthreads();
        if (i + 2 < NK)
            g_load_stage(sb + (i&1)*GSTAGE_, g_entA_hi, g_entA_lo, D_, g_W1c_hi, g_W1c_lo, NW_, r0, n0, (i+2)*32, tid);
        cpa_commit();
    }
    int wm = w >> 1, wn = w & 1, g = l >> 2, tg = l & 3;
    #pragma unroll
    for (int mi = 0; mi < 2; mi++) {
        int row = r0 + wm*32 + mi*16 + g;
        #pragma unroll
        for (int f = 0; f < 8; f++) {
            int col = n0 + wn*64 + f*8 + tg*2;
            float* a4 = acc[mi*8 + f];
            g_E0[(size_t)row*NW_ + col]       = a4[0];
            g_E0[(size_t)row*NW_ + col+1]     = a4[1];
            g_E0[(size_t)(row+8)*NW_ + col]   = a4[2];
            g_E0[(size_t)(row+8)*NW_ + col+1] = a4[3];
        }
    }
}

// ---------------- kernel E1: rs@[W2h|W2t], K-split x2, 2 blocks/SM ---------
__global__ void __launch_bounds__(256, 2) k_E1() {
    extern __shared__ char smem[];
    u32 sb = smem_u32(smem);
    int tid = threadIdx.x, w = tid >> 5, l = tid & 31;
    int khalf = blockIdx.z;
    int r0 = blockIdx.x * 128, n0 = blockIdx.y * 128;
    float* out = g_ep + (size_t)khalf*BP_*NW_;
    float acc[16][4];
    #pragma unroll
    for (int f = 0; f < 16; f++)
        #pragma unroll
        for (int e = 0; e < 4; e++) acc[f][e] = 0.f;
    const int NK = (D_/2)/32;       // 12
    int kb = khalf * (D_/2);
    g_load_stage(sb, g_rs_hi, g_rs_lo, D_, g_W2c_hi, g_W2c_lo, NW_, r0, n0, kb, tid);  cpa_commit();
    g_load_stage(sb+GSTAGE_, g_rs_hi, g_rs_lo, D_, g_W2c_hi, g_W2c_lo, NW_, r0, n0, kb+32, tid); cpa_commit();
    for (int i = 0; i < NK; i++) {
        cpa_wait1(); __syncthreads();
        g_compute(sb + (i&1)*GSTAGE_, w, l, acc);
        __syncthreads();
        if (i + 2 < NK)
            g_load_stage(sb + (i&1)*GSTAGE_, g_rs_hi, g_rs_lo, D_, g_W2c_hi, g_W2c_lo, NW_, r0, n0, kb+(i+2)*32, tid);
        cpa_commit();
    }
    int wm = w >> 1, wn = w & 1, g = l >> 2, tg = l & 3;
    #pragma unroll
    for (int mi = 0; mi < 2; mi++) {
        int row = r0 + wm*32 + mi*16 + g;
        #pragma unroll
        for (int f = 0; f < 8; f++) {
            int col = n0 + wn*64 + f*8 + tg*2;
            float* a4 = acc[mi*8 + f];
            out[(size_t)row*NW_ + col]       = a4[0];
            out[(size_t)row*NW_ + col+1]     = a4[1];
            out[(size_t)(row+8)*NW_ + col]   = a4[2];
            out[(size_t)(row+8)*NW_ + col+1] = a4[3];
        }
    }
}

// ---------------- kernel T: combine E0(gather) + E1 partials + tanh --------
__global__ void k_tanh(const int* __restrict__ hts,
                       const float* __restrict__ bh, const float* __restrict__ bt) {
    int i4 = blockIdx.x*blockDim.x + threadIdx.x;
    if (i4 >= BP_*NW_/4) return;
    int row = (i4*4) / NW_;
    int n   = (i4*4) % NW_;
    int sel = (n >= D_) ? 1 : 0;
    int col = n - sel*D_;
    int b = row / P_;
    int eidx = hts[row*2 + sel];
    int entrow = b*NE_ + eidx;
    const float4 a = ((const float4*)(g_ep))[i4];
    const float4 c = ((const float4*)(g_ep + (size_t)BP_*NW_))[i4];
    const float4 e0 = *(const float4*)(g_E0 + (size_t)entrow*NW_ + n);
    const float* bias = sel ? bt : bh;
    float4 bb = *(const float4*)(bias + col);
    float* out = sel ? g_zo : g_zs;
    float4 o;
    o.x = tanhf(a.x + c.x + e0.x + bb.x);
    o.y = tanhf(a.y + c.y + e0.y + bb.y);
    o.z = tanhf(a.z + c.z + e0.z + bb.z);
    o.w = tanhf(a.w + c.w + e0.w + bb.w);
    *(float4*)(out + (size_t)row*D_ + col) = o;
}

// ---------------- kernel F: bilinear classifier, slim smem, 2 blocks/SM ----
#define SM_ZSB 0                        // [128][24] f32 = 12288
#define SM_WB  12288
#define WSTAGE_ 34816
#define SMEMB_ (SM_WB + 2*WSTAGE_)      // 81920

__global__ void __launch_bounds__(256, 2) k_bilinear_mma(const int* __restrict__ dummy) {
    extern __shared__ char smem[];
    float* zs_s = (float*)(smem + SM_ZSB);  // pitch 24, only this block's i-range
    u32 sw = smem_u32(smem) + SM_WB;
    int tid = threadIdx.x, w = tid >> 5, l = tid & 31;
    int g = l >> 2, tg = l & 3;
    int k  = blockIdx.y;
    int r0 = blockIdx.x * 128;
    int iseg = blockIdx.z;
    int i0 = iseg*21, i1 = (iseg == ISEG_-1) ? BLK_ : (i0 + 21);
    int LEN = i1 - i0;

    // ---- prologue: W stages for i0, i0+1 ----
    #pragma unroll
    for (int p = 0; p < 2; p++) {
        int ii = i0 + p;
        const char* src0 = (const char*)(g_Wb0 + (size_t)(k*BLK_ + ii)*WTILE_);
        const char* src1 = (const char*)(g_Wb1 + (size_t)(k*BLK_ + ii)*WTILE_);
        u32 dst = sw + (ii & 1)*WSTAGE_;
        #pragma unroll
        for (int t = 0; t < 5; t++) {
            int idx = tid + t*256;
            if (idx < 1088) {
                cpa16(dst + idx*16, src0 + idx*16);
                cpa16(dst + 17408 + idx*16, src1 + idx*16);
            }
        }
        cpa_commit();
    }

    int rg = w*16 + g;
    // ---- zo fragment values straight from global (one-time) ----
    float2 zoA[4][2], zoB[4][2];
    {
        const float* zor0 = g_zo + (size_t)(r0+rg)*D_ + k*BLK_;
        const float* zor1 = g_zo + (size_t)(r0+rg+8)*D_ + k*BLK_;
        #pragma unroll
        for (int jc = 0; jc < 4; jc++) {
            zoA[jc][0] = *(const float2*)(zor0 + jc*16 + tg*2);
            zoA[jc][1] = *(const float2*)(zor0 + jc*16 + tg*2 + 8);
            zoB[jc][0] = *(const float2*)(zor1 + jc*16 + tg*2);
            zoB[jc][1] = *(const float2*)(zor1 + jc*16 + tg*2 + 8);
        }
    }
    // ---- stage zs i-range slice [128][LEN] ----
    for (int idx = tid; idx < 128*LEN; idx += 256) {
        int r = idx / LEN, c = idx % LEN;
        zs_s[r*24 + c] = g_zs[(size_t)(r0+r)*D_ + k*BLK_ + i0 + c];
    }

    float acc[14][4];
    #pragma unroll
    for (int t = 0; t < 14; t++)
        #pragma unroll
        for (int e = 0; e < 4; e++) acc[t][e] = 0.f;

    u32 laneoff = (u32)((l & 15)*272 + (l >> 4)*16);

    for (int i = i0; i < i1; i++) {
        int s = i & 1;
        cpa_wait1();
        __syncthreads();                 // W stage ready + zs_s visible
        float zs0 = zs_s[rg*24 + (i - i0)];
        float zs1 = zs_s[(rg+8)*24 + (i - i0)];
        u32 sbase = sw + s*WSTAGE_;
        #pragma unroll
        for (int jc = 0; jc < 4; jc++) {
            float p0x = zs0*zoA[jc][0].x, p0y = zs0*zoA[jc][0].y;
            float p1x = zs1*zoB[jc][0].x, p1y = zs1*zoB[jc][0].y;
            float p2x = zs0*zoA[jc][1].x, p2y = zs0*zoA[jc][1].y;
            float p3x = zs1*zoB[jc][1].x, p3y = zs1*zoB[jc][1].y;
            u32 a0h = cvt_bf2(p0x, p0y);
            u32 a1h = cvt_bf2(p1x, p1y);
            u32 a2h = cvt_bf2(p2x, p2y);
            u32 a3h = cvt_bf2(p3x, p3y);
            u32 a0r = cvt_bf2(p0x - bf_lo_f(a0h), p0y - bf_hi_f(a0h));
            u32 a1r = cvt_bf2(p1x - bf_lo_f(a1h), p1y - bf_hi_f(a1h));
            u32 a2r = cvt_bf2(p2x - bf_lo_f(a2h), p2y - bf_hi_f(a2h));
            u32 a3r = cvt_bf2(p3x - bf_lo_f(a3h), p3y - bf_hi_f(a3h));
            u32 rowb = sbase + (u32)(jc*16*272) + laneoff;
            #pragma unroll
            for (int ntp = 0; ntp < 7; ntp++) {
                u32 b0, b1, b2, b3;
                ldsm4t(rowb + ntp*32, b0, b1, b2, b3);
                mma16816(acc[2*ntp],   a0h,a1h,a2h,a3h, b0, b1);
                mma16816(acc[2*ntp+1], a0h,a1h,a2h,a3h, b2, b3);
                mma16816(acc[2*ntp],   a0r,a1r,a2r,a3r, b0, b1);
                mma16816(acc[2*ntp+1], a0r,a1r,a2r,a3r, b2, b3);
                u32 c0, c1, c2, c3;
                ldsm4t(rowb + 17408 + ntp*32, c0, c1, c2, c3);
                mma16816(acc[2*ntp],   a0h,a1h,a2h,a3h, c0, c1);
                mma16816(acc[2*ntp+1], a0h,a1h,a2h,a3h, c2, c3);
            }
        }
        __syncthreads();
        if (i + 2 < i1) {
            const char* src0 = (const char*)(g_Wb0 + (size_t)(k*BLK_ + i + 2)*WTILE_);
            const char* src1 = (const char*)(g_Wb1 + (size_t)(k*BLK_ + i + 2)*WTILE_);
            u32 dst = sw + s*WSTAGE_;
            #pragma unroll
            for (int t = 0; t < 5; t++) {
                int idx = tid + t*256;
                if (idx < 1088) {
                    cpa16(dst + idx*16, src0 + idx*16);
                    cpa16(dst + 17408 + idx*16, src1 + idx*16);
                }
            }
        }
        cpa_commit();
    }

    int slab = iseg*KCH_ + k;
    float* base0 = g_part + ((size_t)slab*BP_ + r0 + rg)*NL_;
    float* base1 = g_part + ((size_t)slab*BP_ + r0 + rg + 8)*NL_;
    #pragma unroll
    for (int nt = 0; nt < 13; nt++) {
        int n0 = nt*8 + tg*2;
        if (n0 < NL_) { base0[n0] = acc[nt][0]; base1[n0] = acc[nt][2]; }
        if (n0 + 1 < NL_) { base0[n0+1] = acc[nt][1]; base1[n0+1] = acc[nt][3]; }
    }
}

// ---------------- kernel G: reduce split-K partials + bias -----------------
__global__ void k_reduce(const float* __restrict__ bbi, float* __restrict__ out) {
    int idx = blockIdx.x*256 + threadIdx.x;
    if (idx >= BP_*NL_) return;
    int n = idx % NL_;
    float s = bbi[n];
    #pragma unroll
    for (int k = 0; k < KSLAB_; k++)
        s += g_part[(size_t)k*BP_*NL_ + idx];
    out[idx] = s;
}

// ---------------- launch ---------------------------------------------------
extern "C" void kernel_launch(void* const* d_in, const int* in_sizes, int n_in,
                              void* d_out, int out_size) {
    const float* seq  = (const float*)d_in[0];
    const float* att  = (const float*)d_in[1];
    const int*   mpos = (const int*)d_in[2];
    const int*   hts  = (const int*)d_in[3];
    const float* Wh   = (const float*)d_in[4];
    const float* bh   = (const float*)d_in[5];
    const float* Wt   = (const float*)d_in[6];
    const float* bt   = (const float*)d_in[7];
    const float* Wbi  = (const float*)d_in[8];
    const float* bbi  = (const float*)d_in[9];
    float* out = (float*)d_out;

    static bool attr_set = false;
    if (!attr_set) {
        cudaFuncSetAttribute(k_bilinear_mma,
            cudaFuncAttributeMaxDynamicSharedMemorySize, SMEMB_);
        cudaFuncSetAttribute(k_rs_mma,
            cudaFuncAttributeMaxDynamicSharedMemorySize, GSM_);
        cudaFuncSetAttribute(k_E0,
            cudaFuncAttributeMaxDynamicSharedMemorySize, GSM_);
        cudaFuncSetAttribute(k_E1,
            cudaFuncAttributeMaxDynamicSharedMemorySize, GSM_);
        attr_set = true;
    }

    k_prep<<<NB_SPLIT + NB_PADW + NB_EMB, 256>>>(seq, Wh, Wt, Wbi, mpos);
    k_ent_att<<<NB_ATT, 256>>>(att, mpos);
    k_ht<<<B_*P_, 256>>>(hts);
    k_rs_mma<<<dim3(BP_/128, D_/128), 256, GSM_>>>();
    k_E0<<<dim3(2, NW_/128), 256, GSM_>>>();
    k_E1<<<dim3(BP_/128, NW_/128, 2), 256, GSM_>>>();
    k_tanh<<<(BP_*NW_/4 + 255)/256, 256>>>(hts, bh, bt);
    k_bilinear_mma<<<dim3(BP_/128, KCH_, ISEG_), 256, SMEMB_>>>(hts);
    k_reduce<<<(BP_*NL_ + 255)/256, 256>>>(bbi, out);
}

// round 10
// speedup vs baseline: 4.1680x; 1.0722x over previous
#include <cuda_runtime.h>
#include <cuda_bf16.h>
#include <math.h>
#include <stdint.h>

#define B_ 4
#define L_ 1024
#define D_ 768
#define H_ 12
#define NE_ 42
#define M_ 4
#define P_ 512
#define BLK_ 64
#define NL_ 97
#define OFFSET_ 1
#define BP_ (B_*P_)          // 2048
#define KCH_ (D_/BLK_)       // 12 channel blocks
#define ISEG_ 3              // bilinear i-range split
#define KSLAB_ (ISEG_*KCH_)  // 36 partial slabs
#define NW_ 1536             // concat output width for extractors
#define WPITCH_ 136
#define WTILE_ (BLK_*WPITCH_)

typedef unsigned long long u64;
typedef unsigned int u32;

// ---------------- helpers ---------------------------------------------------
__device__ __forceinline__ u32 smem_u32(const void* p) {
    u32 a; asm("{ .reg .u64 t; cvta.to.shared.u64 t, %1; cvt.u32.u64 %0, t; }"
               : "=r"(a) : "l"(p));
    return a;
}
__device__ __forceinline__ u32 cvt_bf2(float lo, float hi) {
    u32 d; asm("cvt.rn.bf16x2.f32 %0, %1, %2;" : "=r"(d) : "f"(hi), "f"(lo));
    return d;
}
__device__ __forceinline__ float bf_lo_f(u32 c) { return __uint_as_float(c << 16); }
__device__ __forceinline__ float bf_hi_f(u32 c) { return __uint_as_float(c & 0xFFFF0000u); }

__device__ __forceinline__ void cpa16(u32 dst, const void* src) {
    asm volatile("cp.async.cg.shared.global [%0], [%1], 16;"
                 :: "r"(dst), "l"(src) : "memory");
}
__device__ __forceinline__ void cpa_commit() {
    asm volatile("cp.async.commit_group;" ::: "memory");
}
__device__ __forceinline__ void cpa_wait1() {
    asm volatile("cp.async.wait_group 1;" ::: "memory");
}
__device__ __forceinline__ void ldsm4(u32 addr, u32& r0, u32& r1, u32& r2, u32& r3) {
    asm volatile("ldmatrix.sync.aligned.m8n8.x4.shared.b16 {%0,%1,%2,%3}, [%4];"
                 : "=r"(r0), "=r"(r1), "=r"(r2), "=r"(r3) : "r"(addr));
}
__device__ __forceinline__ void ldsm4t(u32 addr, u32& r0, u32& r1, u32& r2, u32& r3) {
    asm volatile("ldmatrix.sync.aligned.m8n8.x4.trans.shared.b16 {%0,%1,%2,%3}, [%4];"
                 : "=r"(r0), "=r"(r1), "=r"(r2), "=r"(r3) : "r"(addr));
}
__device__ __forceinline__ void mma16816(float* d,
                                         u32 a0, u32 a1, u32 a2, u32 a3,
                                         u32 b0, u32 b1) {
    asm volatile(
        "mma.sync.aligned.m16n8k16.row.col.f32.bf16.bf16.f32 "
        "{%0,%1,%2,%3}, {%4,%5,%6,%7}, {%8,%9}, {%0,%1,%2,%3};"
        : "+f"(d[0]), "+f"(d[1]), "+f"(d[2]), "+f"(d[3])
        : "r"(a0), "r"(a1), "r"(a2), "r"(a3), "r"(b0), "r"(b1));
}

// ---------------- scratch (device globals; no runtime allocation) ----------
__device__ float g_ent_att[B_*NE_*H_*L_];
__device__ __nv_bfloat16 g_entA_hi[256*D_], g_entA_lo[256*D_];  // 168 used
__device__ __nv_bfloat16 g_seq_hi[B_*L_*D_],  g_seq_lo[B_*L_*D_];
__device__ __nv_bfloat16 g_ht_hi[B_*P_*L_],   g_ht_lo[B_*P_*L_];
__device__ float g_rsp[2*BP_*D_];                // rs K-split fp32 partials
__device__ __nv_bfloat16 g_rs_hi[BP_*D_], g_rs_lo[BP_*D_];
__device__ __nv_bfloat16 g_W1c_hi[D_*NW_], g_W1c_lo[D_*NW_];
__device__ __nv_bfloat16 g_W2c_hi[D_*NW_], g_W2c_lo[D_*NW_];
__device__ float g_E0[256*NW_];
__device__ float g_ep[2*BP_*NW_];
__device__ float g_zs[BP_*D_], g_zo[BP_*D_];
__device__ float g_part[KSLAB_*BP_*NL_];
__device__ __nv_bfloat16 g_Wb0[KCH_*BLK_*WTILE_], g_Wb1[KCH_*BLK_*WTILE_];

// ---------------- fused prep kernel: split + padW + ent_emb + ent_att ------
#define SPLIT_SEQ (B_*L_*D_/2)
#define SPLIT_W   (D_*D_)
#define NB_SPLIT ((SPLIT_SEQ + 2*SPLIT_W + 255)/256)   // 10752
#define NB_PADW  (KCH_*BLK_)                            // 768
#define NB_EMB   (B_*NE_)                               // 168
#define NB_ATT   (B_*NE_*H_)                            // 2016
#define NB_PREP  (NB_SPLIT + NB_PADW + NB_EMB + NB_ATT)

__global__ void k_prep(const float* __restrict__ seq,
                       const float* __restrict__ Wh,
                       const float* __restrict__ Wt,
                       const float* __restrict__ Wbi,
                       const float* __restrict__ att,
                       const int* __restrict__ mpos) {
    int bb = blockIdx.x;
    int tid = threadIdx.x;
    if (bb < NB_SPLIT) {
        int i = bb*256 + tid;
        if (i < SPLIT_SEQ) {
            float v0 = seq[2*i], v1 = seq[2*i+1];
            u32 h = cvt_bf2(v0, v1);
            ((u32*)g_seq_hi)[i] = h;
            ((u32*)g_seq_lo)[i] = cvt_bf2(v0 - bf_lo_f(h), v1 - bf_hi_f(h));
            return;
        }
        int j = i - SPLIT_SEQ;
        if (j >= 2*SPLIT_W) return;
        int sel = (j >= SPLIT_W) ? 1 : 0;
        int off = j - sel*SPLIT_W;
        const float* W = sel ? Wt : Wh;
        int kg = (2*off) / D_;
        int d  = (2*off) % D_;
        float v0 = W[2*off], v1 = W[2*off+1];
        u32 h = cvt_bf2(v0, v1);
        u32 r = cvt_bf2(v0 - bf_lo_f(h), v1 - bf_hi_f(h));
        u32 *hi, *lo;
        int rowk;
        if (kg < D_) { hi = (u32*)g_W1c_hi; lo = (u32*)g_W1c_lo; rowk = kg; }
        else         { hi = (u32*)g_W2c_hi; lo = (u32*)g_W2c_lo; rowk = kg - D_; }
        int idx = rowk*(NW_/2) + sel*(D_/2) + d/2;
        hi[idx] = h;
        lo[idx] = r;
        return;
    }
    bb -= NB_SPLIT;
    if (bb < NB_PADW) {
        int ki = bb;
        u32* d0 = (u32*)(g_Wb0 + (size_t)ki*WTILE_);
        u32* d1 = (u32*)(g_Wb1 + (size_t)ki*WTILE_);
        const float* src = Wbi + (size_t)ki*BLK_*NL_;
        for (int c = tid; c < WTILE_/8; c += 256) {
            int j = c / 17, c8 = (c % 17)*8;
            u32 h[4], lo[4];
            #pragma unroll
            for (int e = 0; e < 4; e++) {
                int n0 = c8 + 2*e, n1 = n0 + 1;
                float v0 = (n0 < NL_) ? src[j*NL_ + n0] : 0.f;
                float v1 = (n1 < NL_) ? src[j*NL_ + n1] : 0.f;
                h[e]  = cvt_bf2(v0, v1);
                lo[e] = cvt_bf2(v0 - bf_lo_f(h[e]), v1 - bf_hi_f(h[e]));
            }
            int base = (j*WPITCH_ + c8) >> 1;
            *(uint4*)(d0 + base) = make_uint4(h[0], h[1], h[2], h[3]);
            *(uint4*)(d1 + base) = make_uint4(lo[0], lo[1], lo[2], lo[3]);
        }
        return;
    }
    bb -= NB_PADW;
    if (bb < NB_EMB) {
        int be = bb;
        int b  = be / NE_;
        int base = be * M_;
        int p0 = mpos[base+0] + OFFSET_;
        int p1 = mpos[base+1] + OFFSET_;
        int p2 = mpos[base+2] + OFFSET_;
        int p3 = mpos[base+3] + OFFSET_;
        const float* s0 = seq + ((size_t)b*L_ + p0)*D_;
        const float* s1 = seq + ((size_t)b*L_ + p1)*D_;
        const float* s2 = seq + ((size_t)b*L_ + p2)*D_;
        const float* s3 = seq + ((size_t)b*L_ + p3)*D_;
        for (int d = tid; d < D_; d += 256) {
            float x0 = s0[d], x1 = s1[d], x2 = s2[d], x3 = s3[d];
            float mx = fmaxf(fmaxf(x0,x1), fmaxf(x2,x3));
            float v = mx + logf(expf(x0-mx) + expf(x1-mx) + expf(x2-mx) + expf(x3-mx));
            __nv_bfloat16 hb = __float2bfloat16(v);
            g_entA_hi[(size_t)be*D_ + d] = hb;
            g_entA_lo[(size_t)be*D_ + d] = __float2bfloat16(v - __bfloat162float(hb));
        }
        return;
    }
    bb -= NB_EMB;
    if (bb < NB_ATT) {
        int h  = bb % H_;
        int be = bb / H_;
        int b  = be / NE_;
        int base = be * M_;
        const float* a = att + (((size_t)b*H_ + h)*L_)*L_;
        const float* r0 = a + (size_t)(mpos[base+0]+OFFSET_)*L_;
        const float* r1 = a + (size_t)(mpos[base+1]+OFFSET_)*L_;
        const float* r2 = a + (size_t)(mpos[base+2]+OFFSET_)*L_;
        const float* r3 = a + (size_t)(mpos[base+3]+OFFSET_)*L_;
        float* out = g_ent_att + ((size_t)be*H_ + h)*L_;
        for (int l = tid; l < L_; l += 256)
            out[l] = 0.25f * (r0[l] + r1[l] + r2[l] + r3[l]);
    }
}

// ---------------- kernel C: per-pair channel attention -> bf16 split -------
__global__ void k_ht(const int* __restrict__ hts) {
    int bp = blockIdx.x;
    int b  = bp / P_;
    int hi = hts[bp*2 + 0];
    int ti = hts[bp*2 + 1];
    const float* ah = g_ent_att + (size_t)(b*NE_ + hi)*H_*L_;
    const float* at = g_ent_att + (size_t)(b*NE_ + ti)*H_*L_;
    const int T = 256;
    float v[4];
    float lsum = 0.f;
    #pragma unroll
    for (int it = 0; it < 4; it++) {
        int l = threadIdx.x + it*T;
        float acc = 0.f;
        #pragma unroll
        for (int h = 0; h < H_; h++)
            acc += ah[h*L_ + l] * at[h*L_ + l];
        acc *= (1.f/H_);
        v[it] = acc;
        lsum += acc;
    }
    __shared__ float red[32];
    #pragma unroll
    for (int o = 16; o; o >>= 1) lsum += __shfl_down_sync(~0u, lsum, o);
    if ((threadIdx.x & 31) == 0) red[threadIdx.x >> 5] = lsum;
    __syncthreads();
    if (threadIdx.x < 8) {
        float t = red[threadIdx.x];
        #pragma unroll
        for (int o = 4; o; o >>= 1) t += __shfl_down_sync(0xffu, t, o);
        if (threadIdx.x == 0) red[0] = 1.f / (t + 1e-5f);
    }
    __syncthreads();
    float inv = red[0];
    #pragma unroll
    for (int it = 0; it < 4; it++) {
        int l = threadIdx.x + it*T;
        float vv = v[it] * inv;
        __nv_bfloat16 hb = __float2bfloat16(vv);
        g_ht_hi[(size_t)bp*L_ + l] = hb;
        g_ht_lo[(size_t)bp*L_ + l] = __float2bfloat16(vv - __bfloat162float(hb));
    }
}

// ---------------- generic mma GEMM core (128x128 tile, K-chunk 32) ---------
#define GA_PITCH 80
#define GB_PITCH 272
#define GSA_ 10240
#define GSB_ 8704
#define GSTAGE_ 37888
#define GSM_ 75776

__device__ __forceinline__ void g_load_stage(u32 sbase,
    const __nv_bfloat16* __restrict__ Ah, const __nv_bfloat16* __restrict__ Al,
    int lda,
    const __nv_bfloat16* __restrict__ Bh, const __nv_bfloat16* __restrict__ Bl,
    int ldb,
    int r0, int n0, int kc, int tid)
{
    #pragma unroll
    for (int t = 0; t < 2; t++) {
        int idx = tid + t*256;
        int row = idx >> 2, c = idx & 3;
        size_t so = (size_t)(r0+row)*lda + kc + c*8;
        cpa16(sbase + row*GA_PITCH + c*16, Ah + so);
        cpa16(sbase + GSA_ + row*GA_PITCH + c*16, Al + so);
    }
    #pragma unroll
    for (int t = 0; t < 2; t++) {
        int idx = tid + t*256;
        int row = idx >> 4, c = idx & 15;
        size_t so = (size_t)(kc+row)*ldb + n0 + c*8;
        cpa16(sbase + 2*GSA_ + row*GB_PITCH + c*16, Bh + so);
        cpa16(sbase + 2*GSA_ + GSB_ + row*GB_PITCH + c*16, Bl + so);
    }
}

__device__ __forceinline__ void g_compute(u32 sbase, int w, int l,
                                          float (*acc)[4]) {
    int wm = w >> 1, wn = w & 1;
    u32 abase = sbase + (u32)((wm*32 + (l&15))*GA_PITCH + (l>>4)*16);
    u32 bbase = sbase + 2*GSA_ +
                (u32)((l&15)*GB_PITCH + (wn*64 + (l>>4)*8)*2);
    #pragma unroll
    for (int kk = 0; kk < 2; kk++) {
        u32 ah[2][4], al[2][4];
        #pragma unroll
        for (int mi = 0; mi < 2; mi++) {
            ldsm4(abase + mi*16*GA_PITCH + kk*32,
                  ah[mi][0], ah[mi][1], ah[mi][2], ah[mi][3]);
            ldsm4(abase + GSA_ + mi*16*GA_PITCH + kk*32,
                  al[mi][0], al[mi][1], al[mi][2], al[mi][3]);
        }
        u32 bb = bbase + kk*16*GB_PITCH;
        #pragma unroll
        for (int ntp = 0; ntp < 4; ntp++) {
            u32 b0,b1,b2,b3, c0,c1,c2,c3;
            ldsm4t(bb + ntp*32, b0,b1,b2,b3);
            ldsm4t(bb + GSB_ + ntp*32, c0,c1,c2,c3);
            #pragma unroll
            for (int mi = 0; mi < 2; mi++) {
                float* A0 = acc[mi*8 + 2*ntp];
                float* A1 = acc[mi*8 + 2*ntp + 1];
                mma16816(A0, ah[mi][0],ah[mi][1],ah[mi][2],ah[mi][3], b0,b1);
                mma16816(A1, ah[mi][0],ah[mi][1],ah[mi][2],ah[mi][3], b2,b3);
                mma16816(A0, ah[mi][0],ah[mi][1],ah[mi][2],ah[mi][3], c0,c1);
                mma16816(A1, ah[mi][0],ah[mi][1],ah[mi][2],ah[mi][3], c2,c3);
                mma16816(A0, al[mi][0],al[mi][1],al[mi][2],al[mi][3], b0,b1);
                mma16816(A1, al[mi][0],al[mi][1],al[mi][2],al[mi][3], b2,b3);
            }
        }
    }
}

// full GEMM body with fp32 epilogue at out[row*ldo + col]
__device__ __forceinline__ void gemm_body(u32 sb, int tid, int w, int l,
    const __nv_bfloat16* Ah, const __nv_bfloat16* Al, int lda,
    const __nv_bfloat16* Bh, const __nv_bfloat16* Bl, int ldb,
    int r0, int n0, int kb, int NK, float* out, int ldo)
{
    float acc[16][4];
    #pragma unroll
    for (int f = 0; f < 16; f++)
        #pragma unroll
        for (int e = 0; e < 4; e++) acc[f][e] = 0.f;
    g_load_stage(sb, Ah, Al, lda, Bh, Bl, ldb, r0, n0, kb, tid);  cpa_commit();
    g_load_stage(sb+GSTAGE_, Ah, Al, lda, Bh, Bl, ldb, r0, n0, kb+32, tid); cpa_commit();
    for (int i = 0; i < NK; i++) {
        cpa_wait1(); __syncthreads();
        g_compute(sb + (i&1)*GSTAGE_, w, l, acc);
        __syncthreads();
        if (i + 2 < NK)
            g_load_stage(sb + (i&1)*GSTAGE_, Ah, Al, lda, Bh, Bl, ldb, r0, n0, kb+(i+2)*32, tid);
        cpa_commit();
    }
    int wm = w >> 1, wn = w & 1, g = l >> 2, tg = l & 3;
    #pragma unroll
    for (int mi = 0; mi < 2; mi++) {
        int row = r0 + wm*32 + mi*16 + g;
        #pragma unroll
        for (int f = 0; f < 8; f++) {
            int col = n0 + wn*64 + f*8 + tg*2;
            float* a4 = acc[mi*8 + f];
            out[(size_t)row*ldo + col]       = a4[0];
            out[(size_t)row*ldo + col+1]     = a4[1];
            out[(size_t)(row+8)*ldo + col]   = a4[2];
            out[(size_t)(row+8)*ldo + col+1] = a4[3];
        }
    }
}

// ---------------- kernel D: rs GEMM, K-split x2, 2 blocks/SM ---------------
__global__ void __launch_bounds__(256, 2) k_rs_mma() {
    extern __shared__ char smem[];
    u32 sb = smem_u32(smem);
    int tid = threadIdx.x, w = tid >> 5, l = tid & 31;
    int r0 = blockIdx.x * 128, n0 = blockIdx.y * 128;
    int khalf = blockIdx.z;
    int b = r0 / P_;
    gemm_body(sb, tid, w, l,
              g_ht_hi, g_ht_lo, L_,
              g_seq_hi + (size_t)b*L_*D_, g_seq_lo + (size_t)b*L_*D_, D_,
              r0, n0, khalf*(L_/2), (L_/2)/32,
              g_rsp + (size_t)khalf*BP_*D_, D_);
}

// ---------------- kernel D2: combine rs partials -> bf16 split -------------
__global__ void k_rs_comb() {
    int i2 = blockIdx.x*256 + threadIdx.x;
    if (i2 >= BP_*D_/2) return;
    float2 a = ((const float2*)g_rsp)[i2];
    float2 b = ((const float2*)(g_rsp + (size_t)BP_*D_))[i2];
    float v0 = a.x + b.x, v1 = a.y + b.y;
    u32 hp = cvt_bf2(v0, v1);
    u32 lp = cvt_bf2(v0 - bf_lo_f(hp), v1 - bf_hi_f(hp));
    ((u32*)g_rs_hi)[i2] = hp;
    ((u32*)g_rs_lo)[i2] = lp;
}

// ---------------- kernel E: merged E1 (384 blocks) + E0 (24 blocks) --------
#define NBE1_ (16*12*2)      // 384
__global__ void __launch_bounds__(256, 2) k_E01() {
    extern __shared__ char smem[];
    u32 sb = smem_u32(smem);
    int tid = threadIdx.x, w = tid >> 5, l = tid & 31;
    int bb = blockIdx.x;
    if (bb < NBE1_) {
        // E1: rs @ [W2h|W2t], K-split x2
        int khalf = bb & 1;
        int t = bb >> 1;
        int r0 = (t & 15) * 128, n0 = (t >> 4) * 128;
        gemm_body(sb, tid, w, l,
                  g_rs_hi, g_rs_lo, D_,
                  g_W2c_hi, g_W2c_lo, NW_,
                  r0, n0, khalf*(D_/2), (D_/2)/32,
                  g_ep + (size_t)khalf*BP_*NW_, NW_);
    } else {
        // E0: entity embeds @ [W1h|W1t]
        int t = bb - NBE1_;                  // 0..23
        int r0 = (t & 1) * 128, n0 = (t >> 1) * 128;
        gemm_body(sb, tid, w, l,
                  g_entA_hi, g_entA_lo, D_,
                  g_W1c_hi, g_W1c_lo, NW_,
                  r0, n0, 0, D_/32,
                  g_E0, NW_);
    }
}

// ---------------- kernel T: combine E0(gather) + E1 partials + tanh --------
__global__ void k_tanh(const int* __restrict__ hts,
                       const float* __restrict__ bh, const float* __restrict__ bt) {
    int i4 = blockIdx.x*blockDim.x + threadIdx.x;
    if (i4 >= BP_*NW_/4) return;
    int row = (i4*4) / NW_;
    int n   = (i4*4) % NW_;
    int sel = (n >= D_) ? 1 : 0;
    int col = n - sel*D_;
    int b = row / P_;
    int eidx = hts[row*2 + sel];
    int entrow = b*NE_ + eidx;
    const float4 a = ((const float4*)(g_ep))[i4];
    const float4 c = ((const float4*)(g_ep + (size_t)BP_*NW_))[i4];
    const float4 e0 = *(const float4*)(g_E0 + (size_t)entrow*NW_ + n);
    const float* bias = sel ? bt : bh;
    float4 bb = *(const float4*)(bias + col);
    float* out = sel ? g_zo : g_zs;
    float4 o;
    o.x = tanhf(a.x + c.x + e0.x + bb.x);
    o.y = tanhf(a.y + c.y + e0.y + bb.y);
    o.z = tanhf(a.z + c.z + e0.z + bb.z);
    o.w = tanhf(a.w + c.w + e0.w + bb.w);
    *(float4*)(out + (size_t)row*D_ + col) = o;
}

// ---------------- kernel F: bilinear classifier, slim smem, 2 blocks/SM ----
#define SM_ZSB 0
#define SM_WB  12288
#define WSTAGE_ 34816
#define SMEMB_ (SM_WB + 2*WSTAGE_)      // 81920

__global__ void __launch_bounds__(256, 2) k_bilinear_mma() {
    extern __shared__ char smem[];
    float* zs_s = (float*)(smem + SM_ZSB);
    u32 sw = smem_u32(smem) + SM_WB;
    int tid = threadIdx.x, w = tid >> 5, l = tid & 31;
    int g = l >> 2, tg = l & 3;
    int k  = blockIdx.y;
    int r0 = blockIdx.x * 128;
    int iseg = blockIdx.z;
    int i0 = iseg*21, i1 = (iseg == ISEG_-1) ? BLK_ : (i0 + 21);
    int LEN = i1 - i0;

    #pragma unroll
    for (int p = 0; p < 2; p++) {
        int ii = i0 + p;
        const char* src0 = (const char*)(g_Wb0 + (size_t)(k*BLK_ + ii)*WTILE_);
        const char* src1 = (const char*)(g_Wb1 + (size_t)(k*BLK_ + ii)*WTILE_);
        u32 dst = sw + (ii & 1)*WSTAGE_;
        #pragma unroll
        for (int t = 0; t < 5; t++) {
            int idx = tid + t*256;
            if (idx < 1088) {
                cpa16(dst + idx*16, src0 + idx*16);
                cpa16(dst + 17408 + idx*16, src1 + idx*16);
            }
        }
        cpa_commit();
    }

    int rg = w*16 + g;
    float2 zoA[4][2], zoB[4][2];
    {
        const float* zor0 = g_zo + (size_t)(r0+rg)*D_ + k*BLK_;
        const float* zor1 = g_zo + (size_t)(r0+rg+8)*D_ + k*BLK_;
        #pragma unroll
        for (int jc = 0; jc < 4; jc++) {
            zoA[jc][0] = *(const float2*)(zor0 + jc*16 + tg*2);
            zoA[jc][1] = *(const float2*)(zor0 + jc*16 + tg*2 + 8);
            zoB[jc][0] = *(const float2*)(zor1 + jc*16 + tg*2);
            zoB[jc][1] = *(const float2*)(zor1 + jc*16 + tg*2 + 8);
        }
    }
    for (int idx = tid; idx < 128*LEN; idx += 256) {
        int r = idx / LEN, c = idx % LEN;
        zs_s[r*24 + c] = g_zs[(size_t)(r0+r)*D_ + k*BLK_ + i0 + c];
    }

    float acc[14][4];
    #pragma unroll
    for (int t = 0; t < 14; t++)
        #pragma unroll
        for (int e = 0; e < 4; e++) acc[t][e] = 0.f;

    u32 laneoff = (u32)((l & 15)*272 + (l >> 4)*16);

    for (int i = i0; i < i1; i++) {
        int s = i & 1;
        cpa_wait1();
        __syncthreads();
        float zs0 = zs_s[rg*24 + (i - i0)];
        float zs1 = zs_s[(rg+8)*24 + (i - i0)];
        u32 sbase = sw + s*WSTAGE_;
        #pragma unroll
        for (int jc = 0; jc < 4; jc++) {
            float p0x = zs0*zoA[jc][0].x, p0y = zs0*zoA[jc][0].y;
            float p1x = zs1*zoB[jc][0].x, p1y = zs1*zoB[jc][0].y;
            float p2x = zs0*zoA[jc][1].x, p2y = zs0*zoA[jc][1].y;
            float p3x = zs1*zoB[jc][1].x, p3y = zs1*zoB[jc][1].y;
            u32 a0h = cvt_bf2(p0x, p0y);
            u32 a1h = cvt_bf2(p1x, p1y);
            u32 a2h = cvt_bf2(p2x, p2y);
            u32 a3h = cvt_bf2(p3x, p3y);
            u32 a0r = cvt_bf2(p0x - bf_lo_f(a0h), p0y - bf_hi_f(a0h));
            u32 a1r = cvt_bf2(p1x - bf_lo_f(a1h), p1y - bf_hi_f(a1h));
            u32 a2r = cvt_bf2(p2x - bf_lo_f(a2h), p2y - bf_hi_f(a2h));
            u32 a3r = cvt_bf2(p3x - bf_lo_f(a3h), p3y - bf_hi_f(a3h));
            u32 rowb = sbase + (u32)(jc*16*272) + laneoff;
            #pragma unroll
            for (int ntp = 0; ntp < 7; ntp++) {
                u32 b0, b1, b2, b3;
                ldsm4t(rowb + ntp*32, b0, b1, b2, b3);
                mma16816(acc[2*ntp],   a0h,a1h,a2h,a3h, b0, b1);
                mma16816(acc[2*ntp+1], a0h,a1h,a2h,a3h, b2, b3);
                mma16816(acc[2*ntp],   a0r,a1r,a2r,a3r, b0, b1);
                mma16816(acc[2*ntp+1], a0r,a1r,a2r,a3r, b2, b3);
                u32 c0, c1, c2, c3;
                ldsm4t(rowb + 17408 + ntp*32, c0, c1, c2, c3);
                mma16816(acc[2*ntp],   a0h,a1h,a2h,a3h, c0, c1);
                mma16816(acc[2*ntp+1], a0h,a1h,a2h,a3h, c2, c3);
            }
        }
        __syncthreads();
        if (i + 2 < i1) {
            const char* src0 = (const char*)(g_Wb0 + (size_t)(k*BLK_ + i + 2)*WTILE_);
            const char* src1 = (const char*)(g_Wb1 + (size_t)(k*BLK_ + i + 2)*WTILE_);
            u32 dst = sw + s*WSTAGE_;
            #pragma unroll
            for (int t = 0; t < 5; t++) {
                int idx = tid + t*256;
                if (idx < 1088) {
                    cpa16(dst + idx*16, src0 + idx*16);
                    cpa16(dst + 17408 + idx*16, src1 + idx*16);
                }
            }
        }
        cpa_commit();
    }

    int slab = iseg*KCH_ + k;
    float* base0 = g_part + ((size_t)slab*BP_ + r0 + rg)*NL_;
    float* base1 = g_part + ((size_t)slab*BP_ + r0 + rg + 8)*NL_;
    #pragma unroll
    for (int nt = 0; nt < 13; nt++) {
        int n0 = nt*8 + tg*2;
        if (n0 < NL_) { base0[n0] = acc[nt][0]; base1[n0] = acc[nt][2]; }
        if (n0 + 1 < NL_) { base0[n0+1] = acc[nt][1]; base1[n0+1] = acc[nt][3]; }
    }
}

// ---------------- kernel G: reduce split-K partials + bias -----------------
__global__ void k_reduce(const float* __restrict__ bbi, float* __restrict__ out) {
    int idx = blockIdx.x*256 + threadIdx.x;
    if (idx >= BP_*NL_) return;
    int n = idx % NL_;
    float s = bbi[n];
    #pragma unroll
    for (int k = 0; k < KSLAB_; k++)
        s += g_part[(size_t)k*BP_*NL_ + idx];
    out[idx] = s;
}

// ---------------- launch ---------------------------------------------------
extern "C" void kernel_launch(void* const* d_in, const int* in_sizes, int n_in,
                              void* d_out, int out_size) {
    const float* seq  = (const float*)d_in[0];
    const float* att  = (const float*)d_in[1];
    const int*   mpos = (const int*)d_in[2];
    const int*   hts  = (const int*)d_in[3];
    const float* Wh   = (const float*)d_in[4];
    const float* bh   = (const float*)d_in[5];
    const float* Wt   = (const float*)d_in[6];
    const float* bt   = (const float*)d_in[7];
    const float* Wbi  = (const float*)d_in[8];
    const float* bbi  = (const float*)d_in[9];
    float* out = (float*)d_out;

    static bool attr_set = false;
    if (!attr_set) {
        cudaFuncSetAttribute(k_bilinear_mma,
            cudaFuncAttributeMaxDynamicSharedMemorySize, SMEMB_);
        cudaFuncSetAttribute(k_rs_mma,
            cudaFuncAttributeMaxDynamicSharedMemorySize, GSM_);
        cudaFuncSetAttribute(k_E01,
            cudaFuncAttributeMaxDynamicSharedMemorySize, GSM_);
        attr_set = true;
    }

    k_prep<<<NB_PREP, 256>>>(seq, Wh, Wt, Wbi, att, mpos);
    k_ht<<<B_*P_, 256>>>(hts);
    k_rs_mma<<<dim3(BP_/128, D_/128, 2), 256, GSM_>>>();
    k_rs_comb<<<(BP_*D_/2 + 255)/256, 256>>>();
    k_E01<<<NBE1_ + 24, 256, GSM_>>>();
    k_tanh<<<(BP_*NW_/4 + 255)/256, 256>>>(hts, bh, bt);
    k_bilinear_mma<<<dim3(BP_/128, KCH_, ISEG_), 256, SMEMB_>>>();
    k_reduce<<<(BP_*NL_ + 255)/256, 256>>>(bbi, out);
}